// round 6
// baseline (speedup 1.0000x reference)
#include <cuda_runtime.h>
#include <math.h>

#define NA   512
#define OBSD 128
#define INP  656
#define HID  64
#define LAT  256
#define NH   64
#define LOG2PI 1.8378770664093453f
#define BNEPS 1e-5f

// ---------------- scratch (device globals; no allocation allowed) ----------------
__device__ __align__(16) float g_pre_e[NA*NH];
__device__ __align__(16) float g_pre_i[NA*NH];
__device__ float g_scale[2][NH], g_shift[2][NH];
__device__ __align__(16) float g_mu[NA*LAT], g_var[NA*LAT], g_logsig[NA*LAT];
__device__ __align__(16) float g_n[NA*LAT], g_p[NA*LAT], g_q[NA*LAT];
__device__ __align__(16) float g_lat[NA*LAT];
__device__ __align__(16) float g_A[NA*NH], g_B[NA*NH];
__device__ __align__(16) float g_w1[NA*NH];
__device__ __align__(16) float g_mi[NA*NA], g_dis[NA*NA];
__device__ double g_ent, g_kl, g_sum_disn, g_sum_min;
__device__ unsigned g_keymin[2], g_keymax[2];
__device__ unsigned g_ctr1, g_ctr2;

// ordered-int encoding for float atomic min/max
__device__ __forceinline__ unsigned fkey(float f) {
    unsigned u = __float_as_uint(f);
    return (u & 0x80000000u) ? ~u : (u | 0x80000000u);
}
__device__ __forceinline__ float funkey(unsigned k) {
    unsigned u = (k & 0x80000000u) ? (k & 0x7fffffffu) : ~k;
    return __uint_as_float(u);
}

// ---------------- fused linear1 (encoder + inference) + global resets ----------------
__global__ void k_lin(const float* __restrict__ obs, const float* __restrict__ hid,
                      const float* __restrict__ eW1, const float* __restrict__ eb1,
                      const float* __restrict__ iW1, const float* __restrict__ ib1) {
    int b = blockIdx.x, t = threadIdx.x;   // 1024 blocks, 128 threads
    if (b == 0 && t == 0) {
        g_ent = 0.0; g_kl = 0.0; g_sum_disn = 0.0; g_sum_min = 0.0;
        g_ctr1 = 0u; g_ctr2 = 0u;
        g_keymin[0] = 0xFFFFFFFFu; g_keymin[1] = 0xFFFFFFFFu;
        g_keymax[0] = 0u; g_keymax[1] = 0u;
    }
    __shared__ float s[HID + INP];
    __shared__ float part[8][NH];
    int g = t & 15, hh = t >> 4;   // 16 col-groups x 8 l-slices
    int c0 = g * 4;
    float4 acc = make_float4(0.f, 0.f, 0.f, 0.f);
    if (b < NA) {
        int i = b;
        if (t < OBSD) s[t] = obs[i*INP + (INP-OBSD) + t];
        __syncthreads();
        int l0 = hh * 16;
        #pragma unroll 16
        for (int l = l0; l < l0 + 16; l++) {
            float4 w = *(const float4*)&eW1[l*NH + c0];
            float x = s[l];
            acc.x = fmaf(x, w.x, acc.x); acc.y = fmaf(x, w.y, acc.y);
            acc.z = fmaf(x, w.z, acc.z); acc.w = fmaf(x, w.w, acc.w);
        }
        part[hh][c0+0] = acc.x; part[hh][c0+1] = acc.y;
        part[hh][c0+2] = acc.z; part[hh][c0+3] = acc.w;
        __syncthreads();
        if (t < NH) {
            float r = eb1[t];
            #pragma unroll
            for (int k = 0; k < 8; k++) r += part[k][t];
            g_pre_e[i*NH + t] = r;
        }
    } else {
        int i = b - NA;
        for (int l = t; l < HID; l += 128) s[l] = hid[i*HID + l];
        for (int l = t; l < INP; l += 128) s[HID + l] = obs[i*INP + l];
        __syncthreads();
        int l0 = hh * 90;
        #pragma unroll 10
        for (int l = l0; l < l0 + 90; l++) {
            float4 w = *(const float4*)&iW1[l*NH + c0];
            float x = s[l];
            acc.x = fmaf(x, w.x, acc.x); acc.y = fmaf(x, w.y, acc.y);
            acc.z = fmaf(x, w.z, acc.z); acc.w = fmaf(x, w.w, acc.w);
        }
        part[hh][c0+0] = acc.x; part[hh][c0+1] = acc.y;
        part[hh][c0+2] = acc.z; part[hh][c0+3] = acc.w;
        __syncthreads();
        if (t < NH) {
            float r = ib1[t];
            #pragma unroll
            for (int k = 0; k < 8; k++) r += part[k][t];
            g_pre_i[i*NH + t] = r;
        }
    }
}

// ---------------- fused BN stats (both tensors), single pass, coalesced ----------------
__global__ void k_bn(const float* __restrict__ eg, const float* __restrict__ ebt,
                     const float* __restrict__ ig, const float* __restrict__ ibt) {
    int which = blockIdx.x;    // 2 blocks, 1024 threads
    const float* pre = which ? g_pre_i : g_pre_e;
    const float* gm  = which ? ig  : eg;
    const float* bt  = which ? ibt : ebt;
    int t = threadIdx.x;
    int c = t & 63, rg = t >> 6;   // 16 row groups
    float s = 0.f, s2 = 0.f;
    for (int r = rg; r < NA; r += 16) {
        float x = pre[r*NH + c];   // addr = t + 1024k : fully coalesced
        s += x; s2 = fmaf(x, x, s2);
    }
    __shared__ float sh1[16][NH], sh2[16][NH];
    sh1[rg][c] = s; sh2[rg][c] = s2;
    __syncthreads();
    if (t < NH) {
        float a = 0.f, b = 0.f;
        #pragma unroll
        for (int k = 0; k < 16; k++) { a += sh1[k][t]; b += sh2[k][t]; }
        float mean = a * (1.f/NA);
        float var = b * (1.f/NA) - mean*mean;
        float sc = gm[t] * rsqrtf(var + BNEPS);
        g_scale[which][t] = sc;
        g_shift[which][t] = bt[t] - mean*sc;
    }
}

// ---------------- encoder linear2 + latent head (mu/var split threads) + entropy ----------------
__global__ void k_lat_e(const float* __restrict__ eW2,
                        const float* __restrict__ eb2,
                        const float* __restrict__ eps) {
    int i = blockIdx.x, t = threadIdx.x;   // 512 blocks, 256 threads
    __shared__ float h[NH];
    __shared__ float sMu[2*LAT > 256 ? LAT : LAT];  // 256 mu values
    __shared__ float red[256];
    if (t < NH) {
        float x = fmaf(g_pre_e[i*NH + t], g_scale[0][t], g_shift[0][t]);
        h[t] = (x > 0.f) ? x : 0.01f*x;
    }
    __syncthreads();
    int c0 = 2*t;
    float a0 = eb2[c0], a1 = eb2[c0+1];
    #pragma unroll 16
    for (int l = 0; l < NH; l++) {
        float2 w = *(const float2*)&eW2[l*(2*LAT) + c0];
        float hl = h[l];
        a0 = fmaf(hl, w.x, a0); a1 = fmaf(hl, w.y, a1);
    }
    float entp = 0.f;
    if (t < 128) {
        sMu[c0] = a0; sMu[c0+1] = a1;
        g_mu[i*LAT + c0] = a0; g_mu[i*LAT + c0+1] = a1;
    }
    __syncthreads();
    if (t >= 128) {
        int li = c0 - 2*LAT + LAT;   // c0-256
        int gi = i*LAT + li;
        float mu0 = sMu[li], mu1 = sMu[li+1];
        float v0 = fmaxf(expf(a0), 0.002f), v1 = fmaxf(expf(a1), 0.002f);
        float ls0 = 0.5f*logf(v0), ls1 = 0.5f*logf(v1);
        g_var[gi] = v0;   g_var[gi+1] = v1;
        g_logsig[gi] = ls0; g_logsig[gi+1] = ls1;
        float n0 = -0.5f/v0, n1 = -0.5f/v1;
        g_n[gi] = n0; g_n[gi+1] = n1;
        g_p[gi] = mu0/v0; g_p[gi+1] = mu1/v1;
        g_q[gi]   = fmaf(n0, mu0*mu0, 13.9f - ls0 - 0.5f*LOG2PI);
        g_q[gi+1] = fmaf(n1, mu1*mu1, 13.9f - ls1 - 0.5f*LOG2PI);
        g_lat[gi]   = fmaf(sqrtf(v0), eps[gi],   mu0);
        g_lat[gi+1] = fmaf(sqrtf(v1), eps[gi+1], mu1);
        entp = 1.f + LOG2PI + ls0 + ls1;
    }
    red[t] = entp;
    __syncthreads();
    for (int o = 128; o; o >>= 1) { if (t < o) red[t] += red[t+o]; __syncthreads(); }
    if (t == 0) atomicAdd(&g_ent, (double)red[0]);
}

// ---------------- inference linear2 + KL ----------------
__global__ void k_lat_i(const float* __restrict__ iW2,
                        const float* __restrict__ ib2) {
    int i = blockIdx.x, t = threadIdx.x;   // 512 blocks, 256 threads
    __shared__ float h[NH];
    __shared__ float sMu[LAT];
    __shared__ float red[256];
    if (t < NH) {
        float x = fmaf(g_pre_i[i*NH + t], g_scale[1][t], g_shift[1][t]);
        h[t] = (x > 0.f) ? x : 0.01f*x;
    }
    __syncthreads();
    int c0 = 2*t;
    float a0 = ib2[c0], a1 = ib2[c0+1];
    #pragma unroll 16
    for (int l = 0; l < NH; l++) {
        float2 w = *(const float2*)&iW2[l*(2*LAT) + c0];
        float hl = h[l];
        a0 = fmaf(hl, w.x, a0); a1 = fmaf(hl, w.y, a1);
    }
    float klp = 0.f;
    if (t < 128) { sMu[c0] = a0; sMu[c0+1] = a1; }
    __syncthreads();
    if (t >= 128) {
        int li = c0 - LAT;
        int gi = i*LAT + li;
        float mq0 = sMu[li], mq1 = sMu[li+1];
        float vq0 = fmaxf(expf(a0), 0.002f), vq1 = fmaxf(expf(a1), 0.002f);
        float lsq0 = 0.5f*logf(vq0), lsq1 = 0.5f*logf(vq1);
        float d0 = g_mu[gi]   - mq0;
        float d1 = g_mu[gi+1] - mq1;
        klp = (lsq0 - g_logsig[gi]   + (g_var[gi]   + d0*d0) / (2.f*vq0) - 0.5f)
            + (lsq1 - g_logsig[gi+1] + (g_var[gi+1] + d1*d1) / (2.f*vq1) - 0.5f);
    }
    red[t] = klp;
    __syncthreads();
    for (int o = 128; o; o >>= 1) { if (t < o) red[t] += red[t+o]; __syncthreads(); }
    if (t == 0) atomicAdd(&g_kl, (double)red[0]);
}

// ---------------- A = latent @ dW1[:256], B = latent @ dW1[256:] ----------------
__global__ void k_AB(const float* __restrict__ dW1) {
    int j = blockIdx.x, t = threadIdx.x;   // 512 blocks, 256 threads
    int c = t & 63, q = t >> 6;
    __shared__ float L[LAT];
    __shared__ float pa[4][NH], pb[4][NH];
    L[t] = g_lat[j*LAT + t];
    __syncthreads();
    float a = 0.f, b = 0.f;
    int l0 = q * 64;
    #pragma unroll 8
    for (int l = l0; l < l0 + 64; l++) {
        float lv = L[l];
        a = fmaf(lv, dW1[l*NH + c], a);
        b = fmaf(lv, dW1[(l + LAT)*NH + c], b);
    }
    pa[q][c] = a; pb[q][c] = b;
    __syncthreads();
    if (q == 0) {
        g_A[j*NH + c] = pa[0][c] + pa[1][c] + pa[2][c] + pa[3][c];
        g_B[j*NH + c] = pb[0][c] + pb[1][c] + pb[2][c] + pb[3][c];
    }
}

// ---------------- fused: col stats + center (in place) + circ-corr -> w1 ----------------
__global__ void k_col(const float* __restrict__ dg) {
    int c = blockIdx.x, s = threadIdx.x;   // 64 blocks, 512 threads
    __shared__ float a[NA], b[NA], r1[NA], r2[NA];
    float av = g_A[s*NH + c], bv = g_B[s*NH + c];
    r1[s] = av; r2[s] = bv;
    __syncthreads();
    for (int o = 256; o; o >>= 1) {
        if (s < o) { r1[s] += r1[s+o]; r2[s] += r2[s+o]; }
        __syncthreads();
    }
    float mA = r1[0] * (1.f/NA), mB = r2[0] * (1.f/NA);
    __syncthreads();
    av -= mA; bv -= mB;
    a[s] = av; b[s] = bv;
    g_A[s*NH + c] = av;
    g_B[s*NH + c] = bv;
    r1[s] = av*av + bv*bv;
    __syncthreads();
    for (int o = 256; o; o >>= 1) { if (s < o) r1[s] += r1[s+o]; __syncthreads(); }
    float s2 = r1[0] * (1.f/NA);
    float cr = 0.f;
    #pragma unroll 8
    for (int j = 0; j < NA; j++) cr = fmaf(a[j], b[(j - s - 1) & (NA-1)], cr);
    float var = s2 + 2.f * cr * (1.f/NA);
    g_w1[s*NH + c] = dg[c] * rsqrtf(var + BNEPS);
}

// ---------------- fused MI (z=0) + DIS (z=1) ----------------
__global__ void k_midis(const float* __restrict__ dbt,
                        const float* __restrict__ dW2,
                        const float* __restrict__ db2) {
    __shared__ float sh[8448];
    const int tid = threadIdx.x;            // 256
    const int j0 = blockIdx.x * 32, s0 = blockIdx.y * 32;
    const int tx = tid & 15, ty = tid >> 4;
    const int jj0 = 2*tx, ss0 = 2*ty;
    const int base = (j0 - s0 - 32) & (NA-1);
    if (blockIdx.z == 0) {
        // ---- MI: poly form n*L^2 + p*L + q; (n,p,q) in registers, L/L^2 band in smem ----
        float* sL = sh;            // 63*9
        float* sQ = sh + 567;      // 63*9
        float acc00 = 0.f, acc01 = 0.f, acc10 = 0.f, acc11 = 0.f;
        const int R = jj0 - ss0 + 30;
        const int rowj0 = (j0 + jj0) * LAT, rowj1 = rowj0 + LAT;
        for (int l0 = 0; l0 < LAT; l0 += 8) {
            float rn0[8], rp0[8], rq0[8], rn1[8], rp1[8], rq1[8];
            *(float4*)&rn0[0] = *(const float4*)&g_n[rowj0 + l0];
            *(float4*)&rn0[4] = *(const float4*)&g_n[rowj0 + l0 + 4];
            *(float4*)&rn1[0] = *(const float4*)&g_n[rowj1 + l0];
            *(float4*)&rn1[4] = *(const float4*)&g_n[rowj1 + l0 + 4];
            *(float4*)&rp0[0] = *(const float4*)&g_p[rowj0 + l0];
            *(float4*)&rp0[4] = *(const float4*)&g_p[rowj0 + l0 + 4];
            *(float4*)&rp1[0] = *(const float4*)&g_p[rowj1 + l0];
            *(float4*)&rp1[4] = *(const float4*)&g_p[rowj1 + l0 + 4];
            *(float4*)&rq0[0] = *(const float4*)&g_q[rowj0 + l0];
            *(float4*)&rq0[4] = *(const float4*)&g_q[rowj0 + l0 + 4];
            *(float4*)&rq1[0] = *(const float4*)&g_q[rowj1 + l0];
            *(float4*)&rq1[4] = *(const float4*)&g_q[rowj1 + l0 + 4];
            for (int idx = tid; idx < 63*8; idx += 256) {
                int r = idx >> 3, lc = idx & 7;
                float v = g_lat[((base + r) & (NA-1))*LAT + l0 + lc];
                sL[r*9 + lc] = v; sQ[r*9 + lc] = v*v;
            }
            __syncthreads();
            const float* pL = sL + R*9;
            const float* pQ = sQ + R*9;
            #pragma unroll
            for (int l = 0; l < 8; l++) {
                float La = pL[l],      Lb = pL[9 + l],  Lc = pL[18 + l];
                float Qa = pQ[l],      Qb = pQ[9 + l],  Qc = pQ[18 + l];
                acc10 += fmaxf(fmaf(rn0[l], Qa, fmaf(rp0[l], La, rq0[l])), -13.9f);
                acc00 += fmaxf(fmaf(rn0[l], Qb, fmaf(rp0[l], Lb, rq0[l])), -13.9f);
                acc11 += fmaxf(fmaf(rn1[l], Qb, fmaf(rp1[l], Lb, rq1[l])), -13.9f);
                acc01 += fmaxf(fmaf(rn1[l], Qc, fmaf(rp1[l], Lc, rq1[l])), -13.9f);
            }
            __syncthreads();
        }
        const float inv = 1.f / LAT;
        g_mi[(s0+ss0  )*NA + j0+jj0  ] = acc00 * inv;
        g_mi[(s0+ss0  )*NA + j0+jj0+1] = acc01 * inv;
        g_mi[(s0+ss0+1)*NA + j0+jj0  ] = acc10 * inv;
        g_mi[(s0+ss0+1)*NA + j0+jj0+1] = acc11 * inv;
    } else {
        // ---- DIS ----
        float* sa   = sh;                 // 32*65
        float* sw   = sh + 2080;          // 32*65
        float* sb   = sh + 4160;          // 64*65
        float* sdbt = sh + 8320;          // 64
        float* sdw2 = sh + 8384;          // 64
        if (tid < NH) { sdbt[tid] = dbt[tid]; sdw2[tid] = dW2[tid]; }
        #pragma unroll
        for (int i = 0; i < 8; i++) {
            int idx = tid + i*256;
            int r = idx >> 6, c = idx & 63;
            sa[r*65 + c] = g_A[(j0 + r)*NH + c];
            sw[r*65 + c] = g_w1[(s0 + r)*NH + c];
        }
        #pragma unroll
        for (int i = 0; i < 16; i++) {
            int idx = tid + i*256;
            int r = idx >> 6, c = idx & 63;
            sb[r*65 + c] = g_B[((base + r) & (NA-1))*NH + c];
        }
        __syncthreads();
        float acc00 = 0.f, acc01 = 0.f, acc10 = 0.f, acc11 = 0.f;
        #pragma unroll 8
        for (int c = 0; c < NH; c++) {
            float a0 = sa[jj0*65 + c], a1 = sa[(jj0+1)*65 + c];
            float w0 = sw[ss0*65 + c], w1v = sw[(ss0+1)*65 + c];
            float bt = sdbt[c], w2 = sdw2[c];
            {
                float b0 = sb[(jj0   - ss0 + 31)*65 + c];
                float b1 = sb[(jj0+1 - ss0 + 31)*65 + c];
                float v0 = fmaf(a0 + b0, w0, bt); v0 = (v0 > 0.f) ? v0 : 0.01f*v0;
                float v1 = fmaf(a1 + b1, w0, bt); v1 = (v1 > 0.f) ? v1 : 0.01f*v1;
                acc00 = fmaf(v0, w2, acc00);
                acc01 = fmaf(v1, w2, acc01);
            }
            {
                float b0 = sb[(jj0   - ss0 + 30)*65 + c];
                float b1 = sb[(jj0+1 - ss0 + 30)*65 + c];
                float v0 = fmaf(a0 + b0, w1v, bt); v0 = (v0 > 0.f) ? v0 : 0.01f*v0;
                float v1 = fmaf(a1 + b1, w1v, bt); v1 = (v1 > 0.f) ? v1 : 0.01f*v1;
                acc10 = fmaf(v0, w2, acc10);
                acc11 = fmaf(v1, w2, acc11);
            }
        }
        float b2 = db2[0];
        g_dis[(s0+ss0  )*NA + j0+jj0  ] = fabsf(acc00 + b2);
        g_dis[(s0+ss0  )*NA + j0+jj0+1] = fabsf(acc01 + b2);
        g_dis[(s0+ss0+1)*NA + j0+jj0  ] = fabsf(acc10 + b2);
        g_dis[(s0+ss0+1)*NA + j0+jj0+1] = fabsf(acc11 + b2);
    }
}

// ---------------- persistent reduce: minmax -> grid barrier -> normalized sums -> final ----------------
__global__ void k_red(float* __restrict__ out) {
    const int t = threadIdx.x;                     // 128 blocks x 256 threads
    const int gtid = blockIdx.x * 256 + t;
    const float4* mi4 = (const float4*)g_mi;
    const float4* ds4 = (const float4*)g_dis;
    float4 m0 = mi4[gtid], m1 = mi4[gtid + 32768];
    float4 d0 = ds4[gtid], d1 = ds4[gtid + 32768];

    float mn0 = fminf(fminf(fminf(m0.x, m0.y), fminf(m0.z, m0.w)),
                      fminf(fminf(m1.x, m1.y), fminf(m1.z, m1.w)));
    float mx0 = fmaxf(fmaxf(fmaxf(m0.x, m0.y), fmaxf(m0.z, m0.w)),
                      fmaxf(fmaxf(m1.x, m1.y), fmaxf(m1.z, m1.w)));
    float mn1 = fminf(fminf(fminf(d0.x, d0.y), fminf(d0.z, d0.w)),
                      fminf(fminf(d1.x, d1.y), fminf(d1.z, d1.w)));
    float mx1 = fmaxf(fmaxf(fmaxf(d0.x, d0.y), fmaxf(d0.z, d0.w)),
                      fmaxf(fmaxf(d1.x, d1.y), fmaxf(d1.z, d1.w)));
    #pragma unroll
    for (int o = 16; o; o >>= 1) {
        mn0 = fminf(mn0, __shfl_xor_sync(0xFFFFFFFFu, mn0, o));
        mx0 = fmaxf(mx0, __shfl_xor_sync(0xFFFFFFFFu, mx0, o));
        mn1 = fminf(mn1, __shfl_xor_sync(0xFFFFFFFFu, mn1, o));
        mx1 = fmaxf(mx1, __shfl_xor_sync(0xFFFFFFFFu, mx1, o));
    }
    __shared__ float w0[8], w1s[8], w2[8], w3[8];
    __shared__ float snorm[4];
    if ((t & 31) == 0) { w0[t>>5] = mn0; w1s[t>>5] = mx0; w2[t>>5] = mn1; w3[t>>5] = mx1; }
    __syncthreads();
    if (t == 0) {
        float a = w0[0], b = w1s[0], c = w2[0], d = w3[0];
        #pragma unroll
        for (int k = 1; k < 8; k++) {
            a = fminf(a, w0[k]); b = fmaxf(b, w1s[k]);
            c = fminf(c, w2[k]); d = fmaxf(d, w3[k]);
        }
        atomicMin(&g_keymin[0], fkey(a)); atomicMax(&g_keymax[0], fkey(b));
        atomicMin(&g_keymin[1], fkey(c)); atomicMax(&g_keymax[1], fkey(d));
        __threadfence();
        atomicAdd(&g_ctr1, 1u);
        while (atomicAdd(&g_ctr1, 0u) < 128u) { }
        __threadfence();
        float mi_min = funkey(atomicAdd(&g_keymin[0], 0u));
        float mi_max = funkey(atomicAdd(&g_keymax[0], 0u));
        float ds_min = funkey(atomicAdd(&g_keymin[1], 0u));
        float ds_max = funkey(atomicAdd(&g_keymax[1], 0u));
        snorm[0] = mi_min; snorm[1] = 1.f / (mi_max - mi_min + 1e-12f);
        snorm[2] = ds_min; snorm[3] = 1.f / (ds_max - ds_min + 1e-12f);
    }
    __syncthreads();
    const float mi_min = snorm[0], mi_inv = snorm[1];
    const float ds_min = snorm[2], ds_inv = snorm[3];
    double s1 = 0.0, s2 = 0.0;
    {
        float mis[8] = {m0.x, m0.y, m0.z, m0.w, m1.x, m1.y, m1.z, m1.w};
        float dss[8] = {d0.x, d0.y, d0.z, d0.w, d1.x, d1.y, d1.z, d1.w};
        #pragma unroll
        for (int k = 0; k < 8; k++) {
            float mn = (mis[k] - mi_min) * mi_inv;
            float dn = (dss[k] - ds_min) * ds_inv;
            s1 += (double)dn;
            s2 += (double)fminf(mn + dn, 1.0f);
        }
    }
    #pragma unroll
    for (int o = 16; o; o >>= 1) {
        s1 += __shfl_xor_sync(0xFFFFFFFFu, s1, o);
        s2 += __shfl_xor_sync(0xFFFFFFFFu, s2, o);
    }
    __shared__ double dw1[8], dw2[8];
    if ((t & 31) == 0) { dw1[t>>5] = s1; dw2[t>>5] = s2; }
    __syncthreads();
    if (t == 0) {
        double a = 0.0, b = 0.0;
        #pragma unroll
        for (int k = 0; k < 8; k++) { a += dw1[k]; b += dw2[k]; }
        atomicAdd(&g_sum_disn, a);
        atomicAdd(&g_sum_min, b);
        __threadfence();
        unsigned old = atomicAdd(&g_ctr2, 1u);
        if (old == 127u) {
            __threadfence();
            double ent = g_ent / (double)NA;
            double kl  = g_kl  / (double)NA;
            double loss0 = fmin(ent*1e-4 + kl*1e-4, 2000.0);
            double ce = log1p(exp(loss0));
            double dis_norm = g_sum_disn / (double)NA;
            double dis_loss = -g_sum_min / (double)NA;
            double cdis = (dis_norm + dis_loss) / (double)NA;
            out[0] = (float)(ce + cdis);
            out[1] = (float)cdis;
            out[2] = (float)ce;
        }
    }
}

// ---------------- launcher ----------------
extern "C" void kernel_launch(void* const* d_in, const int* in_sizes, int n_in,
                              void* d_out, int out_size) {
    const float* obs  = (const float*)d_in[0];
    const float* hid  = (const float*)d_in[1];
    const float* eps  = (const float*)d_in[2];
    const float* eW1  = (const float*)d_in[3];
    const float* eb1  = (const float*)d_in[4];
    const float* eg   = (const float*)d_in[5];
    const float* ebt  = (const float*)d_in[6];
    const float* eW2  = (const float*)d_in[7];
    const float* eb2  = (const float*)d_in[8];
    const float* iW1  = (const float*)d_in[9];
    const float* ib1  = (const float*)d_in[10];
    const float* ig   = (const float*)d_in[11];
    const float* ibt  = (const float*)d_in[12];
    const float* iW2  = (const float*)d_in[13];
    const float* ib2  = (const float*)d_in[14];
    const float* dW1  = (const float*)d_in[15];
    const float* db1  = (const float*)d_in[16]; (void)db1; // cancels in BN
    const float* dg   = (const float*)d_in[17];
    const float* dbt  = (const float*)d_in[18];
    const float* dW2  = (const float*)d_in[19];
    const float* db2  = (const float*)d_in[20];
    float* out = (float*)d_out;

    k_lin<<<2*NA, 128>>>(obs, hid, eW1, eb1, iW1, ib1);
    k_bn<<<2, 1024>>>(eg, ebt, ig, ibt);
    k_lat_e<<<NA, 256>>>(eW2, eb2, eps);
    k_lat_i<<<NA, 256>>>(iW2, ib2);
    k_AB<<<NA, 256>>>(dW1);
    k_col<<<NH, 512>>>(dg);
    k_midis<<<dim3(16, 16, 2), 256>>>(dbt, dW2, db2);
    k_red<<<128, 256>>>(out);
}

// round 7
// speedup vs baseline: 1.8159x; 1.8159x over previous
#include <cuda_runtime.h>
#include <math.h>

#define NA   512
#define OBSD 128
#define INP  656
#define HID  64
#define LAT  256
#define NH   64
#define LOG2PI 1.8378770664093453f
#define BNEPS 1e-5f

// ---------------- scratch (device globals; no allocation allowed) ----------------
__device__ __align__(16) float g_pre_e[NA*NH];
__device__ __align__(16) float g_pre_i[NA*NH];
__device__ float g_scale[2][NH], g_shift[2][NH];
__device__ __align__(16) float g_mu[NA*LAT], g_var[NA*LAT], g_logsig[NA*LAT];
__device__ __align__(16) float g_ni2v[NA*LAT], g_cc[NA*LAT], g_lat[NA*LAT];
__device__ __align__(16) float g_A[NA*NH], g_B[NA*NH];
__device__ __align__(16) float g_w1[NA*NH];
__device__ __align__(16) float g_mi[NA*NA], g_dis[NA*NA];
__device__ double g_ent, g_kl, g_sum_disn, g_sum_min;
__device__ float g_pmin[2][256], g_pmax[2][256];
__device__ float g_norm[4];   // mi_min, mi_inv, dis_min, dis_inv

// ---------------- fused linear1 (encoder + inference), 8 rows/block + resets ----------------
__global__ void k_lin(const float* __restrict__ obs, const float* __restrict__ hid,
                      const float* __restrict__ eW1, const float* __restrict__ eb1,
                      const float* __restrict__ iW1, const float* __restrict__ ib1) {
    int b = blockIdx.x, t = threadIdx.x;   // 128 blocks, 128 threads
    if (b == 0 && t == 0) {
        g_ent = 0.0; g_kl = 0.0; g_sum_disn = 0.0; g_sum_min = 0.0;
    }
    const bool enc = (b < 64);
    const int i0 = (enc ? b : b - 64) * 8;
    __shared__ float s[8][HID + INP];      // enc uses [8][128]
    __shared__ float part[2][8][NH];
    if (enc) {
        for (int idx = t; idx < 8*OBSD; idx += 128) {
            int g = idx >> 7, c = idx & 127;
            s[g][c] = obs[(i0+g)*INP + (INP-OBSD) + c];
        }
    } else {
        for (int idx = t; idx < 8*(HID+INP); idx += 128) {
            int g = idx / (HID+INP), c = idx % (HID+INP);
            s[g][c] = (c < HID) ? hid[(i0+g)*HID + c] : obs[(i0+g)*INP + (c-HID)];
        }
    }
    __syncthreads();
    const int c = t & 63, half = t >> 6;
    const int Ltot = enc ? OBSD : (HID+INP);
    const int l0 = half * (Ltot >> 1);
    const float* __restrict__ W = enc ? eW1 : iW1;
    float acc[8] = {0.f,0.f,0.f,0.f,0.f,0.f,0.f,0.f};
    for (int l = l0; l < l0 + (Ltot >> 1); l++) {
        float w = W[l*NH + c];
        #pragma unroll
        for (int g = 0; g < 8; g++) acc[g] = fmaf(s[g][l], w, acc[g]);
    }
    #pragma unroll
    for (int g = 0; g < 8; g++) part[half][g][c] = acc[g];
    __syncthreads();
    const float* __restrict__ bias = enc ? eb1 : ib1;
    float* __restrict__ dst = enc ? g_pre_e : g_pre_i;
    for (int idx = t; idx < 512; idx += 128) {
        int g = idx >> 6, c2 = idx & 63;
        dst[(i0+g)*NH + c2] = part[0][g][c2] + part[1][g][c2] + bias[c2];
    }
}

// ---------------- fused BN stats (both tensors), single pass, coalesced ----------------
__global__ void k_bn(const float* __restrict__ eg, const float* __restrict__ ebt,
                     const float* __restrict__ ig, const float* __restrict__ ibt) {
    int which = blockIdx.x;    // 2 blocks, 1024 threads
    const float* pre = which ? g_pre_i : g_pre_e;
    const float* gm  = which ? ig  : eg;
    const float* bt  = which ? ibt : ebt;
    int t = threadIdx.x;
    int c = t & 63, rg = t >> 6;   // 16 row groups
    float s = 0.f, s2 = 0.f;
    for (int r = rg; r < NA; r += 16) {
        float x = pre[r*NH + c];   // addr = t + 1024k : fully coalesced
        s += x; s2 = fmaf(x, x, s2);
    }
    __shared__ float sh1[16][NH], sh2[16][NH];
    sh1[rg][c] = s; sh2[rg][c] = s2;
    __syncthreads();
    if (t < NH) {
        float a = 0.f, b = 0.f;
        #pragma unroll
        for (int k = 0; k < 16; k++) { a += sh1[k][t]; b += sh2[k][t]; }
        float mean = a * (1.f/NA);
        float var = b * (1.f/NA) - mean*mean;
        float sc = gm[t] * rsqrtf(var + BNEPS);
        g_scale[which][t] = sc;
        g_shift[which][t] = bt[t] - mean*sc;
    }
}

// ---------------- encoder linear2 + latent head, 8 rows/block + entropy ----------------
__global__ void k_lat_e(const float* __restrict__ eW2,
                        const float* __restrict__ eb2,
                        const float* __restrict__ eps) {
    int i0 = blockIdx.x * 8, t = threadIdx.x;   // 64 blocks, 256 threads
    __shared__ float h[8][NH];
    __shared__ float sMu[8][LAT];
    __shared__ float red[256];
    for (int idx = t; idx < 512; idx += 256) {
        int g = idx >> 6, c = idx & 63;
        float x = fmaf(g_pre_e[(i0+g)*NH + c], g_scale[0][c], g_shift[0][c]);
        h[g][c] = (x > 0.f) ? x : 0.01f*x;
    }
    __syncthreads();
    const int c0 = 2*t;
    float a0[8], a1[8];
    {
        float b0 = eb2[c0], b1 = eb2[c0+1];
        #pragma unroll
        for (int g = 0; g < 8; g++) { a0[g] = b0; a1[g] = b1; }
    }
    for (int l = 0; l < NH; l++) {
        float2 w = *(const float2*)&eW2[l*(2*LAT) + c0];
        #pragma unroll
        for (int g = 0; g < 8; g++) {
            float hv = h[g][l];
            a0[g] = fmaf(hv, w.x, a0[g]);
            a1[g] = fmaf(hv, w.y, a1[g]);
        }
    }
    if (t < 128) {
        #pragma unroll
        for (int g = 0; g < 8; g++) {
            sMu[g][c0] = a0[g]; sMu[g][c0+1] = a1[g];
            float2 m2 = make_float2(a0[g], a1[g]);
            *(float2*)&g_mu[(i0+g)*LAT + c0] = m2;
        }
    }
    __syncthreads();
    float ep = 0.f;
    if (t >= 128) {
        const int li = c0 - 2*LAT + LAT;   // c0 - 256
        #pragma unroll
        for (int g = 0; g < 8; g++) {
            int gi = (i0+g)*LAT + li;
            float v0 = fmaxf(expf(a0[g]), 0.002f);
            float v1 = fmaxf(expf(a1[g]), 0.002f);
            float ls0 = 0.5f*logf(v0), ls1 = 0.5f*logf(v1);
            float mu0 = sMu[g][li], mu1 = sMu[g][li+1];
            *(float2*)&g_var[gi]    = make_float2(v0, v1);
            *(float2*)&g_logsig[gi] = make_float2(ls0, ls1);
            *(float2*)&g_ni2v[gi]   = make_float2(-0.5f/v0, -0.5f/v1);
            *(float2*)&g_cc[gi]     = make_float2(13.9f - ls0 - 0.5f*LOG2PI,
                                                  13.9f - ls1 - 0.5f*LOG2PI);
            float2 e2 = *(const float2*)&eps[gi];
            *(float2*)&g_lat[gi] = make_float2(fmaf(sqrtf(v0), e2.x, mu0),
                                               fmaf(sqrtf(v1), e2.y, mu1));
            ep += 1.f + LOG2PI + ls0 + ls1;
        }
    }
    red[t] = ep;
    __syncthreads();
    for (int o = 128; o; o >>= 1) { if (t < o) red[t] += red[t+o]; __syncthreads(); }
    if (t == 0) atomicAdd(&g_ent, (double)red[0]);
}

// ---------------- inference linear2 + KL, 8 rows/block ----------------
__global__ void k_lat_i(const float* __restrict__ iW2,
                        const float* __restrict__ ib2) {
    int i0 = blockIdx.x * 8, t = threadIdx.x;   // 64 blocks, 256 threads
    __shared__ float h[8][NH];
    __shared__ float sMu[8][LAT];
    __shared__ float red[256];
    for (int idx = t; idx < 512; idx += 256) {
        int g = idx >> 6, c = idx & 63;
        float x = fmaf(g_pre_i[(i0+g)*NH + c], g_scale[1][c], g_shift[1][c]);
        h[g][c] = (x > 0.f) ? x : 0.01f*x;
    }
    __syncthreads();
    const int c0 = 2*t;
    float a0[8], a1[8];
    {
        float b0 = ib2[c0], b1 = ib2[c0+1];
        #pragma unroll
        for (int g = 0; g < 8; g++) { a0[g] = b0; a1[g] = b1; }
    }
    for (int l = 0; l < NH; l++) {
        float2 w = *(const float2*)&iW2[l*(2*LAT) + c0];
        #pragma unroll
        for (int g = 0; g < 8; g++) {
            float hv = h[g][l];
            a0[g] = fmaf(hv, w.x, a0[g]);
            a1[g] = fmaf(hv, w.y, a1[g]);
        }
    }
    if (t < 128) {
        #pragma unroll
        for (int g = 0; g < 8; g++) { sMu[g][c0] = a0[g]; sMu[g][c0+1] = a1[g]; }
    }
    __syncthreads();
    float kp = 0.f;
    if (t >= 128) {
        const int li = c0 - LAT;
        #pragma unroll
        for (int g = 0; g < 8; g++) {
            int gi = (i0+g)*LAT + li;
            float vq0 = fmaxf(expf(a0[g]), 0.002f);
            float vq1 = fmaxf(expf(a1[g]), 0.002f);
            float lsq0 = 0.5f*logf(vq0), lsq1 = 0.5f*logf(vq1);
            float2 mu = *(const float2*)&g_mu[gi];
            float2 vv = *(const float2*)&g_var[gi];
            float2 ls = *(const float2*)&g_logsig[gi];
            float d0 = mu.x - sMu[g][li];
            float d1 = mu.y - sMu[g][li+1];
            kp += (lsq0 - ls.x + (vv.x + d0*d0) / (2.f*vq0) - 0.5f)
                + (lsq1 - ls.y + (vv.y + d1*d1) / (2.f*vq1) - 0.5f);
        }
    }
    red[t] = kp;
    __syncthreads();
    for (int o = 128; o; o >>= 1) { if (t < o) red[t] += red[t+o]; __syncthreads(); }
    if (t == 0) atomicAdd(&g_kl, (double)red[0]);
}

// ---------------- A = latent @ dW1[:256], B = latent @ dW1[256:], 8 rows/block ----------------
__global__ void k_AB(const float* __restrict__ dW1) {
    int i0 = blockIdx.x * 8, t = threadIdx.x;   // 64 blocks, 256 threads
    __shared__ float L[8][LAT];
    __shared__ float pa[4][8][NH], pb[4][8][NH];
    for (int idx = t; idx < 8*LAT; idx += 256) {
        int g = idx >> 8, c = idx & 255;
        L[g][c] = g_lat[(i0+g)*LAT + c];
    }
    __syncthreads();
    const int c = t & 63, q = t >> 6;
    float accA[8] = {0.f,0.f,0.f,0.f,0.f,0.f,0.f,0.f};
    float accB[8] = {0.f,0.f,0.f,0.f,0.f,0.f,0.f,0.f};
    const int l0 = q * 64;
    for (int l = l0; l < l0 + 64; l++) {
        float wa = dW1[l*NH + c];
        float wb = dW1[(l + LAT)*NH + c];
        #pragma unroll
        for (int g = 0; g < 8; g++) {
            float lv = L[g][l];
            accA[g] = fmaf(lv, wa, accA[g]);
            accB[g] = fmaf(lv, wb, accB[g]);
        }
    }
    #pragma unroll
    for (int g = 0; g < 8; g++) { pa[q][g][c] = accA[g]; pb[q][g][c] = accB[g]; }
    __syncthreads();
    for (int idx = t; idx < 512; idx += 256) {
        int g = idx >> 6, c2 = idx & 63;
        g_A[(i0+g)*NH + c2] = pa[0][g][c2] + pa[1][g][c2] + pa[2][g][c2] + pa[3][g][c2];
        g_B[(i0+g)*NH + c2] = pb[0][g][c2] + pb[1][g][c2] + pb[2][g][c2] + pb[3][g][c2];
    }
}

// ---------------- fused: col stats + center (in place) + circ-corr -> w1 ----------------
__global__ void k_col(const float* __restrict__ dg) {
    int c = blockIdx.x, s = threadIdx.x;   // 64 blocks, 512 threads
    __shared__ float a[NA], b[NA], r1[NA], r2[NA];
    float av = g_A[s*NH + c], bv = g_B[s*NH + c];
    r1[s] = av; r2[s] = bv;
    __syncthreads();
    for (int o = 256; o; o >>= 1) {
        if (s < o) { r1[s] += r1[s+o]; r2[s] += r2[s+o]; }
        __syncthreads();
    }
    float mA = r1[0] * (1.f/NA), mB = r2[0] * (1.f/NA);
    __syncthreads();
    av -= mA; bv -= mB;
    a[s] = av; b[s] = bv;
    g_A[s*NH + c] = av;
    g_B[s*NH + c] = bv;
    r1[s] = av*av + bv*bv;
    __syncthreads();
    for (int o = 256; o; o >>= 1) { if (s < o) r1[s] += r1[s+o]; __syncthreads(); }
    float s2 = r1[0] * (1.f/NA);
    float cr = 0.f;
    #pragma unroll 8
    for (int j = 0; j < NA; j++) cr = fmaf(a[j], b[(j - s - 1) & (NA-1)], cr);
    float var = s2 + 2.f * cr * (1.f/NA);
    g_w1[s*NH + c] = dg[c] * rsqrtf(var + BNEPS);
}

// ---------------- fused MI (z=0) + DIS (z=1), R5 bodies ----------------
__global__ void k_midis(const float* __restrict__ dbt,
                        const float* __restrict__ dW2,
                        const float* __restrict__ db2) {
    __shared__ float sh[8448];
    const int tid = threadIdx.x;            // 256
    const int j0 = blockIdx.x * 32, s0 = blockIdx.y * 32;
    const int tx = tid & 15, ty = tid >> 4;
    const int jj0 = 2*tx, ss0 = 2*ty;
    const int base = (j0 - s0 - 32) & (NA-1);
    if (blockIdx.z == 0) {
        // ---- MI (R5 structure: 32-wide l chunks, mu/ni/cc staged in smem) ----
        float* sMU = sh;            // 32*33
        float* sNI = sh + 1056;     // 32*33
        float* sCC = sh + 2112;     // 32*33
        float* sL  = sh + 3168;     // 64*33
        float acc00 = 0.f, acc01 = 0.f, acc10 = 0.f, acc11 = 0.f;
        for (int l0 = 0; l0 < LAT; l0 += 32) {
            #pragma unroll
            for (int i = 0; i < 4; i++) {
                int idx = tid + i*256;
                int r = idx >> 5, cc = idx & 31;
                int g = (j0 + r)*LAT + l0 + cc;
                sMU[r*33+cc] = g_mu[g]; sNI[r*33+cc] = g_ni2v[g]; sCC[r*33+cc] = g_cc[g];
            }
            #pragma unroll
            for (int i = 0; i < 8; i++) {
                int idx = tid + i*256;
                int r = idx >> 5, cc = idx & 31;
                sL[r*33+cc] = g_lat[((base + r) & (NA-1))*LAT + l0 + cc];
            }
            __syncthreads();
            #pragma unroll
            for (int l = 0; l < 32; l++) {
                float mu0 = sMU[jj0*33+l],   mu1 = sMU[(jj0+1)*33+l];
                float n0  = sNI[jj0*33+l],   n1  = sNI[(jj0+1)*33+l];
                float c0  = sCC[jj0*33+l],   c1  = sCC[(jj0+1)*33+l];
                {
                    float L0 = sL[(jj0   - ss0 + 31)*33+l];
                    float L1 = sL[(jj0+1 - ss0 + 31)*33+l];
                    float d0 = L0 - mu0; acc00 += fmaxf(fmaf(d0*d0, n0, c0), -13.9f);
                    float d1 = L1 - mu1; acc01 += fmaxf(fmaf(d1*d1, n1, c1), -13.9f);
                }
                {
                    float L0 = sL[(jj0   - ss0 + 30)*33+l];
                    float L1 = sL[(jj0+1 - ss0 + 30)*33+l];
                    float d0 = L0 - mu0; acc10 += fmaxf(fmaf(d0*d0, n0, c0), -13.9f);
                    float d1 = L1 - mu1; acc11 += fmaxf(fmaf(d1*d1, n1, c1), -13.9f);
                }
            }
            __syncthreads();
        }
        const float inv = 1.f / LAT;
        g_mi[(s0+ss0  )*NA + j0+jj0  ] = acc00 * inv;
        g_mi[(s0+ss0  )*NA + j0+jj0+1] = acc01 * inv;
        g_mi[(s0+ss0+1)*NA + j0+jj0  ] = acc10 * inv;
        g_mi[(s0+ss0+1)*NA + j0+jj0+1] = acc11 * inv;
    } else {
        // ---- DIS ----
        float* sa   = sh;                 // 32*65
        float* sw   = sh + 2080;          // 32*65
        float* sb   = sh + 4160;          // 64*65
        float* sdbt = sh + 8320;          // 64
        float* sdw2 = sh + 8384;          // 64
        if (tid < NH) { sdbt[tid] = dbt[tid]; sdw2[tid] = dW2[tid]; }
        #pragma unroll
        for (int i = 0; i < 8; i++) {
            int idx = tid + i*256;
            int r = idx >> 6, c = idx & 63;
            sa[r*65 + c] = g_A[(j0 + r)*NH + c];
            sw[r*65 + c] = g_w1[(s0 + r)*NH + c];
        }
        #pragma unroll
        for (int i = 0; i < 16; i++) {
            int idx = tid + i*256;
            int r = idx >> 6, c = idx & 63;
            sb[r*65 + c] = g_B[((base + r) & (NA-1))*NH + c];
        }
        __syncthreads();
        float acc00 = 0.f, acc01 = 0.f, acc10 = 0.f, acc11 = 0.f;
        #pragma unroll 8
        for (int c = 0; c < NH; c++) {
            float a0 = sa[jj0*65 + c], a1 = sa[(jj0+1)*65 + c];
            float w0 = sw[ss0*65 + c], w1v = sw[(ss0+1)*65 + c];
            float bt = sdbt[c], w2 = sdw2[c];
            {
                float b0 = sb[(jj0   - ss0 + 31)*65 + c];
                float b1 = sb[(jj0+1 - ss0 + 31)*65 + c];
                float v0 = fmaf(a0 + b0, w0, bt); v0 = (v0 > 0.f) ? v0 : 0.01f*v0;
                float v1 = fmaf(a1 + b1, w0, bt); v1 = (v1 > 0.f) ? v1 : 0.01f*v1;
                acc00 = fmaf(v0, w2, acc00);
                acc01 = fmaf(v1, w2, acc01);
            }
            {
                float b0 = sb[(jj0   - ss0 + 30)*65 + c];
                float b1 = sb[(jj0+1 - ss0 + 30)*65 + c];
                float v0 = fmaf(a0 + b0, w1v, bt); v0 = (v0 > 0.f) ? v0 : 0.01f*v0;
                float v1 = fmaf(a1 + b1, w1v, bt); v1 = (v1 > 0.f) ? v1 : 0.01f*v1;
                acc10 = fmaf(v0, w2, acc10);
                acc11 = fmaf(v1, w2, acc11);
            }
        }
        float b2 = db2[0];
        g_dis[(s0+ss0  )*NA + j0+jj0  ] = fabsf(acc00 + b2);
        g_dis[(s0+ss0  )*NA + j0+jj0+1] = fabsf(acc01 + b2);
        g_dis[(s0+ss0+1)*NA + j0+jj0  ] = fabsf(acc10 + b2);
        g_dis[(s0+ss0+1)*NA + j0+jj0+1] = fabsf(acc11 + b2);
    }
}

// ---------------- min/max partials ----------------
__global__ void k_minmax() {
    int tid = threadIdx.x;
    int base = blockIdx.x * 1024;
    float mn0 = 1e30f, mx0 = -1e30f, mn1 = 1e30f, mx1 = -1e30f;
    #pragma unroll
    for (int i = 0; i < 4; i++) {
        int idx = base + tid + i*256;
        float a = g_mi[idx], d = g_dis[idx];
        mn0 = fminf(mn0, a); mx0 = fmaxf(mx0, a);
        mn1 = fminf(mn1, d); mx1 = fmaxf(mx1, d);
    }
    __shared__ float r0[256], r1[256], r2[256], r3[256];
    r0[tid] = mn0; r1[tid] = mx0; r2[tid] = mn1; r3[tid] = mx1;
    __syncthreads();
    for (int o = 128; o; o >>= 1) {
        if (tid < o) {
            r0[tid] = fminf(r0[tid], r0[tid+o]);
            r1[tid] = fmaxf(r1[tid], r1[tid+o]);
            r2[tid] = fminf(r2[tid], r2[tid+o]);
            r3[tid] = fmaxf(r3[tid], r3[tid+o]);
        }
        __syncthreads();
    }
    if (tid == 0) {
        g_pmin[0][blockIdx.x] = r0[0]; g_pmax[0][blockIdx.x] = r1[0];
        g_pmin[1][blockIdx.x] = r2[0]; g_pmax[1][blockIdx.x] = r3[0];
    }
}

__global__ void k_norm() {
    int tid = threadIdx.x;   // 256
    __shared__ float r0[256], r1[256], r2[256], r3[256];
    r0[tid] = g_pmin[0][tid]; r1[tid] = g_pmax[0][tid];
    r2[tid] = g_pmin[1][tid]; r3[tid] = g_pmax[1][tid];
    __syncthreads();
    for (int o = 128; o; o >>= 1) {
        if (tid < o) {
            r0[tid] = fminf(r0[tid], r0[tid+o]);
            r1[tid] = fmaxf(r1[tid], r1[tid+o]);
            r2[tid] = fminf(r2[tid], r2[tid+o]);
            r3[tid] = fmaxf(r3[tid], r3[tid+o]);
        }
        __syncthreads();
    }
    if (tid == 0) {
        g_norm[0] = r0[0];
        g_norm[1] = 1.f / (r1[0] - r0[0] + 1e-12f);
        g_norm[2] = r2[0];
        g_norm[3] = 1.f / (r3[0] - r2[0] + 1e-12f);
    }
}

// ---------------- normalized sums ----------------
__global__ void k_sums() {
    int tid = threadIdx.x;
    int base = blockIdx.x * 1024;
    float mi_min = g_norm[0], mi_inv = g_norm[1];
    float ds_min = g_norm[2], ds_inv = g_norm[3];
    double s1 = 0.0, s2 = 0.0;
    #pragma unroll
    for (int i = 0; i < 4; i++) {
        int idx = base + tid + i*256;
        float mi_n = (g_mi[idx] - mi_min) * mi_inv;
        float ds_n = (g_dis[idx] - ds_min) * ds_inv;
        s1 += (double)ds_n;
        s2 += (double)fminf(mi_n + ds_n, 1.0f);
    }
    __shared__ double d1[256], d2[256];
    d1[tid] = s1; d2[tid] = s2;
    __syncthreads();
    for (int o = 128; o; o >>= 1) {
        if (tid < o) { d1[tid] += d1[tid+o]; d2[tid] += d2[tid+o]; }
        __syncthreads();
    }
    if (tid == 0) {
        atomicAdd(&g_sum_disn, d1[0]);
        atomicAdd(&g_sum_min, d2[0]);
    }
}

// ---------------- final scalar assembly ----------------
__global__ void k_final(float* __restrict__ out) {
    double ent = g_ent / (double)NA;
    double kl  = g_kl  / (double)NA;
    double loss0 = fmin(ent*1e-4 + kl*1e-4, 2000.0);
    double ce = log1p(exp(loss0));
    double dis_norm = g_sum_disn / (double)NA;
    double dis_loss = -g_sum_min / (double)NA;
    double cdis = (dis_norm + dis_loss) / (double)NA;
    out[0] = (float)(ce + cdis);
    out[1] = (float)cdis;
    out[2] = (float)ce;
}

// ---------------- launcher ----------------
extern "C" void kernel_launch(void* const* d_in, const int* in_sizes, int n_in,
                              void* d_out, int out_size) {
    const float* obs  = (const float*)d_in[0];
    const float* hid  = (const float*)d_in[1];
    const float* eps  = (const float*)d_in[2];
    const float* eW1  = (const float*)d_in[3];
    const float* eb1  = (const float*)d_in[4];
    const float* eg   = (const float*)d_in[5];
    const float* ebt  = (const float*)d_in[6];
    const float* eW2  = (const float*)d_in[7];
    const float* eb2  = (const float*)d_in[8];
    const float* iW1  = (const float*)d_in[9];
    const float* ib1  = (const float*)d_in[10];
    const float* ig   = (const float*)d_in[11];
    const float* ibt  = (const float*)d_in[12];
    const float* iW2  = (const float*)d_in[13];
    const float* ib2  = (const float*)d_in[14];
    const float* dW1  = (const float*)d_in[15];
    const float* db1  = (const float*)d_in[16]; (void)db1; // cancels in BN
    const float* dg   = (const float*)d_in[17];
    const float* dbt  = (const float*)d_in[18];
    const float* dW2  = (const float*)d_in[19];
    const float* db2  = (const float*)d_in[20];
    float* out = (float*)d_out;

    k_lin<<<128, 128>>>(obs, hid, eW1, eb1, iW1, ib1);
    k_bn<<<2, 1024>>>(eg, ebt, ig, ibt);
    k_lat_e<<<64, 256>>>(eW2, eb2, eps);
    k_lat_i<<<64, 256>>>(iW2, ib2);
    k_AB<<<64, 256>>>(dW1);
    k_col<<<NH, 512>>>(dg);
    k_midis<<<dim3(16, 16, 2), 256>>>(dbt, dW2, db2);
    k_minmax<<<256, 256>>>();
    k_norm<<<1, 256>>>();
    k_sums<<<256, 256>>>();
    k_final<<<1, 1>>>(out);
}

// round 8
// speedup vs baseline: 2.4190x; 1.3321x over previous
#include <cuda_runtime.h>
#include <math.h>

#define NA   512
#define OBSD 128
#define INP  656
#define HID  64
#define LAT  256
#define NH   64
#define LOG2PI 1.8378770664093453f
#define BNEPS 1e-5f

// ---------------- scratch (device globals; no allocation allowed) ----------------
__device__ __align__(16) float g_pre_e[NA*NH];
__device__ __align__(16) float g_pre_i[NA*NH];
__device__ float g_scale[2][NH], g_shift[2][NH];
__device__ __align__(16) float g_mu[NA*LAT], g_var[NA*LAT], g_logsig[NA*LAT];
__device__ __align__(16) float g_ni2v[NA*LAT], g_cc[NA*LAT], g_lat[NA*LAT];
__device__ __align__(16) float g_A[NA*NH], g_B[NA*NH];
__device__ __align__(16) float g_w1[NA*NH];
__device__ __align__(16) float g_mi[NA*NA], g_dis[NA*NA];
__device__ double g_ent, g_kl, g_sum_disn, g_sum_min;
__device__ float g_pmin[2][256], g_pmax[2][256];
__device__ float g_norm[4];   // mi_min, mi_inv, dis_min, dis_inv

// ---------------- fused linear1 (encoder + inference), 1 row/block, 8-way split ----------------
__global__ void k_lin(const float* __restrict__ obs, const float* __restrict__ hid,
                      const float* __restrict__ eW1, const float* __restrict__ eb1,
                      const float* __restrict__ iW1, const float* __restrict__ ib1) {
    int b = blockIdx.x, t = threadIdx.x;   // 1024 blocks, 128 threads
    if (b == 0 && t == 0) {
        g_ent = 0.0; g_kl = 0.0; g_sum_disn = 0.0; g_sum_min = 0.0;
    }
    __shared__ float s[HID + INP];
    __shared__ float part[8][NH];
    int g = t & 15, hh = t >> 4;   // 16 col-groups x 8 l-slices
    int c0 = g * 4;
    float4 acc = make_float4(0.f, 0.f, 0.f, 0.f);
    if (b < NA) {
        int i = b;
        if (t < OBSD) s[t] = obs[i*INP + (INP-OBSD) + t];
        __syncthreads();
        int l0 = hh * 16;
        #pragma unroll 16
        for (int l = l0; l < l0 + 16; l++) {
            float4 w = *(const float4*)&eW1[l*NH + c0];
            float x = s[l];
            acc.x = fmaf(x, w.x, acc.x); acc.y = fmaf(x, w.y, acc.y);
            acc.z = fmaf(x, w.z, acc.z); acc.w = fmaf(x, w.w, acc.w);
        }
        part[hh][c0+0] = acc.x; part[hh][c0+1] = acc.y;
        part[hh][c0+2] = acc.z; part[hh][c0+3] = acc.w;
        __syncthreads();
        if (t < NH) {
            float r = eb1[t];
            #pragma unroll
            for (int k = 0; k < 8; k++) r += part[k][t];
            g_pre_e[i*NH + t] = r;
        }
    } else {
        int i = b - NA;
        for (int l = t; l < HID; l += 128) s[l] = hid[i*HID + l];
        for (int l = t; l < INP; l += 128) s[HID + l] = obs[i*INP + l];
        __syncthreads();
        int l0 = hh * 90;
        #pragma unroll 10
        for (int l = l0; l < l0 + 90; l++) {
            float4 w = *(const float4*)&iW1[l*NH + c0];
            float x = s[l];
            acc.x = fmaf(x, w.x, acc.x); acc.y = fmaf(x, w.y, acc.y);
            acc.z = fmaf(x, w.z, acc.z); acc.w = fmaf(x, w.w, acc.w);
        }
        part[hh][c0+0] = acc.x; part[hh][c0+1] = acc.y;
        part[hh][c0+2] = acc.z; part[hh][c0+3] = acc.w;
        __syncthreads();
        if (t < NH) {
            float r = ib1[t];
            #pragma unroll
            for (int k = 0; k < 8; k++) r += part[k][t];
            g_pre_i[i*NH + t] = r;
        }
    }
}

// ---------------- fused BN stats (both tensors), single pass, coalesced ----------------
__global__ void k_bn(const float* __restrict__ eg, const float* __restrict__ ebt,
                     const float* __restrict__ ig, const float* __restrict__ ibt) {
    int which = blockIdx.x;    // 2 blocks, 1024 threads
    const float* pre = which ? g_pre_i : g_pre_e;
    const float* gm  = which ? ig  : eg;
    const float* bt  = which ? ibt : ebt;
    int t = threadIdx.x;
    int c = t & 63, rg = t >> 6;   // 16 row groups
    float s = 0.f, s2 = 0.f;
    for (int r = rg; r < NA; r += 16) {
        float x = pre[r*NH + c];   // addr = t + 1024k : fully coalesced
        s += x; s2 = fmaf(x, x, s2);
    }
    __shared__ float sh1[16][NH], sh2[16][NH];
    sh1[rg][c] = s; sh2[rg][c] = s2;
    __syncthreads();
    if (t < NH) {
        float a = 0.f, b = 0.f;
        #pragma unroll
        for (int k = 0; k < 16; k++) { a += sh1[k][t]; b += sh2[k][t]; }
        float mean = a * (1.f/NA);
        float var = b * (1.f/NA) - mean*mean;
        float sc = gm[t] * rsqrtf(var + BNEPS);
        g_scale[which][t] = sc;
        g_shift[which][t] = bt[t] - mean*sc;
    }
}

// ---------------- encoder linear2 + latent head, 2 rows/block + entropy ----------------
__global__ void k_lat_e(const float* __restrict__ eW2,
                        const float* __restrict__ eb2,
                        const float* __restrict__ eps) {
    int i0 = blockIdx.x * 2, t = threadIdx.x;   // 256 blocks, 256 threads
    __shared__ float h[2][NH];
    __shared__ float sMu[2][LAT];
    __shared__ float red[256];
    if (t < 128) {
        int g = t >> 6, c = t & 63;
        float x = fmaf(g_pre_e[(i0+g)*NH + c], g_scale[0][c], g_shift[0][c]);
        h[g][c] = (x > 0.f) ? x : 0.01f*x;
    }
    __syncthreads();
    const int c0 = 2*t;
    float b0v = eb2[c0], b1v = eb2[c0+1];
    float a00 = b0v, a01 = b1v, a10 = b0v, a11 = b1v;
    #pragma unroll 8
    for (int l = 0; l < NH; l++) {
        float2 w = *(const float2*)&eW2[l*(2*LAT) + c0];
        float h0 = h[0][l], h1 = h[1][l];
        a00 = fmaf(h0, w.x, a00); a01 = fmaf(h0, w.y, a01);
        a10 = fmaf(h1, w.x, a10); a11 = fmaf(h1, w.y, a11);
    }
    if (t < 128) {
        sMu[0][c0] = a00; sMu[0][c0+1] = a01;
        sMu[1][c0] = a10; sMu[1][c0+1] = a11;
        *(float2*)&g_mu[i0*LAT + c0]     = make_float2(a00, a01);
        *(float2*)&g_mu[(i0+1)*LAT + c0] = make_float2(a10, a11);
    }
    __syncthreads();
    float ep = 0.f;
    if (t >= 128) {
        const int li = c0 - 2*LAT;   // c0 in [256,510] -> li in [0,254]
        float av0[2] = {a00, a10}, av1[2] = {a01, a11};
        #pragma unroll
        for (int g = 0; g < 2; g++) {
            int gi = (i0+g)*LAT + li + LAT;     // wait: li+LAT would exceed; fix below
            gi = (i0+g)*LAT + (c0 - LAT) - LAT + LAT; // simplify
            gi = (i0+g)*LAT + (c0 - LAT);
            // c0-LAT in [0,254]? c0 in [256,510] -> c0-256 in [0,254]. LAT==256. OK.
            float v0 = fmaxf(expf(av0[g]), 0.002f);
            float v1 = fmaxf(expf(av1[g]), 0.002f);
            float ls0 = 0.5f*logf(v0), ls1 = 0.5f*logf(v1);
            float mu0 = sMu[g][c0 - LAT], mu1 = sMu[g][c0 - LAT + 1];
            *(float2*)&g_var[gi]    = make_float2(v0, v1);
            *(float2*)&g_logsig[gi] = make_float2(ls0, ls1);
            *(float2*)&g_ni2v[gi]   = make_float2(-0.5f/v0, -0.5f/v1);
            *(float2*)&g_cc[gi]     = make_float2(13.9f - ls0 - 0.5f*LOG2PI,
                                                  13.9f - ls1 - 0.5f*LOG2PI);
            float2 e2 = *(const float2*)&eps[gi];
            *(float2*)&g_lat[gi] = make_float2(fmaf(sqrtf(v0), e2.x, mu0),
                                               fmaf(sqrtf(v1), e2.y, mu1));
            ep += 1.f + LOG2PI + ls0 + ls1;
        }
    }
    red[t] = ep;
    __syncthreads();
    for (int o = 128; o; o >>= 1) { if (t < o) red[t] += red[t+o]; __syncthreads(); }
    if (t == 0) atomicAdd(&g_ent, (double)red[0]);
}

// ---------------- inference linear2 + KL, 2 rows/block ----------------
__global__ void k_lat_i(const float* __restrict__ iW2,
                        const float* __restrict__ ib2) {
    int i0 = blockIdx.x * 2, t = threadIdx.x;   // 256 blocks, 256 threads
    __shared__ float h[2][NH];
    __shared__ float sMu[2][LAT];
    __shared__ float red[256];
    if (t < 128) {
        int g = t >> 6, c = t & 63;
        float x = fmaf(g_pre_i[(i0+g)*NH + c], g_scale[1][c], g_shift[1][c]);
        h[g][c] = (x > 0.f) ? x : 0.01f*x;
    }
    __syncthreads();
    const int c0 = 2*t;
    float b0v = ib2[c0], b1v = ib2[c0+1];
    float a00 = b0v, a01 = b1v, a10 = b0v, a11 = b1v;
    #pragma unroll 8
    for (int l = 0; l < NH; l++) {
        float2 w = *(const float2*)&iW2[l*(2*LAT) + c0];
        float h0 = h[0][l], h1 = h[1][l];
        a00 = fmaf(h0, w.x, a00); a01 = fmaf(h0, w.y, a01);
        a10 = fmaf(h1, w.x, a10); a11 = fmaf(h1, w.y, a11);
    }
    if (t < 128) {
        sMu[0][c0] = a00; sMu[0][c0+1] = a01;
        sMu[1][c0] = a10; sMu[1][c0+1] = a11;
    }
    __syncthreads();
    float kp = 0.f;
    if (t >= 128) {
        float av0[2] = {a00, a10}, av1[2] = {a01, a11};
        #pragma unroll
        for (int g = 0; g < 2; g++) {
            int li = c0 - LAT;
            int gi = (i0+g)*LAT + li;
            float vq0 = fmaxf(expf(av0[g]), 0.002f);
            float vq1 = fmaxf(expf(av1[g]), 0.002f);
            float lsq0 = 0.5f*logf(vq0), lsq1 = 0.5f*logf(vq1);
            float2 mu = *(const float2*)&g_mu[gi];
            float2 vv = *(const float2*)&g_var[gi];
            float2 ls = *(const float2*)&g_logsig[gi];
            float d0 = mu.x - sMu[g][li];
            float d1 = mu.y - sMu[g][li+1];
            kp += (lsq0 - ls.x + (vv.x + d0*d0) / (2.f*vq0) - 0.5f)
                + (lsq1 - ls.y + (vv.y + d1*d1) / (2.f*vq1) - 0.5f);
        }
    }
    red[t] = kp;
    __syncthreads();
    for (int o = 128; o; o >>= 1) { if (t < o) red[t] += red[t+o]; __syncthreads(); }
    if (t == 0) atomicAdd(&g_kl, (double)red[0]);
}

// ---------------- A = latent @ dW1[:256], B = latent @ dW1[256:] ----------------
__global__ void k_AB(const float* __restrict__ dW1) {
    int j = blockIdx.x, t = threadIdx.x;   // 512 blocks, 256 threads
    int c = t & 63, q = t >> 6;
    __shared__ float L[LAT];
    __shared__ float pa[4][NH], pb[4][NH];
    L[t] = g_lat[j*LAT + t];
    __syncthreads();
    float a = 0.f, b = 0.f;
    int l0 = q * 64;
    #pragma unroll 8
    for (int l = l0; l < l0 + 64; l++) {
        float lv = L[l];
        a = fmaf(lv, dW1[l*NH + c], a);
        b = fmaf(lv, dW1[(l + LAT)*NH + c], b);
    }
    pa[q][c] = a; pb[q][c] = b;
    __syncthreads();
    if (q == 0) {
        g_A[j*NH + c] = pa[0][c] + pa[1][c] + pa[2][c] + pa[3][c];
        g_B[j*NH + c] = pb[0][c] + pb[1][c] + pb[2][c] + pb[3][c];
    }
}

// ---------------- fused: col stats + center (in place) + circ-corr -> w1 ----------------
__global__ void k_col(const float* __restrict__ dg) {
    int c = blockIdx.x, s = threadIdx.x;   // 64 blocks, 512 threads
    __shared__ float a[NA], b[NA], r1[NA], r2[NA];
    float av = g_A[s*NH + c], bv = g_B[s*NH + c];
    r1[s] = av; r2[s] = bv;
    __syncthreads();
    for (int o = 256; o; o >>= 1) {
        if (s < o) { r1[s] += r1[s+o]; r2[s] += r2[s+o]; }
        __syncthreads();
    }
    float mA = r1[0] * (1.f/NA), mB = r2[0] * (1.f/NA);
    __syncthreads();
    av -= mA; bv -= mB;
    a[s] = av; b[s] = bv;
    g_A[s*NH + c] = av;
    g_B[s*NH + c] = bv;
    r1[s] = av*av + bv*bv;
    __syncthreads();
    for (int o = 256; o; o >>= 1) { if (s < o) r1[s] += r1[s+o]; __syncthreads(); }
    float s2 = r1[0] * (1.f/NA);
    float cr = 0.f;
    #pragma unroll 8
    for (int j = 0; j < NA; j++) cr = fmaf(a[j], b[(j - s - 1) & (NA-1)], cr);
    float var = s2 + 2.f * cr * (1.f/NA);
    g_w1[s*NH + c] = dg[c] * rsqrtf(var + BNEPS);
}

// ---------------- fused MI (z=0) + DIS (z=1), R5 bodies ----------------
__global__ void k_midis(const float* __restrict__ dbt,
                        const float* __restrict__ dW2,
                        const float* __restrict__ db2) {
    __shared__ float sh[8448];
    const int tid = threadIdx.x;            // 256
    const int j0 = blockIdx.x * 32, s0 = blockIdx.y * 32;
    const int tx = tid & 15, ty = tid >> 4;
    const int jj0 = 2*tx, ss0 = 2*ty;
    const int base = (j0 - s0 - 32) & (NA-1);
    if (blockIdx.z == 0) {
        float* sMU = sh;            // 32*33
        float* sNI = sh + 1056;     // 32*33
        float* sCC = sh + 2112;     // 32*33
        float* sL  = sh + 3168;     // 64*33
        float acc00 = 0.f, acc01 = 0.f, acc10 = 0.f, acc11 = 0.f;
        for (int l0 = 0; l0 < LAT; l0 += 32) {
            #pragma unroll
            for (int i = 0; i < 4; i++) {
                int idx = tid + i*256;
                int r = idx >> 5, cc = idx & 31;
                int g = (j0 + r)*LAT + l0 + cc;
                sMU[r*33+cc] = g_mu[g]; sNI[r*33+cc] = g_ni2v[g]; sCC[r*33+cc] = g_cc[g];
            }
            #pragma unroll
            for (int i = 0; i < 8; i++) {
                int idx = tid + i*256;
                int r = idx >> 5, cc = idx & 31;
                sL[r*33+cc] = g_lat[((base + r) & (NA-1))*LAT + l0 + cc];
            }
            __syncthreads();
            #pragma unroll
            for (int l = 0; l < 32; l++) {
                float mu0 = sMU[jj0*33+l],   mu1 = sMU[(jj0+1)*33+l];
                float n0  = sNI[jj0*33+l],   n1  = sNI[(jj0+1)*33+l];
                float c0  = sCC[jj0*33+l],   c1  = sCC[(jj0+1)*33+l];
                {
                    float L0 = sL[(jj0   - ss0 + 31)*33+l];
                    float L1 = sL[(jj0+1 - ss0 + 31)*33+l];
                    float d0 = L0 - mu0; acc00 += fmaxf(fmaf(d0*d0, n0, c0), -13.9f);
                    float d1 = L1 - mu1; acc01 += fmaxf(fmaf(d1*d1, n1, c1), -13.9f);
                }
                {
                    float L0 = sL[(jj0   - ss0 + 30)*33+l];
                    float L1 = sL[(jj0+1 - ss0 + 30)*33+l];
                    float d0 = L0 - mu0; acc10 += fmaxf(fmaf(d0*d0, n0, c0), -13.9f);
                    float d1 = L1 - mu1; acc11 += fmaxf(fmaf(d1*d1, n1, c1), -13.9f);
                }
            }
            __syncthreads();
        }
        const float inv = 1.f / LAT;
        g_mi[(s0+ss0  )*NA + j0+jj0  ] = acc00 * inv;
        g_mi[(s0+ss0  )*NA + j0+jj0+1] = acc01 * inv;
        g_mi[(s0+ss0+1)*NA + j0+jj0  ] = acc10 * inv;
        g_mi[(s0+ss0+1)*NA + j0+jj0+1] = acc11 * inv;
    } else {
        float* sa   = sh;                 // 32*65
        float* sw   = sh + 2080;          // 32*65
        float* sb   = sh + 4160;          // 64*65
        float* sdbt = sh + 8320;          // 64
        float* sdw2 = sh + 8384;          // 64
        if (tid < NH) { sdbt[tid] = dbt[tid]; sdw2[tid] = dW2[tid]; }
        #pragma unroll
        for (int i = 0; i < 8; i++) {
            int idx = tid + i*256;
            int r = idx >> 6, c = idx & 63;
            sa[r*65 + c] = g_A[(j0 + r)*NH + c];
            sw[r*65 + c] = g_w1[(s0 + r)*NH + c];
        }
        #pragma unroll
        for (int i = 0; i < 16; i++) {
            int idx = tid + i*256;
            int r = idx >> 6, c = idx & 63;
            sb[r*65 + c] = g_B[((base + r) & (NA-1))*NH + c];
        }
        __syncthreads();
        float acc00 = 0.f, acc01 = 0.f, acc10 = 0.f, acc11 = 0.f;
        #pragma unroll 8
        for (int c = 0; c < NH; c++) {
            float a0 = sa[jj0*65 + c], a1 = sa[(jj0+1)*65 + c];
            float w0 = sw[ss0*65 + c], w1v = sw[(ss0+1)*65 + c];
            float bt = sdbt[c], w2 = sdw2[c];
            {
                float b0 = sb[(jj0   - ss0 + 31)*65 + c];
                float b1 = sb[(jj0+1 - ss0 + 31)*65 + c];
                float v0 = fmaf(a0 + b0, w0, bt); v0 = (v0 > 0.f) ? v0 : 0.01f*v0;
                float v1 = fmaf(a1 + b1, w0, bt); v1 = (v1 > 0.f) ? v1 : 0.01f*v1;
                acc00 = fmaf(v0, w2, acc00);
                acc01 = fmaf(v1, w2, acc01);
            }
            {
                float b0 = sb[(jj0   - ss0 + 30)*65 + c];
                float b1 = sb[(jj0+1 - ss0 + 30)*65 + c];
                float v0 = fmaf(a0 + b0, w1v, bt); v0 = (v0 > 0.f) ? v0 : 0.01f*v0;
                float v1 = fmaf(a1 + b1, w1v, bt); v1 = (v1 > 0.f) ? v1 : 0.01f*v1;
                acc10 = fmaf(v0, w2, acc10);
                acc11 = fmaf(v1, w2, acc11);
            }
        }
        float b2 = db2[0];
        g_dis[(s0+ss0  )*NA + j0+jj0  ] = fabsf(acc00 + b2);
        g_dis[(s0+ss0  )*NA + j0+jj0+1] = fabsf(acc01 + b2);
        g_dis[(s0+ss0+1)*NA + j0+jj0  ] = fabsf(acc10 + b2);
        g_dis[(s0+ss0+1)*NA + j0+jj0+1] = fabsf(acc11 + b2);
    }
}

// ---------------- min/max partials ----------------
__global__ void k_minmax() {
    int tid = threadIdx.x;
    int base = blockIdx.x * 1024;
    float mn0 = 1e30f, mx0 = -1e30f, mn1 = 1e30f, mx1 = -1e30f;
    #pragma unroll
    for (int i = 0; i < 4; i++) {
        int idx = base + tid + i*256;
        float a = g_mi[idx], d = g_dis[idx];
        mn0 = fminf(mn0, a); mx0 = fmaxf(mx0, a);
        mn1 = fminf(mn1, d); mx1 = fmaxf(mx1, d);
    }
    __shared__ float r0[256], r1[256], r2[256], r3[256];
    r0[tid] = mn0; r1[tid] = mx0; r2[tid] = mn1; r3[tid] = mx1;
    __syncthreads();
    for (int o = 128; o; o >>= 1) {
        if (tid < o) {
            r0[tid] = fminf(r0[tid], r0[tid+o]);
            r1[tid] = fmaxf(r1[tid], r1[tid+o]);
            r2[tid] = fminf(r2[tid], r2[tid+o]);
            r3[tid] = fmaxf(r3[tid], r3[tid+o]);
        }
        __syncthreads();
    }
    if (tid == 0) {
        g_pmin[0][blockIdx.x] = r0[0]; g_pmax[0][blockIdx.x] = r1[0];
        g_pmin[1][blockIdx.x] = r2[0]; g_pmax[1][blockIdx.x] = r3[0];
    }
}

__global__ void k_norm() {
    int tid = threadIdx.x;   // 256
    __shared__ float r0[256], r1[256], r2[256], r3[256];
    r0[tid] = g_pmin[0][tid]; r1[tid] = g_pmax[0][tid];
    r2[tid] = g_pmin[1][tid]; r3[tid] = g_pmax[1][tid];
    __syncthreads();
    for (int o = 128; o; o >>= 1) {
        if (tid < o) {
            r0[tid] = fminf(r0[tid], r0[tid+o]);
            r1[tid] = fmaxf(r1[tid], r1[tid+o]);
            r2[tid] = fminf(r2[tid], r2[tid+o]);
            r3[tid] = fmaxf(r3[tid], r3[tid+o]);
        }
        __syncthreads();
    }
    if (tid == 0) {
        g_norm[0] = r0[0];
        g_norm[1] = 1.f / (r1[0] - r0[0] + 1e-12f);
        g_norm[2] = r2[0];
        g_norm[3] = 1.f / (r3[0] - r2[0] + 1e-12f);
    }
}

// ---------------- normalized sums ----------------
__global__ void k_sums() {
    int tid = threadIdx.x;
    int base = blockIdx.x * 1024;
    float mi_min = g_norm[0], mi_inv = g_norm[1];
    float ds_min = g_norm[2], ds_inv = g_norm[3];
    double s1 = 0.0, s2 = 0.0;
    #pragma unroll
    for (int i = 0; i < 4; i++) {
        int idx = base + tid + i*256;
        float mi_n = (g_mi[idx] - mi_min) * mi_inv;
        float ds_n = (g_dis[idx] - ds_min) * ds_inv;
        s1 += (double)ds_n;
        s2 += (double)fminf(mi_n + ds_n, 1.0f);
    }
    __shared__ double d1[256], d2[256];
    d1[tid] = s1; d2[tid] = s2;
    __syncthreads();
    for (int o = 128; o; o >>= 1) {
        if (tid < o) { d1[tid] += d1[tid+o]; d2[tid] += d2[tid+o]; }
        __syncthreads();
    }
    if (tid == 0) {
        atomicAdd(&g_sum_disn, d1[0]);
        atomicAdd(&g_sum_min, d2[0]);
    }
}

// ---------------- final scalar assembly ----------------
__global__ void k_final(float* __restrict__ out) {
    double ent = g_ent / (double)NA;
    double kl  = g_kl  / (double)NA;
    double loss0 = fmin(ent*1e-4 + kl*1e-4, 2000.0);
    double ce = log1p(exp(loss0));
    double dis_norm = g_sum_disn / (double)NA;
    double dis_loss = -g_sum_min / (double)NA;
    double cdis = (dis_norm + dis_loss) / (double)NA;
    out[0] = (float)(ce + cdis);
    out[1] = (float)cdis;
    out[2] = (float)ce;
}

// ---------------- launcher ----------------
extern "C" void kernel_launch(void* const* d_in, const int* in_sizes, int n_in,
                              void* d_out, int out_size) {
    const float* obs  = (const float*)d_in[0];
    const float* hid  = (const float*)d_in[1];
    const float* eps  = (const float*)d_in[2];
    const float* eW1  = (const float*)d_in[3];
    const float* eb1  = (const float*)d_in[4];
    const float* eg   = (const float*)d_in[5];
    const float* ebt  = (const float*)d_in[6];
    const float* eW2  = (const float*)d_in[7];
    const float* eb2  = (const float*)d_in[8];
    const float* iW1  = (const float*)d_in[9];
    const float* ib1  = (const float*)d_in[10];
    const float* ig   = (const float*)d_in[11];
    const float* ibt  = (const float*)d_in[12];
    const float* iW2  = (const float*)d_in[13];
    const float* ib2  = (const float*)d_in[14];
    const float* dW1  = (const float*)d_in[15];
    const float* db1  = (const float*)d_in[16]; (void)db1; // cancels in BN
    const float* dg   = (const float*)d_in[17];
    const float* dbt  = (const float*)d_in[18];
    const float* dW2  = (const float*)d_in[19];
    const float* db2  = (const float*)d_in[20];
    float* out = (float*)d_out;

    k_lin<<<2*NA, 128>>>(obs, hid, eW1, eb1, iW1, ib1);
    k_bn<<<2, 1024>>>(eg, ebt, ig, ibt);
    k_lat_e<<<256, 256>>>(eW2, eb2, eps);
    k_lat_i<<<256, 256>>>(iW2, ib2);
    k_AB<<<NA, 256>>>(dW1);
    k_col<<<NH, 512>>>(dg);
    k_midis<<<dim3(16, 16, 2), 256>>>(dbt, dW2, db2);
    k_minmax<<<256, 256>>>();
    k_norm<<<1, 256>>>();
    k_sums<<<256, 256>>>();
    k_final<<<1, 1>>>(out);
}

// round 10
// speedup vs baseline: 2.5695x; 1.0622x over previous
#include <cuda_runtime.h>
#include <math.h>

#define NA   512
#define OBSD 128
#define INP  656
#define HID  64
#define LAT  256
#define NH   64
#define LOG2PI 1.8378770664093453f
#define BNEPS 1e-5f

// ---------------- scratch (device globals; no allocation allowed) ----------------
__device__ __align__(16) float g_pre_e[NA*NH];
__device__ __align__(16) float g_pre_i[NA*NH];
__device__ float g_scale[2][NH], g_shift[2][NH];
__device__ __align__(16) float g_mu[NA*LAT];
__device__ __align__(16) float g_ni2v[NA*LAT], g_cc[NA*LAT], g_lat[NA*LAT];
__device__ __align__(16) float g_A[NA*NH], g_B[NA*NH];
__device__ __align__(16) float g_w1[NA*NH];
__device__ __align__(16) float g_mi[NA*NA], g_dis[NA*NA];
__device__ double g_ent, g_kl, g_sum_disn, g_sum_min;
__device__ unsigned g_keymin[2], g_keymax[2];

// ordered-uint encoding for float atomic min/max
__device__ __forceinline__ unsigned fkey(float f) {
    unsigned u = __float_as_uint(f);
    return (u & 0x80000000u) ? ~u : (u | 0x80000000u);
}
__device__ __forceinline__ float funkey(unsigned k) {
    unsigned u = (k & 0x80000000u) ? (k & 0x7fffffffu) : ~k;
    return __uint_as_float(u);
}

// ---------------- fused linear1 (encoder + inference), 1 row/block, 8-way split ----------------
__global__ void k_lin(const float* __restrict__ obs, const float* __restrict__ hid,
                      const float* __restrict__ eW1, const float* __restrict__ eb1,
                      const float* __restrict__ iW1, const float* __restrict__ ib1) {
    int b = blockIdx.x, t = threadIdx.x;   // 1024 blocks, 128 threads
    if (b == 0 && t == 0) {
        g_ent = 0.0; g_kl = 0.0; g_sum_disn = 0.0; g_sum_min = 0.0;
        g_keymin[0] = 0xFFFFFFFFu; g_keymin[1] = 0xFFFFFFFFu;
        g_keymax[0] = 0u; g_keymax[1] = 0u;
    }
    __shared__ float s[HID + INP];
    __shared__ float part[8][NH];
    int g = t & 15, hh = t >> 4;   // 16 col-groups x 8 l-slices
    int c0 = g * 4;
    float4 acc = make_float4(0.f, 0.f, 0.f, 0.f);
    if (b < NA) {
        int i = b;
        if (t < OBSD) s[t] = obs[i*INP + (INP-OBSD) + t];
        __syncthreads();
        int l0 = hh * 16;
        #pragma unroll 16
        for (int l = l0; l < l0 + 16; l++) {
            float4 w = *(const float4*)&eW1[l*NH + c0];
            float x = s[l];
            acc.x = fmaf(x, w.x, acc.x); acc.y = fmaf(x, w.y, acc.y);
            acc.z = fmaf(x, w.z, acc.z); acc.w = fmaf(x, w.w, acc.w);
        }
        part[hh][c0+0] = acc.x; part[hh][c0+1] = acc.y;
        part[hh][c0+2] = acc.z; part[hh][c0+3] = acc.w;
        __syncthreads();
        if (t < NH) {
            float r = eb1[t];
            #pragma unroll
            for (int k = 0; k < 8; k++) r += part[k][t];
            g_pre_e[i*NH + t] = r;
        }
    } else {
        int i = b - NA;
        for (int l = t; l < HID; l += 128) s[l] = hid[i*HID + l];
        for (int l = t; l < INP; l += 128) s[HID + l] = obs[i*INP + l];
        __syncthreads();
        int l0 = hh * 90;
        #pragma unroll 10
        for (int l = l0; l < l0 + 90; l++) {
            float4 w = *(const float4*)&iW1[l*NH + c0];
            float x = s[l];
            acc.x = fmaf(x, w.x, acc.x); acc.y = fmaf(x, w.y, acc.y);
            acc.z = fmaf(x, w.z, acc.z); acc.w = fmaf(x, w.w, acc.w);
        }
        part[hh][c0+0] = acc.x; part[hh][c0+1] = acc.y;
        part[hh][c0+2] = acc.z; part[hh][c0+3] = acc.w;
        __syncthreads();
        if (t < NH) {
            float r = ib1[t];
            #pragma unroll
            for (int k = 0; k < 8; k++) r += part[k][t];
            g_pre_i[i*NH + t] = r;
        }
    }
}

// ---------------- fused BN stats (both tensors), single pass, coalesced ----------------
__global__ void k_bn(const float* __restrict__ eg, const float* __restrict__ ebt,
                     const float* __restrict__ ig, const float* __restrict__ ibt) {
    int which = blockIdx.x;    // 2 blocks, 1024 threads
    const float* pre = which ? g_pre_i : g_pre_e;
    const float* gm  = which ? ig  : eg;
    const float* bt  = which ? ibt : ebt;
    int t = threadIdx.x;
    int c = t & 63, rg = t >> 6;   // 16 row groups
    float s = 0.f, s2 = 0.f;
    for (int r = rg; r < NA; r += 16) {
        float x = pre[r*NH + c];   // addr = t + 1024k : fully coalesced
        s += x; s2 = fmaf(x, x, s2);
    }
    __shared__ float sh1[16][NH], sh2[16][NH];
    sh1[rg][c] = s; sh2[rg][c] = s2;
    __syncthreads();
    if (t < NH) {
        float a = 0.f, b = 0.f;
        #pragma unroll
        for (int k = 0; k < 16; k++) { a += sh1[k][t]; b += sh2[k][t]; }
        float mean = a * (1.f/NA);
        float var = b * (1.f/NA) - mean*mean;
        float sc = gm[t] * rsqrtf(var + BNEPS);
        g_scale[which][t] = sc;
        g_shift[which][t] = bt[t] - mean*sc;
    }
}

// ---------------- fused: enc linear2 + inf linear2 + latent head + entropy + KL + A/B GEMV ----------------
__global__ void k_lat(const float* __restrict__ eW2, const float* __restrict__ eb2,
                      const float* __restrict__ iW2, const float* __restrict__ ib2,
                      const float* __restrict__ eps, const float* __restrict__ dW1) {
    int i0 = blockIdx.x * 2, t = threadIdx.x;   // 256 blocks, 256 threads
    __shared__ float he[2][NH], hif[2][NH];
    __shared__ float sMuE[2][LAT], sMuI[2][LAT];
    __shared__ float sLat[2][LAT];
    __shared__ float red1[256], red2[256];
    __shared__ float pa[4][2][NH], pb[4][2][NH];
    {
        int g = (t >> 6) & 1, c = t & 63;
        if (t < 128) {
            float x = fmaf(g_pre_e[(i0+g)*NH + c], g_scale[0][c], g_shift[0][c]);
            he[g][c] = (x > 0.f) ? x : 0.01f*x;
        } else {
            float x = fmaf(g_pre_i[(i0+g)*NH + c], g_scale[1][c], g_shift[1][c]);
            hif[g][c] = (x > 0.f) ? x : 0.01f*x;
        }
    }
    __syncthreads();
    const int c0 = 2*t;   // t<128: mu columns [0,254]; t>=128: logvar columns [256,510]
    float be0 = eb2[c0], be1 = eb2[c0+1];
    float bi0 = ib2[c0], bi1 = ib2[c0+1];
    float e00 = be0, e01 = be1, e10 = be0, e11 = be1;
    float i00 = bi0, i01 = bi1, i10 = bi0, i11 = bi1;
    #pragma unroll 8
    for (int l = 0; l < NH; l++) {
        float2 we = *(const float2*)&eW2[l*(2*LAT) + c0];
        float2 wi = *(const float2*)&iW2[l*(2*LAT) + c0];
        float h0 = he[0][l], h1 = he[1][l];
        float q0 = hif[0][l], q1 = hif[1][l];
        e00 = fmaf(h0, we.x, e00); e01 = fmaf(h0, we.y, e01);
        e10 = fmaf(h1, we.x, e10); e11 = fmaf(h1, we.y, e11);
        i00 = fmaf(q0, wi.x, i00); i01 = fmaf(q0, wi.y, i01);
        i10 = fmaf(q1, wi.x, i10); i11 = fmaf(q1, wi.y, i11);
    }
    if (t < 128) {
        sMuE[0][c0] = e00; sMuE[0][c0+1] = e01;
        sMuE[1][c0] = e10; sMuE[1][c0+1] = e11;
        sMuI[0][c0] = i00; sMuI[0][c0+1] = i01;
        sMuI[1][c0] = i10; sMuI[1][c0+1] = i11;
        *(float2*)&g_mu[i0*LAT + c0]     = make_float2(e00, e01);
        *(float2*)&g_mu[(i0+1)*LAT + c0] = make_float2(e10, e11);
    }
    __syncthreads();
    float ent = 0.f, kl = 0.f;
    if (t >= 128) {
        const int li = c0 - LAT;   // c0 in [256,510] -> li in [0,254]
        float eA0[2] = {e00, e10}, eA1[2] = {e01, e11};
        float iA0[2] = {i00, i10}, iA1[2] = {i01, i11};
        #pragma unroll
        for (int g = 0; g < 2; g++) {
            int gi = (i0+g)*LAT + li;
            // encoder path
            float v0 = fmaxf(expf(eA0[g]), 0.002f);
            float v1 = fmaxf(expf(eA1[g]), 0.002f);
            float ls0 = 0.5f*logf(v0), ls1 = 0.5f*logf(v1);
            float mu0 = sMuE[g][li], mu1 = sMuE[g][li+1];
            *(float2*)&g_ni2v[gi] = make_float2(-0.5f/v0, -0.5f/v1);
            *(float2*)&g_cc[gi]   = make_float2(13.9f - ls0 - 0.5f*LOG2PI,
                                                13.9f - ls1 - 0.5f*LOG2PI);
            float2 e2 = *(const float2*)&eps[gi];
            float l0v = fmaf(sqrtf(v0), e2.x, mu0);
            float l1v = fmaf(sqrtf(v1), e2.y, mu1);
            *(float2*)&g_lat[gi] = make_float2(l0v, l1v);
            sLat[g][li] = l0v; sLat[g][li+1] = l1v;
            ent += 1.f + LOG2PI + ls0 + ls1;
            // inference path + KL
            float vq0 = fmaxf(expf(iA0[g]), 0.002f);
            float vq1 = fmaxf(expf(iA1[g]), 0.002f);
            float lsq0 = 0.5f*logf(vq0), lsq1 = 0.5f*logf(vq1);
            float d0 = mu0 - sMuI[g][li];
            float d1 = mu1 - sMuI[g][li+1];
            kl += (lsq0 - ls0 + (v0 + d0*d0) / (2.f*vq0) - 0.5f)
                + (lsq1 - ls1 + (v1 + d1*d1) / (2.f*vq1) - 0.5f);
        }
    }
    red1[t] = ent; red2[t] = kl;
    __syncthreads();
    for (int o = 128; o; o >>= 1) {
        if (t < o) { red1[t] += red1[t+o]; red2[t] += red2[t+o]; }
        __syncthreads();
    }
    if (t == 0) { atomicAdd(&g_ent, (double)red1[0]); atomicAdd(&g_kl, (double)red2[0]); }
    __syncthreads();   // sLat fully written before GEMV reads it
    // ---- A/B GEMV on the latent already in smem ----
    const int c = t & 63, q = t >> 6;
    float a0 = 0.f, b0 = 0.f, a1 = 0.f, b1 = 0.f;
    const int l0 = q * 64;
    #pragma unroll 8
    for (int l = l0; l < l0 + 64; l++) {
        float wa = dW1[l*NH + c];
        float wb = dW1[(l + LAT)*NH + c];
        float L0 = sLat[0][l], L1 = sLat[1][l];
        a0 = fmaf(L0, wa, a0); b0 = fmaf(L0, wb, b0);
        a1 = fmaf(L1, wa, a1); b1 = fmaf(L1, wb, b1);
    }
    pa[q][0][c] = a0; pa[q][1][c] = a1;
    pb[q][0][c] = b0; pb[q][1][c] = b1;
    __syncthreads();
    if (t < 128) {
        int g = t >> 6, c2 = t & 63;
        g_A[(i0+g)*NH + c2] = pa[0][g][c2] + pa[1][g][c2] + pa[2][g][c2] + pa[3][g][c2];
        g_B[(i0+g)*NH + c2] = pb[0][g][c2] + pb[1][g][c2] + pb[2][g][c2] + pb[3][g][c2];
    }
}

// ---------------- fused: col stats + center (in place) + circ-corr -> w1 ----------------
__global__ void k_col(const float* __restrict__ dg) {
    int c = blockIdx.x, s = threadIdx.x;   // 64 blocks, 512 threads
    __shared__ float a[NA], b[NA], r1[NA], r2[NA];
    float av = g_A[s*NH + c], bv = g_B[s*NH + c];
    r1[s] = av; r2[s] = bv;
    __syncthreads();
    for (int o = 256; o; o >>= 1) {
        if (s < o) { r1[s] += r1[s+o]; r2[s] += r2[s+o]; }
        __syncthreads();
    }
    float mA = r1[0] * (1.f/NA), mB = r2[0] * (1.f/NA);
    __syncthreads();
    av -= mA; bv -= mB;
    a[s] = av; b[s] = bv;
    g_A[s*NH + c] = av;
    g_B[s*NH + c] = bv;
    r1[s] = av*av + bv*bv;
    __syncthreads();
    for (int o = 256; o; o >>= 1) { if (s < o) r1[s] += r1[s+o]; __syncthreads(); }
    float s2 = r1[0] * (1.f/NA);
    float cr = 0.f;
    #pragma unroll 8
    for (int j = 0; j < NA; j++) cr = fmaf(a[j], b[(j - s - 1) & (NA-1)], cr);
    float var = s2 + 2.f * cr * (1.f/NA);
    g_w1[s*NH + c] = dg[c] * rsqrtf(var + BNEPS);
}

// ---------------- fused MI (z=0) + DIS (z=1) + per-block min/max atomics ----------------
__global__ void k_midis(const float* __restrict__ dbt,
                        const float* __restrict__ dW2,
                        const float* __restrict__ db2) {
    __shared__ float sh[8448];
    const int tid = threadIdx.x;            // 256
    const int j0 = blockIdx.x * 32, s0 = blockIdx.y * 32;
    const int tx = tid & 15, ty = tid >> 4;
    const int jj0 = 2*tx, ss0 = 2*ty;
    const int base = (j0 - s0 - 32) & (NA-1);
    float v00, v01, v10, v11;
    if (blockIdx.z == 0) {
        float* sMU = sh;            // 32*33
        float* sNI = sh + 1056;     // 32*33
        float* sCC = sh + 2112;     // 32*33
        float* sL  = sh + 3168;     // 64*33
        float acc00 = 0.f, acc01 = 0.f, acc10 = 0.f, acc11 = 0.f;
        for (int l0 = 0; l0 < LAT; l0 += 32) {
            #pragma unroll
            for (int i = 0; i < 4; i++) {
                int idx = tid + i*256;
                int r = idx >> 5, cc = idx & 31;
                int g = (j0 + r)*LAT + l0 + cc;
                sMU[r*33+cc] = g_mu[g]; sNI[r*33+cc] = g_ni2v[g]; sCC[r*33+cc] = g_cc[g];
            }
            #pragma unroll
            for (int i = 0; i < 8; i++) {
                int idx = tid + i*256;
                int r = idx >> 5, cc = idx & 31;
                sL[r*33+cc] = g_lat[((base + r) & (NA-1))*LAT + l0 + cc];
            }
            __syncthreads();
            #pragma unroll
            for (int l = 0; l < 32; l++) {
                float mu0 = sMU[jj0*33+l],   mu1 = sMU[(jj0+1)*33+l];
                float n0  = sNI[jj0*33+l],   n1  = sNI[(jj0+1)*33+l];
                float c0  = sCC[jj0*33+l],   c1  = sCC[(jj0+1)*33+l];
                {
                    float L0 = sL[(jj0   - ss0 + 31)*33+l];
                    float L1 = sL[(jj0+1 - ss0 + 31)*33+l];
                    float d0 = L0 - mu0; acc00 += fmaxf(fmaf(d0*d0, n0, c0), -13.9f);
                    float d1 = L1 - mu1; acc01 += fmaxf(fmaf(d1*d1, n1, c1), -13.9f);
                }
                {
                    float L0 = sL[(jj0   - ss0 + 30)*33+l];
                    float L1 = sL[(jj0+1 - ss0 + 30)*33+l];
                    float d0 = L0 - mu0; acc10 += fmaxf(fmaf(d0*d0, n0, c0), -13.9f);
                    float d1 = L1 - mu1; acc11 += fmaxf(fmaf(d1*d1, n1, c1), -13.9f);
                }
            }
            __syncthreads();
        }
        const float inv = 1.f / LAT;
        v00 = acc00 * inv; v01 = acc01 * inv; v10 = acc10 * inv; v11 = acc11 * inv;
        g_mi[(s0+ss0  )*NA + j0+jj0  ] = v00;
        g_mi[(s0+ss0  )*NA + j0+jj0+1] = v01;
        g_mi[(s0+ss0+1)*NA + j0+jj0  ] = v10;
        g_mi[(s0+ss0+1)*NA + j0+jj0+1] = v11;
    } else {
        float* sa   = sh;                 // 32*65
        float* sw   = sh + 2080;          // 32*65
        float* sb   = sh + 4160;          // 64*65
        float* sdbt = sh + 8320;          // 64
        float* sdw2 = sh + 8384;          // 64
        if (tid < NH) { sdbt[tid] = dbt[tid]; sdw2[tid] = dW2[tid]; }
        #pragma unroll
        for (int i = 0; i < 8; i++) {
            int idx = tid + i*256;
            int r = idx >> 6, c = idx & 63;
            sa[r*65 + c] = g_A[(j0 + r)*NH + c];
            sw[r*65 + c] = g_w1[(s0 + r)*NH + c];
        }
        #pragma unroll
        for (int i = 0; i < 16; i++) {
            int idx = tid + i*256;
            int r = idx >> 6, c = idx & 63;
            sb[r*65 + c] = g_B[((base + r) & (NA-1))*NH + c];
        }
        __syncthreads();
        float acc00 = 0.f, acc01 = 0.f, acc10 = 0.f, acc11 = 0.f;
        #pragma unroll 8
        for (int c = 0; c < NH; c++) {
            float a0 = sa[jj0*65 + c], a1 = sa[(jj0+1)*65 + c];
            float w0 = sw[ss0*65 + c], w1v = sw[(ss0+1)*65 + c];
            float bt = sdbt[c], w2 = sdw2[c];
            {
                float b0 = sb[(jj0   - ss0 + 31)*65 + c];
                float b1 = sb[(jj0+1 - ss0 + 31)*65 + c];
                float u0 = fmaf(a0 + b0, w0, bt); u0 = (u0 > 0.f) ? u0 : 0.01f*u0;
                float u1 = fmaf(a1 + b1, w0, bt); u1 = (u1 > 0.f) ? u1 : 0.01f*u1;
                acc00 = fmaf(u0, w2, acc00);
                acc01 = fmaf(u1, w2, acc01);
            }
            {
                float b0 = sb[(jj0   - ss0 + 30)*65 + c];
                float b1 = sb[(jj0+1 - ss0 + 30)*65 + c];
                float u0 = fmaf(a0 + b0, w1v, bt); u0 = (u0 > 0.f) ? u0 : 0.01f*u0;
                float u1 = fmaf(a1 + b1, w1v, bt); u1 = (u1 > 0.f) ? u1 : 0.01f*u1;
                acc10 = fmaf(u0, w2, acc10);
                acc11 = fmaf(u1, w2, acc11);
            }
        }
        float b2 = db2[0];
        v00 = fabsf(acc00 + b2); v01 = fabsf(acc01 + b2);
        v10 = fabsf(acc10 + b2); v11 = fabsf(acc11 + b2);
        g_dis[(s0+ss0  )*NA + j0+jj0  ] = v00;
        g_dis[(s0+ss0  )*NA + j0+jj0+1] = v01;
        g_dis[(s0+ss0+1)*NA + j0+jj0  ] = v10;
        g_dis[(s0+ss0+1)*NA + j0+jj0+1] = v11;
    }
    // ---- block min/max -> global atomic keys ----
    float mn = fminf(fminf(v00, v01), fminf(v10, v11));
    float mx = fmaxf(fmaxf(v00, v01), fmaxf(v10, v11));
    #pragma unroll
    for (int o = 16; o; o >>= 1) {
        mn = fminf(mn, __shfl_xor_sync(0xFFFFFFFFu, mn, o));
        mx = fmaxf(mx, __shfl_xor_sync(0xFFFFFFFFu, mx, o));
    }
    __shared__ float wmn[8], wmx[8];
    if ((tid & 31) == 0) { wmn[tid>>5] = mn; wmx[tid>>5] = mx; }
    __syncthreads();
    if (tid == 0) {
        float a = wmn[0], b = wmx[0];
        #pragma unroll
        for (int k = 1; k < 8; k++) { a = fminf(a, wmn[k]); b = fmaxf(b, wmx[k]); }
        atomicMin(&g_keymin[blockIdx.z], fkey(a));
        atomicMax(&g_keymax[blockIdx.z], fkey(b));
    }
}

// ---------------- normalized sums (norm computed inline from keys) ----------------
__global__ void k_sums() {
    int tid = threadIdx.x;
    int base = blockIdx.x * 1024;
    float mi_min = funkey(g_keymin[0]);
    float mi_inv = 1.f / (funkey(g_keymax[0]) - mi_min + 1e-12f);
    float ds_min = funkey(g_keymin[1]);
    float ds_inv = 1.f / (funkey(g_keymax[1]) - ds_min + 1e-12f);
    double s1 = 0.0, s2 = 0.0;
    #pragma unroll
    for (int i = 0; i < 4; i++) {
        int idx = base + tid + i*256;
        float mi_n = (g_mi[idx] - mi_min) * mi_inv;
        float ds_n = (g_dis[idx] - ds_min) * ds_inv;
        s1 += (double)ds_n;
        s2 += (double)fminf(mi_n + ds_n, 1.0f);
    }
    __shared__ double d1[256], d2[256];
    d1[tid] = s1; d2[tid] = s2;
    __syncthreads();
    for (int o = 128; o; o >>= 1) {
        if (tid < o) { d1[tid] += d1[tid+o]; d2[tid] += d2[tid+o]; }
        __syncthreads();
    }
    if (tid == 0) {
        atomicAdd(&g_sum_disn, d1[0]);
        atomicAdd(&g_sum_min, d2[0]);
    }
}

// ---------------- final scalar assembly ----------------
__global__ void k_final(float* __restrict__ out) {
    double ent = g_ent / (double)NA;
    double kl  = g_kl  / (double)NA;
    double loss0 = fmin(ent*1e-4 + kl*1e-4, 2000.0);
    double ce = log1p(exp(loss0));
    double dis_norm = g_sum_disn / (double)NA;
    double dis_loss = -g_sum_min / (double)NA;
    double cdis = (dis_norm + dis_loss) / (double)NA;
    out[0] = (float)(ce + cdis);
    out[1] = (float)cdis;
    out[2] = (float)ce;
}

// ---------------- launcher ----------------
extern "C" void kernel_launch(void* const* d_in, const int* in_sizes, int n_in,
                              void* d_out, int out_size) {
    const float* obs  = (const float*)d_in[0];
    const float* hid  = (const float*)d_in[1];
    const float* eps  = (const float*)d_in[2];
    const float* eW1  = (const float*)d_in[3];
    const float* eb1  = (const float*)d_in[4];
    const float* eg   = (const float*)d_in[5];
    const float* ebt  = (const float*)d_in[6];
    const float* eW2  = (const float*)d_in[7];
    const float* eb2  = (const float*)d_in[8];
    const float* iW1  = (const float*)d_in[9];
    const float* ib1  = (const float*)d_in[10];
    const float* ig   = (const float*)d_in[11];
    const float* ibt  = (const float*)d_in[12];
    const float* iW2  = (const float*)d_in[13];
    const float* ib2  = (const float*)d_in[14];
    const float* dW1  = (const float*)d_in[15];
    const float* db1  = (const float*)d_in[16]; (void)db1; // cancels in BN
    const float* dg   = (const float*)d_in[17];
    const float* dbt  = (const float*)d_in[18];
    const float* dW2  = (const float*)d_in[19];
    const float* db2  = (const float*)d_in[20];
    float* out = (float*)d_out;

    k_lin<<<2*NA, 128>>>(obs, hid, eW1, eb1, iW1, ib1);
    k_bn<<<2, 1024>>>(eg, ebt, ig, ibt);
    k_lat<<<256, 256>>>(eW2, eb2, iW2, ib2, eps, dW1);
    k_col<<<NH, 512>>>(dg);
    k_midis<<<dim3(16, 16, 2), 256>>>(dbt, dW2, db2);
    k_sums<<<256, 256>>>();
    k_final<<<1, 1>>>(out);
}

// round 11
// speedup vs baseline: 2.6725x; 1.0401x over previous
#include <cuda_runtime.h>
#include <math.h>

#define NA   512
#define OBSD 128
#define INP  656
#define HID  64
#define LAT  256
#define NH   64
#define LOG2PI 1.8378770664093453f
#define BNEPS 1e-5f

// ---------------- scratch (device globals; no allocation allowed) ----------------
__device__ __align__(16) float g_pre_e[NA*NH];
__device__ __align__(16) float g_pre_i[NA*NH];
__device__ float g_scale[2][NH], g_shift[2][NH];
__device__ __align__(16) float g_mu[NA*LAT];
__device__ __align__(16) float g_ni2v[NA*LAT], g_cc[NA*LAT], g_lat[NA*LAT];
__device__ __align__(16) float g_A[NA*NH], g_B[NA*NH];
__device__ __align__(16) float g_Ac[NA*NH], g_Bc[NA*NH];
__device__ __align__(16) float g_w1[NA*NH];
__device__ __align__(16) float g_mi[NA*NA], g_dis[NA*NA];
__device__ double g_ent, g_kl, g_sum_disn, g_sum_min;
__device__ unsigned g_keymin[2], g_keymax[2];
__device__ unsigned g_done;

// ordered-uint encoding for float atomic min/max
__device__ __forceinline__ unsigned fkey(float f) {
    unsigned u = __float_as_uint(f);
    return (u & 0x80000000u) ? ~u : (u | 0x80000000u);
}
__device__ __forceinline__ float funkey(unsigned k) {
    unsigned u = (k & 0x80000000u) ? (k & 0x7fffffffu) : ~k;
    return __uint_as_float(u);
}

// ---------------- fused linear1 (encoder + inference), 1 row/block, 8-way split ----------------
__global__ void k_lin(const float* __restrict__ obs, const float* __restrict__ hid,
                      const float* __restrict__ eW1, const float* __restrict__ eb1,
                      const float* __restrict__ iW1, const float* __restrict__ ib1) {
    int b = blockIdx.x, t = threadIdx.x;   // 1024 blocks, 128 threads
    if (b == 0 && t == 0) {
        g_ent = 0.0; g_kl = 0.0; g_sum_disn = 0.0; g_sum_min = 0.0;
        g_keymin[0] = 0xFFFFFFFFu; g_keymin[1] = 0xFFFFFFFFu;
        g_keymax[0] = 0u; g_keymax[1] = 0u;
        g_done = 0u;
    }
    __shared__ float s[HID + INP];
    __shared__ float part[8][NH];
    int g = t & 15, hh = t >> 4;   // 16 col-groups x 8 l-slices
    int c0 = g * 4;
    float4 acc = make_float4(0.f, 0.f, 0.f, 0.f);
    if (b < NA) {
        int i = b;
        if (t < OBSD) s[t] = obs[i*INP + (INP-OBSD) + t];
        __syncthreads();
        int l0 = hh * 16;
        #pragma unroll 16
        for (int l = l0; l < l0 + 16; l++) {
            float4 w = *(const float4*)&eW1[l*NH + c0];
            float x = s[l];
            acc.x = fmaf(x, w.x, acc.x); acc.y = fmaf(x, w.y, acc.y);
            acc.z = fmaf(x, w.z, acc.z); acc.w = fmaf(x, w.w, acc.w);
        }
        part[hh][c0+0] = acc.x; part[hh][c0+1] = acc.y;
        part[hh][c0+2] = acc.z; part[hh][c0+3] = acc.w;
        __syncthreads();
        if (t < NH) {
            float r = eb1[t];
            #pragma unroll
            for (int k = 0; k < 8; k++) r += part[k][t];
            g_pre_e[i*NH + t] = r;
        }
    } else {
        int i = b - NA;
        for (int l = t; l < HID; l += 128) s[l] = hid[i*HID + l];
        for (int l = t; l < INP; l += 128) s[HID + l] = obs[i*INP + l];
        __syncthreads();
        int l0 = hh * 90;
        #pragma unroll 10
        for (int l = l0; l < l0 + 90; l++) {
            float4 w = *(const float4*)&iW1[l*NH + c0];
            float x = s[l];
            acc.x = fmaf(x, w.x, acc.x); acc.y = fmaf(x, w.y, acc.y);
            acc.z = fmaf(x, w.z, acc.z); acc.w = fmaf(x, w.w, acc.w);
        }
        part[hh][c0+0] = acc.x; part[hh][c0+1] = acc.y;
        part[hh][c0+2] = acc.z; part[hh][c0+3] = acc.w;
        __syncthreads();
        if (t < NH) {
            float r = ib1[t];
            #pragma unroll
            for (int k = 0; k < 8; k++) r += part[k][t];
            g_pre_i[i*NH + t] = r;
        }
    }
}

// ---------------- fused BN stats (both tensors), single pass, coalesced ----------------
__global__ void k_bn(const float* __restrict__ eg, const float* __restrict__ ebt,
                     const float* __restrict__ ig, const float* __restrict__ ibt) {
    int which = blockIdx.x;    // 2 blocks, 1024 threads
    const float* pre = which ? g_pre_i : g_pre_e;
    const float* gm  = which ? ig  : eg;
    const float* bt  = which ? ibt : ebt;
    int t = threadIdx.x;
    int c = t & 63, rg = t >> 6;   // 16 row groups
    float s = 0.f, s2 = 0.f;
    for (int r = rg; r < NA; r += 16) {
        float x = pre[r*NH + c];   // addr = t + 1024k : fully coalesced
        s += x; s2 = fmaf(x, x, s2);
    }
    __shared__ float sh1[16][NH], sh2[16][NH];
    sh1[rg][c] = s; sh2[rg][c] = s2;
    __syncthreads();
    if (t < NH) {
        float a = 0.f, b = 0.f;
        #pragma unroll
        for (int k = 0; k < 16; k++) { a += sh1[k][t]; b += sh2[k][t]; }
        float mean = a * (1.f/NA);
        float var = b * (1.f/NA) - mean*mean;
        float sc = gm[t] * rsqrtf(var + BNEPS);
        g_scale[which][t] = sc;
        g_shift[which][t] = bt[t] - mean*sc;
    }
}

// ---------------- fused: enc linear2 + inf linear2 + latent head + entropy + KL + A/B GEMV ----------------
__global__ void k_lat(const float* __restrict__ eW2, const float* __restrict__ eb2,
                      const float* __restrict__ iW2, const float* __restrict__ ib2,
                      const float* __restrict__ eps, const float* __restrict__ dW1) {
    int i0 = blockIdx.x * 2, t = threadIdx.x;   // 256 blocks, 256 threads
    __shared__ float he[2][NH], hif[2][NH];
    __shared__ float sMuE[2][LAT], sMuI[2][LAT];
    __shared__ float sLat[2][LAT];
    __shared__ float red1[256], red2[256];
    __shared__ float pa[4][2][NH], pb[4][2][NH];
    {
        int g = (t >> 6) & 1, c = t & 63;
        if (t < 128) {
            float x = fmaf(g_pre_e[(i0+g)*NH + c], g_scale[0][c], g_shift[0][c]);
            he[g][c] = (x > 0.f) ? x : 0.01f*x;
        } else {
            float x = fmaf(g_pre_i[(i0+g)*NH + c], g_scale[1][c], g_shift[1][c]);
            hif[g][c] = (x > 0.f) ? x : 0.01f*x;
        }
    }
    __syncthreads();
    const int c0 = 2*t;   // t<128: mu columns [0,254]; t>=128: logvar columns [256,510]
    float be0 = eb2[c0], be1 = eb2[c0+1];
    float bi0 = ib2[c0], bi1 = ib2[c0+1];
    float e00 = be0, e01 = be1, e10 = be0, e11 = be1;
    float i00 = bi0, i01 = bi1, i10 = bi0, i11 = bi1;
    #pragma unroll 8
    for (int l = 0; l < NH; l++) {
        float2 we = *(const float2*)&eW2[l*(2*LAT) + c0];
        float2 wi = *(const float2*)&iW2[l*(2*LAT) + c0];
        float h0 = he[0][l], h1 = he[1][l];
        float q0 = hif[0][l], q1 = hif[1][l];
        e00 = fmaf(h0, we.x, e00); e01 = fmaf(h0, we.y, e01);
        e10 = fmaf(h1, we.x, e10); e11 = fmaf(h1, we.y, e11);
        i00 = fmaf(q0, wi.x, i00); i01 = fmaf(q0, wi.y, i01);
        i10 = fmaf(q1, wi.x, i10); i11 = fmaf(q1, wi.y, i11);
    }
    if (t < 128) {
        sMuE[0][c0] = e00; sMuE[0][c0+1] = e01;
        sMuE[1][c0] = e10; sMuE[1][c0+1] = e11;
        sMuI[0][c0] = i00; sMuI[0][c0+1] = i01;
        sMuI[1][c0] = i10; sMuI[1][c0+1] = i11;
        *(float2*)&g_mu[i0*LAT + c0]     = make_float2(e00, e01);
        *(float2*)&g_mu[(i0+1)*LAT + c0] = make_float2(e10, e11);
    }
    __syncthreads();
    float ent = 0.f, kl = 0.f;
    if (t >= 128) {
        const int li = c0 - LAT;   // c0 in [256,510] -> li in [0,254]
        float eA0[2] = {e00, e10}, eA1[2] = {e01, e11};
        float iA0[2] = {i00, i10}, iA1[2] = {i01, i11};
        #pragma unroll
        for (int g = 0; g < 2; g++) {
            int gi = (i0+g)*LAT + li;
            // encoder path
            float v0 = fmaxf(expf(eA0[g]), 0.002f);
            float v1 = fmaxf(expf(eA1[g]), 0.002f);
            float ls0 = 0.5f*logf(v0), ls1 = 0.5f*logf(v1);
            float mu0 = sMuE[g][li], mu1 = sMuE[g][li+1];
            *(float2*)&g_ni2v[gi] = make_float2(-0.5f/v0, -0.5f/v1);
            *(float2*)&g_cc[gi]   = make_float2(13.9f - ls0 - 0.5f*LOG2PI,
                                                13.9f - ls1 - 0.5f*LOG2PI);
            float2 e2 = *(const float2*)&eps[gi];
            float l0v = fmaf(sqrtf(v0), e2.x, mu0);
            float l1v = fmaf(sqrtf(v1), e2.y, mu1);
            *(float2*)&g_lat[gi] = make_float2(l0v, l1v);
            sLat[g][li] = l0v; sLat[g][li+1] = l1v;
            ent += 1.f + LOG2PI + ls0 + ls1;
            // inference path + KL
            float vq0 = fmaxf(expf(iA0[g]), 0.002f);
            float vq1 = fmaxf(expf(iA1[g]), 0.002f);
            float lsq0 = 0.5f*logf(vq0), lsq1 = 0.5f*logf(vq1);
            float d0 = mu0 - sMuI[g][li];
            float d1 = mu1 - sMuI[g][li+1];
            kl += (lsq0 - ls0 + (v0 + d0*d0) / (2.f*vq0) - 0.5f)
                + (lsq1 - ls1 + (v1 + d1*d1) / (2.f*vq1) - 0.5f);
        }
    }
    red1[t] = ent; red2[t] = kl;
    __syncthreads();
    for (int o = 128; o; o >>= 1) {
        if (t < o) { red1[t] += red1[t+o]; red2[t] += red2[t+o]; }
        __syncthreads();
    }
    if (t == 0) { atomicAdd(&g_ent, (double)red1[0]); atomicAdd(&g_kl, (double)red2[0]); }
    __syncthreads();   // sLat fully written before GEMV reads it
    // ---- A/B GEMV on the latent already in smem ----
    const int c = t & 63, q = t >> 6;
    float a0 = 0.f, b0 = 0.f, a1 = 0.f, b1 = 0.f;
    const int l0 = q * 64;
    #pragma unroll 8
    for (int l = l0; l < l0 + 64; l++) {
        float wa = dW1[l*NH + c];
        float wb = dW1[(l + LAT)*NH + c];
        float L0 = sLat[0][l], L1 = sLat[1][l];
        a0 = fmaf(L0, wa, a0); b0 = fmaf(L0, wb, b0);
        a1 = fmaf(L1, wa, a1); b1 = fmaf(L1, wb, b1);
    }
    pa[q][0][c] = a0; pa[q][1][c] = a1;
    pb[q][0][c] = b0; pb[q][1][c] = b1;
    __syncthreads();
    if (t < 128) {
        int g = t >> 6, c2 = t & 63;
        g_A[(i0+g)*NH + c2] = pa[0][g][c2] + pa[1][g][c2] + pa[2][g][c2] + pa[3][g][c2];
        g_B[(i0+g)*NH + c2] = pb[0][g][c2] + pb[1][g][c2] + pb[2][g][c2] + pb[3][g][c2];
    }
}

// ---------------- fused: col stats + center (to g_Ac/g_Bc) + circ-corr -> w1 ----------------
// grid (64 columns, 2 s-halves), 512 threads
__global__ void k_col(const float* __restrict__ dg) {
    int c = blockIdx.x, sh = blockIdx.y;
    int t = threadIdx.x;
    int lane = t & 31, wid = t >> 5;
    __shared__ float a[NA], b2[2*NA];
    __shared__ float wred[16];
    __shared__ float bc[3];   // mA, mB, s2
    __shared__ float part[512];
    float av = g_A[t*NH + c], bv = g_B[t*NH + c];
    // mean(A)
    float r = av;
    #pragma unroll
    for (int o = 16; o; o >>= 1) r += __shfl_xor_sync(0xFFFFFFFFu, r, o);
    if (lane == 0) wred[wid] = r;
    __syncthreads();
    if (t == 0) { float x = 0.f; for (int k = 0; k < 16; k++) x += wred[k]; bc[0] = x * (1.f/NA); }
    __syncthreads();
    // mean(B)
    r = bv;
    #pragma unroll
    for (int o = 16; o; o >>= 1) r += __shfl_xor_sync(0xFFFFFFFFu, r, o);
    if (lane == 0) wred[wid] = r;
    __syncthreads();
    if (t == 0) { float x = 0.f; for (int k = 0; k < 16; k++) x += wred[k]; bc[1] = x * (1.f/NA); }
    __syncthreads();
    av -= bc[0]; bv -= bc[1];
    a[t] = av; b2[t] = bv; b2[t + NA] = bv;
    if (sh == 0) { g_Ac[t*NH + c] = av; g_Bc[t*NH + c] = bv; }
    // mean(a^2+b^2)
    r = av*av + bv*bv;
    #pragma unroll
    for (int o = 16; o; o >>= 1) r += __shfl_xor_sync(0xFFFFFFFFu, r, o);
    if (lane == 0) wred[wid] = r;
    __syncthreads();
    if (t == 0) { float x = 0.f; for (int k = 0; k < 16; k++) x += wred[k]; bc[2] = x * (1.f/NA); }
    __syncthreads();   // also guarantees a[], b2[] complete
    // circular correlation: cr(s) = sum_j a[j] * b[(j - s - 1) & 511] = sum_j a[j]*b2[511 - s + j]
    const int sidx = t & 255, jh = t >> 8;
    const int s = sh*256 + sidx;
    const float* ap = &a[jh*256];
    const float* bp = &b2[NA - 1 - s + jh*256];
    float cr = 0.f;
    #pragma unroll 8
    for (int j = 0; j < 256; j++) cr = fmaf(ap[j], bp[j], cr);
    part[t] = cr;
    __syncthreads();
    if (t < 256) {
        float crt = part[t] + part[t + 256];
        int ss = sh*256 + t;
        float var = bc[2] + 2.f * crt * (1.f/NA);
        g_w1[ss*NH + c] = dg[c] * rsqrtf(var + BNEPS);
    }
}

// ---------------- fused MI (z=0) + DIS (z=1) + per-block min/max atomics ----------------
__global__ void k_midis(const float* __restrict__ dbt,
                        const float* __restrict__ dW2,
                        const float* __restrict__ db2) {
    __shared__ float sh[8448];
    const int tid = threadIdx.x;            // 256
    const int j0 = blockIdx.x * 32, s0 = blockIdx.y * 32;
    const int tx = tid & 15, ty = tid >> 4;
    const int jj0 = 2*tx, ss0 = 2*ty;
    const int base = (j0 - s0 - 32) & (NA-1);
    float v00, v01, v10, v11;
    if (blockIdx.z == 0) {
        float* sMU = sh;            // 32*33
        float* sNI = sh + 1056;     // 32*33
        float* sCC = sh + 2112;     // 32*33
        float* sL  = sh + 3168;     // 64*33
        float acc00 = 0.f, acc01 = 0.f, acc10 = 0.f, acc11 = 0.f;
        for (int l0 = 0; l0 < LAT; l0 += 32) {
            #pragma unroll
            for (int i = 0; i < 4; i++) {
                int idx = tid + i*256;
                int r = idx >> 5, cc = idx & 31;
                int g = (j0 + r)*LAT + l0 + cc;
                sMU[r*33+cc] = g_mu[g]; sNI[r*33+cc] = g_ni2v[g]; sCC[r*33+cc] = g_cc[g];
            }
            #pragma unroll
            for (int i = 0; i < 8; i++) {
                int idx = tid + i*256;
                int r = idx >> 5, cc = idx & 31;
                sL[r*33+cc] = g_lat[((base + r) & (NA-1))*LAT + l0 + cc];
            }
            __syncthreads();
            #pragma unroll
            for (int l = 0; l < 32; l++) {
                float mu0 = sMU[jj0*33+l],   mu1 = sMU[(jj0+1)*33+l];
                float n0  = sNI[jj0*33+l],   n1  = sNI[(jj0+1)*33+l];
                float c0  = sCC[jj0*33+l],   c1  = sCC[(jj0+1)*33+l];
                {
                    float L0 = sL[(jj0   - ss0 + 31)*33+l];
                    float L1 = sL[(jj0+1 - ss0 + 31)*33+l];
                    float d0 = L0 - mu0; acc00 += fmaxf(fmaf(d0*d0, n0, c0), -13.9f);
                    float d1 = L1 - mu1; acc01 += fmaxf(fmaf(d1*d1, n1, c1), -13.9f);
                }
                {
                    float L0 = sL[(jj0   - ss0 + 30)*33+l];
                    float L1 = sL[(jj0+1 - ss0 + 30)*33+l];
                    float d0 = L0 - mu0; acc10 += fmaxf(fmaf(d0*d0, n0, c0), -13.9f);
                    float d1 = L1 - mu1; acc11 += fmaxf(fmaf(d1*d1, n1, c1), -13.9f);
                }
            }
            __syncthreads();
        }
        const float inv = 1.f / LAT;
        v00 = acc00 * inv; v01 = acc01 * inv; v10 = acc10 * inv; v11 = acc11 * inv;
        g_mi[(s0+ss0  )*NA + j0+jj0  ] = v00;
        g_mi[(s0+ss0  )*NA + j0+jj0+1] = v01;
        g_mi[(s0+ss0+1)*NA + j0+jj0  ] = v10;
        g_mi[(s0+ss0+1)*NA + j0+jj0+1] = v11;
    } else {
        float* sa   = sh;                 // 32*65
        float* sw   = sh + 2080;          // 32*65
        float* sb   = sh + 4160;          // 64*65
        float* sdbt = sh + 8320;          // 64
        float* sdw2 = sh + 8384;          // 64
        if (tid < NH) { sdbt[tid] = dbt[tid]; sdw2[tid] = dW2[tid]; }
        #pragma unroll
        for (int i = 0; i < 8; i++) {
            int idx = tid + i*256;
            int r = idx >> 6, c = idx & 63;
            sa[r*65 + c] = g_Ac[(j0 + r)*NH + c];
            sw[r*65 + c] = g_w1[(s0 + r)*NH + c];
        }
        #pragma unroll
        for (int i = 0; i < 16; i++) {
            int idx = tid + i*256;
            int r = idx >> 6, c = idx & 63;
            sb[r*65 + c] = g_Bc[((base + r) & (NA-1))*NH + c];
        }
        __syncthreads();
        float acc00 = 0.f, acc01 = 0.f, acc10 = 0.f, acc11 = 0.f;
        #pragma unroll 8
        for (int c = 0; c < NH; c++) {
            float a0 = sa[jj0*65 + c], a1 = sa[(jj0+1)*65 + c];
            float w0 = sw[ss0*65 + c], w1v = sw[(ss0+1)*65 + c];
            float bt = sdbt[c], w2 = sdw2[c];
            {
                float b0 = sb[(jj0   - ss0 + 31)*65 + c];
                float b1 = sb[(jj0+1 - ss0 + 31)*65 + c];
                float u0 = fmaf(a0 + b0, w0, bt); u0 = (u0 > 0.f) ? u0 : 0.01f*u0;
                float u1 = fmaf(a1 + b1, w0, bt); u1 = (u1 > 0.f) ? u1 : 0.01f*u1;
                acc00 = fmaf(u0, w2, acc00);
                acc01 = fmaf(u1, w2, acc01);
            }
            {
                float b0 = sb[(jj0   - ss0 + 30)*65 + c];
                float b1 = sb[(jj0+1 - ss0 + 30)*65 + c];
                float u0 = fmaf(a0 + b0, w1v, bt); u0 = (u0 > 0.f) ? u0 : 0.01f*u0;
                float u1 = fmaf(a1 + b1, w1v, bt); u1 = (u1 > 0.f) ? u1 : 0.01f*u1;
                acc10 = fmaf(u0, w2, acc10);
                acc11 = fmaf(u1, w2, acc11);
            }
        }
        float b2 = db2[0];
        v00 = fabsf(acc00 + b2); v01 = fabsf(acc01 + b2);
        v10 = fabsf(acc10 + b2); v11 = fabsf(acc11 + b2);
        g_dis[(s0+ss0  )*NA + j0+jj0  ] = v00;
        g_dis[(s0+ss0  )*NA + j0+jj0+1] = v01;
        g_dis[(s0+ss0+1)*NA + j0+jj0  ] = v10;
        g_dis[(s0+ss0+1)*NA + j0+jj0+1] = v11;
    }
    // ---- block min/max -> global atomic keys ----
    float mn = fminf(fminf(v00, v01), fminf(v10, v11));
    float mx = fmaxf(fmaxf(v00, v01), fmaxf(v10, v11));
    #pragma unroll
    for (int o = 16; o; o >>= 1) {
        mn = fminf(mn, __shfl_xor_sync(0xFFFFFFFFu, mn, o));
        mx = fmaxf(mx, __shfl_xor_sync(0xFFFFFFFFu, mx, o));
    }
    __shared__ float wmn[8], wmx[8];
    if ((tid & 31) == 0) { wmn[tid>>5] = mn; wmx[tid>>5] = mx; }
    __syncthreads();
    if (tid == 0) {
        float a = wmn[0], b = wmx[0];
        #pragma unroll
        for (int k = 1; k < 8; k++) { a = fminf(a, wmn[k]); b = fmaxf(b, wmx[k]); }
        atomicMin(&g_keymin[blockIdx.z], fkey(a));
        atomicMax(&g_keymax[blockIdx.z], fkey(b));
    }
}

// ---------------- normalized sums + last-block final assembly ----------------
__global__ void k_sums(float* __restrict__ out) {
    int tid = threadIdx.x;
    int base = blockIdx.x * 1024;
    float mi_min = funkey(g_keymin[0]);
    float mi_inv = 1.f / (funkey(g_keymax[0]) - mi_min + 1e-12f);
    float ds_min = funkey(g_keymin[1]);
    float ds_inv = 1.f / (funkey(g_keymax[1]) - ds_min + 1e-12f);
    double s1 = 0.0, s2 = 0.0;
    #pragma unroll
    for (int i = 0; i < 4; i++) {
        int idx = base + tid + i*256;
        float mi_n = (g_mi[idx] - mi_min) * mi_inv;
        float ds_n = (g_dis[idx] - ds_min) * ds_inv;
        s1 += (double)ds_n;
        s2 += (double)fminf(mi_n + ds_n, 1.0f);
    }
    __shared__ double d1[256], d2[256];
    d1[tid] = s1; d2[tid] = s2;
    __syncthreads();
    for (int o = 128; o; o >>= 1) {
        if (tid < o) { d1[tid] += d1[tid+o]; d2[tid] += d2[tid+o]; }
        __syncthreads();
    }
    if (tid == 0) {
        atomicAdd(&g_sum_disn, d1[0]);
        atomicAdd(&g_sum_min, d2[0]);
        __threadfence();
        unsigned old = atomicAdd(&g_done, 1u);
        if (old == 255u) {   // last of 256 blocks
            __threadfence();
            double sum_disn = atomicAdd(&g_sum_disn, 0.0);
            double sum_min  = atomicAdd(&g_sum_min, 0.0);
            double ent = atomicAdd(&g_ent, 0.0) / (double)NA;
            double kl  = atomicAdd(&g_kl, 0.0)  / (double)NA;
            double loss0 = fmin(ent*1e-4 + kl*1e-4, 2000.0);
            double ce = log1p(exp(loss0));
            double dis_norm = sum_disn / (double)NA;
            double dis_loss = -sum_min / (double)NA;
            double cdis = (dis_norm + dis_loss) / (double)NA;
            out[0] = (float)(ce + cdis);
            out[1] = (float)cdis;
            out[2] = (float)ce;
        }
    }
}

// ---------------- launcher ----------------
extern "C" void kernel_launch(void* const* d_in, const int* in_sizes, int n_in,
                              void* d_out, int out_size) {
    const float* obs  = (const float*)d_in[0];
    const float* hid  = (const float*)d_in[1];
    const float* eps  = (const float*)d_in[2];
    const float* eW1  = (const float*)d_in[3];
    const float* eb1  = (const float*)d_in[4];
    const float* eg   = (const float*)d_in[5];
    const float* ebt  = (const float*)d_in[6];
    const float* eW2  = (const float*)d_in[7];
    const float* eb2  = (const float*)d_in[8];
    const float* iW1  = (const float*)d_in[9];
    const float* ib1  = (const float*)d_in[10];
    const float* ig   = (const float*)d_in[11];
    const float* ibt  = (const float*)d_in[12];
    const float* iW2  = (const float*)d_in[13];
    const float* ib2  = (const float*)d_in[14];
    const float* dW1  = (const float*)d_in[15];
    const float* db1  = (const float*)d_in[16]; (void)db1; // cancels in BN
    const float* dg   = (const float*)d_in[17];
    const float* dbt  = (const float*)d_in[18];
    const float* dW2  = (const float*)d_in[19];
    const float* db2  = (const float*)d_in[20];
    float* out = (float*)d_out;

    k_lin<<<2*NA, 128>>>(obs, hid, eW1, eb1, iW1, ib1);
    k_bn<<<2, 1024>>>(eg, ebt, ig, ibt);
    k_lat<<<256, 256>>>(eW2, eb2, iW2, ib2, eps, dW1);
    k_col<<<dim3(64, 2), 512>>>(dg);
    k_midis<<<dim3(16, 16, 2), 256>>>(dbt, dW2, db2);
    k_sums<<<256, 256>>>(out);
}

// round 12
// speedup vs baseline: 2.8698x; 1.0738x over previous
#include <cuda_runtime.h>
#include <math.h>

#define NA   512
#define OBSD 128
#define INP  656
#define HID  64
#define LAT  256
#define NH   64
#define LOG2PI 1.8378770664093453f
#define BNEPS 1e-5f

// ---------------- scratch (device globals; no allocation allowed) ----------------
__device__ __align__(16) float g_pre_e[NA*NH];
__device__ __align__(16) float g_pre_i[NA*NH];
__device__ float g_scale[2][NH], g_shift[2][NH];
__device__ __align__(16) float g_mu[NA*LAT];
__device__ __align__(16) float g_ni2v[NA*LAT], g_cc[NA*LAT], g_lat[NA*LAT];
__device__ __align__(16) float g_A[NA*NH], g_B[NA*NH];
__device__ __align__(16) float g_Ac[NA*NH], g_Bc[NA*NH];
__device__ __align__(16) float g_w1[NA*NH];
__device__ __align__(16) float g_mi[NA*NA], g_dis[NA*NA];
__device__ double g_ent, g_kl, g_sum_disn, g_sum_min;
__device__ unsigned g_keymin[2], g_keymax[2];
__device__ unsigned g_done;

// ordered-uint encoding for float atomic min/max
__device__ __forceinline__ unsigned fkey(float f) {
    unsigned u = __float_as_uint(f);
    return (u & 0x80000000u) ? ~u : (u | 0x80000000u);
}
__device__ __forceinline__ float funkey(unsigned k) {
    unsigned u = (k & 0x80000000u) ? (k & 0x7fffffffu) : ~k;
    return __uint_as_float(u);
}

// ---------------- fused linear1 (encoder + inference), 1 row/block, 8-way split ----------------
__global__ void k_lin(const float* __restrict__ obs, const float* __restrict__ hid,
                      const float* __restrict__ eW1, const float* __restrict__ eb1,
                      const float* __restrict__ iW1, const float* __restrict__ ib1) {
    int b = blockIdx.x, t = threadIdx.x;   // 1024 blocks, 128 threads
    if (b == 0 && t == 0) {
        g_ent = 0.0; g_kl = 0.0; g_sum_disn = 0.0; g_sum_min = 0.0;
        g_keymin[0] = 0xFFFFFFFFu; g_keymin[1] = 0xFFFFFFFFu;
        g_keymax[0] = 0u; g_keymax[1] = 0u;
        g_done = 0u;
    }
    __shared__ float s[HID + INP];
    __shared__ float part[8][NH];
    int g = t & 15, hh = t >> 4;   // 16 col-groups x 8 l-slices
    int c0 = g * 4;
    float4 acc = make_float4(0.f, 0.f, 0.f, 0.f);
    if (b < NA) {
        int i = b;
        if (t < OBSD) s[t] = obs[i*INP + (INP-OBSD) + t];
        __syncthreads();
        int l0 = hh * 16;
        #pragma unroll 16
        for (int l = l0; l < l0 + 16; l++) {
            float4 w = *(const float4*)&eW1[l*NH + c0];
            float x = s[l];
            acc.x = fmaf(x, w.x, acc.x); acc.y = fmaf(x, w.y, acc.y);
            acc.z = fmaf(x, w.z, acc.z); acc.w = fmaf(x, w.w, acc.w);
        }
        part[hh][c0+0] = acc.x; part[hh][c0+1] = acc.y;
        part[hh][c0+2] = acc.z; part[hh][c0+3] = acc.w;
        __syncthreads();
        if (t < NH) {
            float r = eb1[t];
            #pragma unroll
            for (int k = 0; k < 8; k++) r += part[k][t];
            g_pre_e[i*NH + t] = r;
        }
    } else {
        int i = b - NA;
        for (int l = t; l < HID; l += 128) s[l] = hid[i*HID + l];
        for (int l = t; l < INP; l += 128) s[HID + l] = obs[i*INP + l];
        __syncthreads();
        int l0 = hh * 90;
        #pragma unroll 10
        for (int l = l0; l < l0 + 90; l++) {
            float4 w = *(const float4*)&iW1[l*NH + c0];
            float x = s[l];
            acc.x = fmaf(x, w.x, acc.x); acc.y = fmaf(x, w.y, acc.y);
            acc.z = fmaf(x, w.z, acc.z); acc.w = fmaf(x, w.w, acc.w);
        }
        part[hh][c0+0] = acc.x; part[hh][c0+1] = acc.y;
        part[hh][c0+2] = acc.z; part[hh][c0+3] = acc.w;
        __syncthreads();
        if (t < NH) {
            float r = ib1[t];
            #pragma unroll
            for (int k = 0; k < 8; k++) r += part[k][t];
            g_pre_i[i*NH + t] = r;
        }
    }
}

// ---------------- fused BN stats (both tensors), single pass, coalesced ----------------
__global__ void k_bn(const float* __restrict__ eg, const float* __restrict__ ebt,
                     const float* __restrict__ ig, const float* __restrict__ ibt) {
    int which = blockIdx.x;    // 2 blocks, 1024 threads
    const float* pre = which ? g_pre_i : g_pre_e;
    const float* gm  = which ? ig  : eg;
    const float* bt  = which ? ibt : ebt;
    int t = threadIdx.x;
    int c = t & 63, rg = t >> 6;   // 16 row groups
    float s = 0.f, s2 = 0.f;
    for (int r = rg; r < NA; r += 16) {
        float x = pre[r*NH + c];   // addr = t + 1024k : fully coalesced
        s += x; s2 = fmaf(x, x, s2);
    }
    __shared__ float sh1[16][NH], sh2[16][NH];
    sh1[rg][c] = s; sh2[rg][c] = s2;
    __syncthreads();
    if (t < NH) {
        float a = 0.f, b = 0.f;
        #pragma unroll
        for (int k = 0; k < 16; k++) { a += sh1[k][t]; b += sh2[k][t]; }
        float mean = a * (1.f/NA);
        float var = b * (1.f/NA) - mean*mean;
        float sc = gm[t] * rsqrtf(var + BNEPS);
        g_scale[which][t] = sc;
        g_shift[which][t] = bt[t] - mean*sc;
    }
}

// ---------------- fused: enc linear2 + inf linear2 + latent head + entropy + KL + A/B GEMV ----------------
__global__ void k_lat(const float* __restrict__ eW2, const float* __restrict__ eb2,
                      const float* __restrict__ iW2, const float* __restrict__ ib2,
                      const float* __restrict__ eps, const float* __restrict__ dW1) {
    int i0 = blockIdx.x * 2, t = threadIdx.x;   // 256 blocks, 256 threads
    __shared__ float he[2][NH], hif[2][NH];
    __shared__ float sMuE[2][LAT], sMuI[2][LAT];
    __shared__ float sLat[2][LAT];
    __shared__ float red1[256], red2[256];
    __shared__ float pa[4][2][NH], pb[4][2][NH];
    {
        int g = (t >> 6) & 1, c = t & 63;
        if (t < 128) {
            float x = fmaf(g_pre_e[(i0+g)*NH + c], g_scale[0][c], g_shift[0][c]);
            he[g][c] = (x > 0.f) ? x : 0.01f*x;
        } else {
            float x = fmaf(g_pre_i[(i0+g)*NH + c], g_scale[1][c], g_shift[1][c]);
            hif[g][c] = (x > 0.f) ? x : 0.01f*x;
        }
    }
    __syncthreads();
    const int c0 = 2*t;   // t<128: mu columns [0,254]; t>=128: logvar columns [256,510]
    float be0 = eb2[c0], be1 = eb2[c0+1];
    float bi0 = ib2[c0], bi1 = ib2[c0+1];
    float e00 = be0, e01 = be1, e10 = be0, e11 = be1;
    float i00 = bi0, i01 = bi1, i10 = bi0, i11 = bi1;
    #pragma unroll 8
    for (int l = 0; l < NH; l++) {
        float2 we = *(const float2*)&eW2[l*(2*LAT) + c0];
        float2 wi = *(const float2*)&iW2[l*(2*LAT) + c0];
        float h0 = he[0][l], h1 = he[1][l];
        float q0 = hif[0][l], q1 = hif[1][l];
        e00 = fmaf(h0, we.x, e00); e01 = fmaf(h0, we.y, e01);
        e10 = fmaf(h1, we.x, e10); e11 = fmaf(h1, we.y, e11);
        i00 = fmaf(q0, wi.x, i00); i01 = fmaf(q0, wi.y, i01);
        i10 = fmaf(q1, wi.x, i10); i11 = fmaf(q1, wi.y, i11);
    }
    if (t < 128) {
        sMuE[0][c0] = e00; sMuE[0][c0+1] = e01;
        sMuE[1][c0] = e10; sMuE[1][c0+1] = e11;
        sMuI[0][c0] = i00; sMuI[0][c0+1] = i01;
        sMuI[1][c0] = i10; sMuI[1][c0+1] = i11;
        *(float2*)&g_mu[i0*LAT + c0]     = make_float2(e00, e01);
        *(float2*)&g_mu[(i0+1)*LAT + c0] = make_float2(e10, e11);
    }
    __syncthreads();
    float ent = 0.f, kl = 0.f;
    if (t >= 128) {
        const int li = c0 - LAT;   // c0 in [256,510] -> li in [0,254]
        float eA0[2] = {e00, e10}, eA1[2] = {e01, e11};
        float iA0[2] = {i00, i10}, iA1[2] = {i01, i11};
        #pragma unroll
        for (int g = 0; g < 2; g++) {
            int gi = (i0+g)*LAT + li;
            // encoder path
            float v0 = fmaxf(expf(eA0[g]), 0.002f);
            float v1 = fmaxf(expf(eA1[g]), 0.002f);
            float ls0 = 0.5f*logf(v0), ls1 = 0.5f*logf(v1);
            float mu0 = sMuE[g][li], mu1 = sMuE[g][li+1];
            *(float2*)&g_ni2v[gi] = make_float2(-0.5f/v0, -0.5f/v1);
            *(float2*)&g_cc[gi]   = make_float2(13.9f - ls0 - 0.5f*LOG2PI,
                                                13.9f - ls1 - 0.5f*LOG2PI);
            float2 e2 = *(const float2*)&eps[gi];
            float l0v = fmaf(sqrtf(v0), e2.x, mu0);
            float l1v = fmaf(sqrtf(v1), e2.y, mu1);
            *(float2*)&g_lat[gi] = make_float2(l0v, l1v);
            sLat[g][li] = l0v; sLat[g][li+1] = l1v;
            ent += 1.f + LOG2PI + ls0 + ls1;
            // inference path + KL
            float vq0 = fmaxf(expf(iA0[g]), 0.002f);
            float vq1 = fmaxf(expf(iA1[g]), 0.002f);
            float lsq0 = 0.5f*logf(vq0), lsq1 = 0.5f*logf(vq1);
            float d0 = mu0 - sMuI[g][li];
            float d1 = mu1 - sMuI[g][li+1];
            kl += (lsq0 - ls0 + (v0 + d0*d0) / (2.f*vq0) - 0.5f)
                + (lsq1 - ls1 + (v1 + d1*d1) / (2.f*vq1) - 0.5f);
        }
    }
    red1[t] = ent; red2[t] = kl;
    __syncthreads();
    for (int o = 128; o; o >>= 1) {
        if (t < o) { red1[t] += red1[t+o]; red2[t] += red2[t+o]; }
        __syncthreads();
    }
    if (t == 0) { atomicAdd(&g_ent, (double)red1[0]); atomicAdd(&g_kl, (double)red2[0]); }
    __syncthreads();   // sLat fully written before GEMV reads it
    // ---- A/B GEMV on the latent already in smem ----
    const int c = t & 63, q = t >> 6;
    float a0 = 0.f, b0 = 0.f, a1 = 0.f, b1 = 0.f;
    const int l0 = q * 64;
    #pragma unroll 8
    for (int l = l0; l < l0 + 64; l++) {
        float wa = dW1[l*NH + c];
        float wb = dW1[(l + LAT)*NH + c];
        float L0 = sLat[0][l], L1 = sLat[1][l];
        a0 = fmaf(L0, wa, a0); b0 = fmaf(L0, wb, b0);
        a1 = fmaf(L1, wa, a1); b1 = fmaf(L1, wb, b1);
    }
    pa[q][0][c] = a0; pa[q][1][c] = a1;
    pb[q][0][c] = b0; pb[q][1][c] = b1;
    __syncthreads();
    if (t < 128) {
        int g = t >> 6, c2 = t & 63;
        g_A[(i0+g)*NH + c2] = pa[0][g][c2] + pa[1][g][c2] + pa[2][g][c2] + pa[3][g][c2];
        g_B[(i0+g)*NH + c2] = pb[0][g][c2] + pb[1][g][c2] + pb[2][g][c2] + pb[3][g][c2];
    }
}

// ---------------- fused: col stats + center (to g_Ac/g_Bc) + circ-corr -> w1 ----------------
// grid (64 columns, 2 s-halves), 512 threads; 2 s per thread with sliding carry
__global__ void k_col(const float* __restrict__ dg) {
    int c = blockIdx.x, sh = blockIdx.y;
    int t = threadIdx.x;
    int lane = t & 31, wid = t >> 5;
    __shared__ float a[NA], b2[2*NA];
    __shared__ float wred[16];
    __shared__ float bc[3];   // mA, mB, s2
    __shared__ float part0[512], part1[512];
    float av = g_A[t*NH + c], bv = g_B[t*NH + c];
    // mean(A)
    float r = av;
    #pragma unroll
    for (int o = 16; o; o >>= 1) r += __shfl_xor_sync(0xFFFFFFFFu, r, o);
    if (lane == 0) wred[wid] = r;
    __syncthreads();
    if (t == 0) { float x = 0.f; for (int k = 0; k < 16; k++) x += wred[k]; bc[0] = x * (1.f/NA); }
    __syncthreads();
    // mean(B)
    r = bv;
    #pragma unroll
    for (int o = 16; o; o >>= 1) r += __shfl_xor_sync(0xFFFFFFFFu, r, o);
    if (lane == 0) wred[wid] = r;
    __syncthreads();
    if (t == 0) { float x = 0.f; for (int k = 0; k < 16; k++) x += wred[k]; bc[1] = x * (1.f/NA); }
    __syncthreads();
    av -= bc[0]; bv -= bc[1];
    a[t] = av; b2[t] = bv; b2[t + NA] = bv;
    if (sh == 0) { g_Ac[t*NH + c] = av; g_Bc[t*NH + c] = bv; }
    // mean(a^2+b^2)
    r = av*av + bv*bv;
    #pragma unroll
    for (int o = 16; o; o >>= 1) r += __shfl_xor_sync(0xFFFFFFFFu, r, o);
    if (lane == 0) wred[wid] = r;
    __syncthreads();
    if (t == 0) { float x = 0.f; for (int k = 0; k < 16; k++) x += wred[k]; bc[2] = x * (1.f/NA); }
    __syncthreads();   // also guarantees a[], b2[] complete
    // circular correlation, 2 s per thread with sliding carry:
    //   s0 = sh*256 + 2*sq, s1 = s0+1
    //   cr0 += a[j]*b2[511-s0+j], cr1 += a[j]*b2[510-s0+j]
    const int sq = t & 127, jh = t >> 7;   // 128 s-pairs x 4 j-quarters
    const int s0 = sh*256 + 2*sq;
    const int jbase = jh * 128;
    const float* ap = &a[jbase];
    const float* bp = &b2[510 - s0 + jbase];   // bp[j'] = b2[510-s0+jbase+j']
    float cr0 = 0.f, cr1 = 0.f;
    float wprev = bp[0];
    #pragma unroll 8
    for (int j = 0; j < 128; j++) {
        float wnew = bp[j + 1];
        float aj = ap[j];
        cr0 = fmaf(aj, wnew, cr0);
        cr1 = fmaf(aj, wprev, cr1);
        wprev = wnew;
    }
    part0[t] = cr0; part1[t] = cr1;
    __syncthreads();
    if (t < 128) {
        float c0 = part0[t] + part0[t+128] + part0[t+256] + part0[t+384];
        float c1 = part1[t] + part1[t+128] + part1[t+256] + part1[t+384];
        int ss0 = sh*256 + 2*t;
        float var0 = bc[2] + 2.f * c0 * (1.f/NA);
        float var1 = bc[2] + 2.f * c1 * (1.f/NA);
        float scale = dg[c];
        g_w1[ss0*NH + c]     = scale * rsqrtf(var0 + BNEPS);
        g_w1[(ss0+1)*NH + c] = scale * rsqrtf(var1 + BNEPS);
    }
}

// ---------------- fused MI (z=0) + DIS (z=1), transposed smem, float2 loads ----------------
__global__ void k_midis(const float* __restrict__ dbt,
                        const float* __restrict__ dW2,
                        const float* __restrict__ db2) {
    __shared__ float sh[8704];
    const int tid = threadIdx.x;            // 256
    const int j0 = blockIdx.x * 32, s0 = blockIdx.y * 32;
    const int tx = tid & 15, ty = tid >> 4;
    const int jj0 = 2*tx, ss0 = 2*ty;
    const int base = (j0 - s0 - 32) & (NA-1);
    const int r_lo = jj0 - ss0 + 30;        // even
    float v00, v01, v10, v11;
    if (blockIdx.z == 0) {
        // transposed: sMU_T/sNI_T/sCC_T [l][34], sL_T [l][66]
        float* sMU = sh;            // 32*34 = 1088
        float* sNI = sh + 1088;     // 1088
        float* sCC = sh + 2176;     // 1088
        float* sL  = sh + 3264;     // 32*66 = 2112
        float acc00 = 0.f, acc01 = 0.f, acc10 = 0.f, acc11 = 0.f;
        for (int l0 = 0; l0 < LAT; l0 += 32) {
            #pragma unroll
            for (int i = 0; i < 4; i++) {
                int idx = tid + i*256;
                int rr = idx >> 5, cc = idx & 31;
                int g = (j0 + rr)*LAT + l0 + cc;
                sMU[cc*34 + rr] = g_mu[g]; sNI[cc*34 + rr] = g_ni2v[g]; sCC[cc*34 + rr] = g_cc[g];
            }
            #pragma unroll
            for (int i = 0; i < 8; i++) {
                int idx = tid + i*256;
                int rr = idx >> 5, cc = idx & 31;
                sL[cc*66 + rr] = g_lat[((base + rr) & (NA-1))*LAT + l0 + cc];
            }
            __syncthreads();
            #pragma unroll
            for (int l = 0; l < 32; l++) {
                float2 mu  = *(const float2*)&sMU[l*34 + jj0];
                float2 nn  = *(const float2*)&sNI[l*34 + jj0];
                float2 cc2 = *(const float2*)&sCC[l*34 + jj0];
                float2 Llo = *(const float2*)&sL[l*66 + r_lo];      // rows r_lo, r_lo+1
                float2 Lhi = *(const float2*)&sL[l*66 + r_lo + 2];  // rows r_lo+2, r_lo+3
                float d;
                d = Llo.y - mu.x; acc00 += fmaxf(fmaf(d*d, nn.x, cc2.x), -13.9f);  // (ss0,   jj0)
                d = Lhi.x - mu.y; acc01 += fmaxf(fmaf(d*d, nn.y, cc2.y), -13.9f);  // (ss0,   jj0+1)
                d = Llo.x - mu.x; acc10 += fmaxf(fmaf(d*d, nn.x, cc2.x), -13.9f);  // (ss0+1, jj0)
                d = Llo.y - mu.y; acc11 += fmaxf(fmaf(d*d, nn.y, cc2.y), -13.9f);  // (ss0+1, jj0+1)
            }
            __syncthreads();
        }
        const float inv = 1.f / LAT;
        v00 = acc00 * inv; v01 = acc01 * inv; v10 = acc10 * inv; v11 = acc11 * inv;
        g_mi[(s0+ss0  )*NA + j0+jj0  ] = v00;
        g_mi[(s0+ss0  )*NA + j0+jj0+1] = v01;
        g_mi[(s0+ss0+1)*NA + j0+jj0  ] = v10;
        g_mi[(s0+ss0+1)*NA + j0+jj0+1] = v11;
    } else {
        // transposed: sa_T/sw_T [c][34], sb_T [c][66]
        float* sa   = sh;                 // 64*34 = 2176
        float* sw   = sh + 2176;          // 2176
        float* sb   = sh + 4352;          // 64*66 = 4224
        float* sdbt = sh + 8576;          // 64
        float* sdw2 = sh + 8640;          // 64
        if (tid < NH) { sdbt[tid] = dbt[tid]; sdw2[tid] = dW2[tid]; }
        #pragma unroll
        for (int i = 0; i < 8; i++) {
            int idx = tid + i*256;
            int rr = idx >> 6, c = idx & 63;
            sa[c*34 + rr] = g_Ac[(j0 + rr)*NH + c];
            sw[c*34 + rr] = g_w1[(s0 + rr)*NH + c];
        }
        #pragma unroll
        for (int i = 0; i < 16; i++) {
            int idx = tid + i*256;
            int rr = idx >> 6, c = idx & 63;
            sb[c*66 + rr] = g_Bc[((base + rr) & (NA-1))*NH + c];
        }
        __syncthreads();
        float acc00 = 0.f, acc01 = 0.f, acc10 = 0.f, acc11 = 0.f;
        #pragma unroll 8
        for (int c = 0; c < NH; c++) {
            float2 av = *(const float2*)&sa[c*34 + jj0];
            float2 wv = *(const float2*)&sw[c*34 + ss0];
            float bt = sdbt[c], w2 = sdw2[c];
            float2 Blo = *(const float2*)&sb[c*66 + r_lo];
            float2 Bhi = *(const float2*)&sb[c*66 + r_lo + 2];
            float u;
            u = fmaf(av.x + Blo.y, wv.x, bt); u = (u > 0.f) ? u : 0.01f*u; acc00 = fmaf(u, w2, acc00);
            u = fmaf(av.y + Bhi.x, wv.x, bt); u = (u > 0.f) ? u : 0.01f*u; acc01 = fmaf(u, w2, acc01);
            u = fmaf(av.x + Blo.x, wv.y, bt); u = (u > 0.f) ? u : 0.01f*u; acc10 = fmaf(u, w2, acc10);
            u = fmaf(av.y + Blo.y, wv.y, bt); u = (u > 0.f) ? u : 0.01f*u; acc11 = fmaf(u, w2, acc11);
        }
        float b2v = db2[0];
        v00 = fabsf(acc00 + b2v); v01 = fabsf(acc01 + b2v);
        v10 = fabsf(acc10 + b2v); v11 = fabsf(acc11 + b2v);
        g_dis[(s0+ss0  )*NA + j0+jj0  ] = v00;
        g_dis[(s0+ss0  )*NA + j0+jj0+1] = v01;
        g_dis[(s0+ss0+1)*NA + j0+jj0  ] = v10;
        g_dis[(s0+ss0+1)*NA + j0+jj0+1] = v11;
    }
    // ---- block min/max -> global atomic keys ----
    float mn = fminf(fminf(v00, v01), fminf(v10, v11));
    float mx = fmaxf(fmaxf(v00, v01), fmaxf(v10, v11));
    #pragma unroll
    for (int o = 16; o; o >>= 1) {
        mn = fminf(mn, __shfl_xor_sync(0xFFFFFFFFu, mn, o));
        mx = fmaxf(mx, __shfl_xor_sync(0xFFFFFFFFu, mx, o));
    }
    __shared__ float wmn[8], wmx[8];
    if ((tid & 31) == 0) { wmn[tid>>5] = mn; wmx[tid>>5] = mx; }
    __syncthreads();
    if (tid == 0) {
        float a = wmn[0], b = wmx[0];
        #pragma unroll
        for (int k = 1; k < 8; k++) { a = fminf(a, wmn[k]); b = fmaxf(b, wmx[k]); }
        atomicMin(&g_keymin[blockIdx.z], fkey(a));
        atomicMax(&g_keymax[blockIdx.z], fkey(b));
    }
}

// ---------------- normalized sums + last-block final assembly ----------------
__global__ void k_sums(float* __restrict__ out) {
    int tid = threadIdx.x;
    int base = blockIdx.x * 1024;
    float mi_min = funkey(g_keymin[0]);
    float mi_inv = 1.f / (funkey(g_keymax[0]) - mi_min + 1e-12f);
    float ds_min = funkey(g_keymin[1]);
    float ds_inv = 1.f / (funkey(g_keymax[1]) - ds_min + 1e-12f);
    double s1 = 0.0, s2 = 0.0;
    #pragma unroll
    for (int i = 0; i < 4; i++) {
        int idx = base + tid + i*256;
        float mi_n = (g_mi[idx] - mi_min) * mi_inv;
        float ds_n = (g_dis[idx] - ds_min) * ds_inv;
        s1 += (double)ds_n;
        s2 += (double)fminf(mi_n + ds_n, 1.0f);
    }
    __shared__ double d1[256], d2[256];
    d1[tid] = s1; d2[tid] = s2;
    __syncthreads();
    for (int o = 128; o; o >>= 1) {
        if (tid < o) { d1[tid] += d1[tid+o]; d2[tid] += d2[tid+o]; }
        __syncthreads();
    }
    if (tid == 0) {
        atomicAdd(&g_sum_disn, d1[0]);
        atomicAdd(&g_sum_min, d2[0]);
        __threadfence();
        unsigned old = atomicAdd(&g_done, 1u);
        if (old == 255u) {   // last of 256 blocks
            __threadfence();
            double sum_disn = atomicAdd(&g_sum_disn, 0.0);
            double sum_min  = atomicAdd(&g_sum_min, 0.0);
            double ent = atomicAdd(&g_ent, 0.0) / (double)NA;
            double kl  = atomicAdd(&g_kl, 0.0)  / (double)NA;
            double loss0 = fmin(ent*1e-4 + kl*1e-4, 2000.0);
            double ce = log1p(exp(loss0));
            double dis_norm = sum_disn / (double)NA;
            double dis_loss = -sum_min / (double)NA;
            double cdis = (dis_norm + dis_loss) / (double)NA;
            out[0] = (float)(ce + cdis);
            out[1] = (float)cdis;
            out[2] = (float)ce;
        }
    }
}

// ---------------- launcher ----------------
extern "C" void kernel_launch(void* const* d_in, const int* in_sizes, int n_in,
                              void* d_out, int out_size) {
    const float* obs  = (const float*)d_in[0];
    const float* hid  = (const float*)d_in[1];
    const float* eps  = (const float*)d_in[2];
    const float* eW1  = (const float*)d_in[3];
    const float* eb1  = (const float*)d_in[4];
    const float* eg   = (const float*)d_in[5];
    const float* ebt  = (const float*)d_in[6];
    const float* eW2  = (const float*)d_in[7];
    const float* eb2  = (const float*)d_in[8];
    const float* iW1  = (const float*)d_in[9];
    const float* ib1  = (const float*)d_in[10];
    const float* ig   = (const float*)d_in[11];
    const float* ibt  = (const float*)d_in[12];
    const float* iW2  = (const float*)d_in[13];
    const float* ib2  = (const float*)d_in[14];
    const float* dW1  = (const float*)d_in[15];
    const float* db1  = (const float*)d_in[16]; (void)db1; // cancels in BN
    const float* dg   = (const float*)d_in[17];
    const float* dbt  = (const float*)d_in[18];
    const float* dW2  = (const float*)d_in[19];
    const float* db2  = (const float*)d_in[20];
    float* out = (float*)d_out;

    k_lin<<<2*NA, 128>>>(obs, hid, eW1, eb1, iW1, ib1);
    k_bn<<<2, 1024>>>(eg, ebt, ig, ibt);
    k_lat<<<256, 256>>>(eW2, eb2, iW2, ib2, eps, dW1);
    k_col<<<dim3(64, 2), 512>>>(dg);
    k_midis<<<dim3(16, 16, 2), 256>>>(dbt, dW2, db2);
    k_sums<<<256, 256>>>(out);
}

// round 13
// speedup vs baseline: 2.9259x; 1.0196x over previous
#include <cuda_runtime.h>
#include <math.h>

#define NA   512
#define OBSD 128
#define INP  656
#define HID  64
#define LAT  256
#define NH   64
#define LOG2PI 1.8378770664093453f
#define BNEPS 1e-5f

// ---------------- scratch (device globals; no allocation allowed) ----------------
// g_A/g_B/g_Ac/g_Bc/g_w1 are TRANSPOSED: [c][s] i.e. index c*NA + s
__device__ __align__(16) float g_pre_e[NA*NH];
__device__ __align__(16) float g_pre_i[NA*NH];
__device__ float g_scale[2][NH], g_shift[2][NH];
__device__ __align__(16) float g_mu[NA*LAT];
__device__ __align__(16) float g_ni2v[NA*LAT], g_cc[NA*LAT], g_lat[NA*LAT];
__device__ __align__(16) float g_A[NH*NA], g_B[NH*NA];
__device__ __align__(16) float g_Ac[NH*NA], g_Bc[NH*NA];
__device__ __align__(16) float g_w1[NH*NA];
__device__ __align__(16) float g_mi[NA*NA], g_dis[NA*NA];
__device__ double g_ent, g_kl, g_sum_disn, g_sum_min;
__device__ unsigned g_keymin[2], g_keymax[2];
__device__ unsigned g_done;

// ordered-uint encoding for float atomic min/max
__device__ __forceinline__ unsigned fkey(float f) {
    unsigned u = __float_as_uint(f);
    return (u & 0x80000000u) ? ~u : (u | 0x80000000u);
}
__device__ __forceinline__ float funkey(unsigned k) {
    unsigned u = (k & 0x80000000u) ? (k & 0x7fffffffu) : ~k;
    return __uint_as_float(u);
}

// ---------------- fused linear1 (encoder + inference), 1 row/block, 8-way split ----------------
__global__ void k_lin(const float* __restrict__ obs, const float* __restrict__ hid,
                      const float* __restrict__ eW1, const float* __restrict__ eb1,
                      const float* __restrict__ iW1, const float* __restrict__ ib1) {
    int b = blockIdx.x, t = threadIdx.x;   // 1024 blocks, 128 threads
    if (b == 0 && t == 0) {
        g_ent = 0.0; g_kl = 0.0; g_sum_disn = 0.0; g_sum_min = 0.0;
        g_keymin[0] = 0xFFFFFFFFu; g_keymin[1] = 0xFFFFFFFFu;
        g_keymax[0] = 0u; g_keymax[1] = 0u;
        g_done = 0u;
    }
    __shared__ float s[HID + INP];
    __shared__ float part[8][NH];
    int g = t & 15, hh = t >> 4;   // 16 col-groups x 8 l-slices
    int c0 = g * 4;
    float4 acc = make_float4(0.f, 0.f, 0.f, 0.f);
    if (b < NA) {
        int i = b;
        // last 128 floats of row; offset 528 floats = 2112 B, 16B aligned
        if (t < 32) ((float4*)s)[t] = *(const float4*)(obs + i*INP + (INP-OBSD) + 4*t);
        __syncthreads();
        int l0 = hh * 16;
        #pragma unroll 16
        for (int l = l0; l < l0 + 16; l++) {
            float4 w = *(const float4*)&eW1[l*NH + c0];
            float x = s[l];
            acc.x = fmaf(x, w.x, acc.x); acc.y = fmaf(x, w.y, acc.y);
            acc.z = fmaf(x, w.z, acc.z); acc.w = fmaf(x, w.w, acc.w);
        }
        part[hh][c0+0] = acc.x; part[hh][c0+1] = acc.y;
        part[hh][c0+2] = acc.z; part[hh][c0+3] = acc.w;
        __syncthreads();
        if (t < NH) {
            float r = eb1[t];
            #pragma unroll
            for (int k = 0; k < 8; k++) r += part[k][t];
            g_pre_e[i*NH + t] = r;
        }
    } else {
        int i = b - NA;
        if (t < 16) ((float4*)s)[t] = ((const float4*)(hid + i*HID))[t];
        {
            const float4* o4 = (const float4*)(obs + i*INP);   // 656 = 164 float4, aligned
            float4* s4 = (float4*)(s + HID);
            for (int l = t; l < INP/4; l += 128) s4[l] = o4[l];
        }
        __syncthreads();
        int l0 = hh * 90;
        #pragma unroll 10
        for (int l = l0; l < l0 + 90; l++) {
            float4 w = *(const float4*)&iW1[l*NH + c0];
            float x = s[l];
            acc.x = fmaf(x, w.x, acc.x); acc.y = fmaf(x, w.y, acc.y);
            acc.z = fmaf(x, w.z, acc.z); acc.w = fmaf(x, w.w, acc.w);
        }
        part[hh][c0+0] = acc.x; part[hh][c0+1] = acc.y;
        part[hh][c0+2] = acc.z; part[hh][c0+3] = acc.w;
        __syncthreads();
        if (t < NH) {
            float r = ib1[t];
            #pragma unroll
            for (int k = 0; k < 8; k++) r += part[k][t];
            g_pre_i[i*NH + t] = r;
        }
    }
}

// ---------------- fused BN stats (both tensors), single pass, coalesced ----------------
__global__ void k_bn(const float* __restrict__ eg, const float* __restrict__ ebt,
                     const float* __restrict__ ig, const float* __restrict__ ibt) {
    int which = blockIdx.x;    // 2 blocks, 1024 threads
    const float* pre = which ? g_pre_i : g_pre_e;
    const float* gm  = which ? ig  : eg;
    const float* bt  = which ? ibt : ebt;
    int t = threadIdx.x;
    int c = t & 63, rg = t >> 6;   // 16 row groups
    float s = 0.f, s2 = 0.f;
    for (int r = rg; r < NA; r += 16) {
        float x = pre[r*NH + c];   // addr = t + 1024k : fully coalesced
        s += x; s2 = fmaf(x, x, s2);
    }
    __shared__ float sh1[16][NH], sh2[16][NH];
    sh1[rg][c] = s; sh2[rg][c] = s2;
    __syncthreads();
    if (t < NH) {
        float a = 0.f, b = 0.f;
        #pragma unroll
        for (int k = 0; k < 16; k++) { a += sh1[k][t]; b += sh2[k][t]; }
        float mean = a * (1.f/NA);
        float var = b * (1.f/NA) - mean*mean;
        float sc = gm[t] * rsqrtf(var + BNEPS);
        g_scale[which][t] = sc;
        g_shift[which][t] = bt[t] - mean*sc;
    }
}

// ---------------- fused: enc linear2 + inf linear2 + latent head + entropy + KL + A/B GEMV ----------------
__global__ void k_lat(const float* __restrict__ eW2, const float* __restrict__ eb2,
                      const float* __restrict__ iW2, const float* __restrict__ ib2,
                      const float* __restrict__ eps, const float* __restrict__ dW1) {
    int i0 = blockIdx.x * 2, t = threadIdx.x;   // 256 blocks, 256 threads
    __shared__ float he[2][NH], hif[2][NH];
    __shared__ float sMuE[2][LAT], sMuI[2][LAT];
    __shared__ float sLat[2][LAT];
    __shared__ float red1[256], red2[256];
    __shared__ float pa[4][2][NH], pb[4][2][NH];
    {
        int g = (t >> 6) & 1, c = t & 63;
        if (t < 128) {
            float x = fmaf(g_pre_e[(i0+g)*NH + c], g_scale[0][c], g_shift[0][c]);
            he[g][c] = (x > 0.f) ? x : 0.01f*x;
        } else {
            float x = fmaf(g_pre_i[(i0+g)*NH + c], g_scale[1][c], g_shift[1][c]);
            hif[g][c] = (x > 0.f) ? x : 0.01f*x;
        }
    }
    __syncthreads();
    const int c0 = 2*t;   // t<128: mu columns [0,254]; t>=128: logvar columns [256,510]
    float be0 = eb2[c0], be1 = eb2[c0+1];
    float bi0 = ib2[c0], bi1 = ib2[c0+1];
    float e00 = be0, e01 = be1, e10 = be0, e11 = be1;
    float i00 = bi0, i01 = bi1, i10 = bi0, i11 = bi1;
    #pragma unroll 8
    for (int l = 0; l < NH; l++) {
        float2 we = *(const float2*)&eW2[l*(2*LAT) + c0];
        float2 wi = *(const float2*)&iW2[l*(2*LAT) + c0];
        float h0 = he[0][l], h1 = he[1][l];
        float q0 = hif[0][l], q1 = hif[1][l];
        e00 = fmaf(h0, we.x, e00); e01 = fmaf(h0, we.y, e01);
        e10 = fmaf(h1, we.x, e10); e11 = fmaf(h1, we.y, e11);
        i00 = fmaf(q0, wi.x, i00); i01 = fmaf(q0, wi.y, i01);
        i10 = fmaf(q1, wi.x, i10); i11 = fmaf(q1, wi.y, i11);
    }
    if (t < 128) {
        sMuE[0][c0] = e00; sMuE[0][c0+1] = e01;
        sMuE[1][c0] = e10; sMuE[1][c0+1] = e11;
        sMuI[0][c0] = i00; sMuI[0][c0+1] = i01;
        sMuI[1][c0] = i10; sMuI[1][c0+1] = i11;
        *(float2*)&g_mu[i0*LAT + c0]     = make_float2(e00, e01);
        *(float2*)&g_mu[(i0+1)*LAT + c0] = make_float2(e10, e11);
    }
    __syncthreads();
    float ent = 0.f, kl = 0.f;
    if (t >= 128) {
        const int li = c0 - LAT;   // c0 in [256,510] -> li in [0,254]
        float eA0[2] = {e00, e10}, eA1[2] = {e01, e11};
        float iA0[2] = {i00, i10}, iA1[2] = {i01, i11};
        #pragma unroll
        for (int g = 0; g < 2; g++) {
            int gi = (i0+g)*LAT + li;
            // encoder path
            float v0 = fmaxf(expf(eA0[g]), 0.002f);
            float v1 = fmaxf(expf(eA1[g]), 0.002f);
            float ls0 = 0.5f*logf(v0), ls1 = 0.5f*logf(v1);
            float mu0 = sMuE[g][li], mu1 = sMuE[g][li+1];
            *(float2*)&g_ni2v[gi] = make_float2(-0.5f/v0, -0.5f/v1);
            *(float2*)&g_cc[gi]   = make_float2(13.9f - ls0 - 0.5f*LOG2PI,
                                                13.9f - ls1 - 0.5f*LOG2PI);
            float2 e2 = *(const float2*)&eps[gi];
            float l0v = fmaf(sqrtf(v0), e2.x, mu0);
            float l1v = fmaf(sqrtf(v1), e2.y, mu1);
            *(float2*)&g_lat[gi] = make_float2(l0v, l1v);
            sLat[g][li] = l0v; sLat[g][li+1] = l1v;
            ent += 1.f + LOG2PI + ls0 + ls1;
            // inference path + KL
            float vq0 = fmaxf(expf(iA0[g]), 0.002f);
            float vq1 = fmaxf(expf(iA1[g]), 0.002f);
            float lsq0 = 0.5f*logf(vq0), lsq1 = 0.5f*logf(vq1);
            float d0 = mu0 - sMuI[g][li];
            float d1 = mu1 - sMuI[g][li+1];
            kl += (lsq0 - ls0 + (v0 + d0*d0) / (2.f*vq0) - 0.5f)
                + (lsq1 - ls1 + (v1 + d1*d1) / (2.f*vq1) - 0.5f);
        }
    }
    red1[t] = ent; red2[t] = kl;
    __syncthreads();
    for (int o = 128; o; o >>= 1) {
        if (t < o) { red1[t] += red1[t+o]; red2[t] += red2[t+o]; }
        __syncthreads();
    }
    if (t == 0) { atomicAdd(&g_ent, (double)red1[0]); atomicAdd(&g_kl, (double)red2[0]); }
    __syncthreads();   // sLat fully written before GEMV reads it
    // ---- A/B GEMV on the latent already in smem ----
    const int c = t & 63, q = t >> 6;
    float a0 = 0.f, b0 = 0.f, a1 = 0.f, b1 = 0.f;
    const int l0 = q * 64;
    #pragma unroll 8
    for (int l = l0; l < l0 + 64; l++) {
        float wa = dW1[l*NH + c];
        float wb = dW1[(l + LAT)*NH + c];
        float L0 = sLat[0][l], L1 = sLat[1][l];
        a0 = fmaf(L0, wa, a0); b0 = fmaf(L0, wb, b0);
        a1 = fmaf(L1, wa, a1); b1 = fmaf(L1, wb, b1);
    }
    pa[q][0][c] = a0; pa[q][1][c] = a1;
    pb[q][0][c] = b0; pb[q][1][c] = b1;
    __syncthreads();
    if (t < 128) {
        int g = t >> 6, c2 = t & 63;
        // transposed write: [c][s]
        g_A[c2*NA + i0+g] = pa[0][g][c2] + pa[1][g][c2] + pa[2][g][c2] + pa[3][g][c2];
        g_B[c2*NA + i0+g] = pb[0][g][c2] + pb[1][g][c2] + pb[2][g][c2] + pb[3][g][c2];
    }
}

// ---------------- fused: col stats + center (to g_Ac/g_Bc) + circ-corr -> w1 ----------------
// grid (64 columns, 2 s-halves), 512 threads; all global traffic unit-stride ([c][s] layout)
__global__ void k_col(const float* __restrict__ dg) {
    int c = blockIdx.x, sh = blockIdx.y;
    int t = threadIdx.x;
    int lane = t & 31, wid = t >> 5;
    __shared__ float a[NA], b2[2*NA];
    __shared__ float wred[16];
    __shared__ float bc[3];   // mA, mB, s2
    __shared__ float part0[512], part1[512];
    float av = g_A[c*NA + t], bv = g_B[c*NA + t];   // coalesced
    // mean(A)
    float r = av;
    #pragma unroll
    for (int o = 16; o; o >>= 1) r += __shfl_xor_sync(0xFFFFFFFFu, r, o);
    if (lane == 0) wred[wid] = r;
    __syncthreads();
    if (t < 32) {
        float x = (t < 16) ? wred[t] : 0.f;
        x += __shfl_xor_sync(0xFFFFFFFFu, x, 8);
        x += __shfl_xor_sync(0xFFFFFFFFu, x, 4);
        x += __shfl_xor_sync(0xFFFFFFFFu, x, 2);
        x += __shfl_xor_sync(0xFFFFFFFFu, x, 1);
        if (t == 0) bc[0] = x * (1.f/NA);
    }
    __syncthreads();
    // mean(B)
    r = bv;
    #pragma unroll
    for (int o = 16; o; o >>= 1) r += __shfl_xor_sync(0xFFFFFFFFu, r, o);
    if (lane == 0) wred[wid] = r;
    __syncthreads();
    if (t < 32) {
        float x = (t < 16) ? wred[t] : 0.f;
        x += __shfl_xor_sync(0xFFFFFFFFu, x, 8);
        x += __shfl_xor_sync(0xFFFFFFFFu, x, 4);
        x += __shfl_xor_sync(0xFFFFFFFFu, x, 2);
        x += __shfl_xor_sync(0xFFFFFFFFu, x, 1);
        if (t == 0) bc[1] = x * (1.f/NA);
    }
    __syncthreads();
    av -= bc[0]; bv -= bc[1];
    a[t] = av; b2[t] = bv; b2[t + NA] = bv;
    if (sh == 0) { g_Ac[c*NA + t] = av; g_Bc[c*NA + t] = bv; }   // coalesced
    // mean(a^2+b^2)
    r = av*av + bv*bv;
    #pragma unroll
    for (int o = 16; o; o >>= 1) r += __shfl_xor_sync(0xFFFFFFFFu, r, o);
    if (lane == 0) wred[wid] = r;
    __syncthreads();
    if (t < 32) {
        float x = (t < 16) ? wred[t] : 0.f;
        x += __shfl_xor_sync(0xFFFFFFFFu, x, 8);
        x += __shfl_xor_sync(0xFFFFFFFFu, x, 4);
        x += __shfl_xor_sync(0xFFFFFFFFu, x, 2);
        x += __shfl_xor_sync(0xFFFFFFFFu, x, 1);
        if (t == 0) bc[2] = x * (1.f/NA);
    }
    __syncthreads();   // also guarantees a[], b2[] complete
    // circular correlation, 2 s per thread with sliding carry:
    //   s0 = sh*256 + 2*sq, s1 = s0+1
    //   cr0 += a[j]*b2[511-s0+j], cr1 += a[j]*b2[510-s0+j]
    const int sq = t & 127, jh = t >> 7;   // 128 s-pairs x 4 j-quarters
    const int s0 = sh*256 + 2*sq;
    const int jbase = jh * 128;
    const float* ap = &a[jbase];
    const float* bp = &b2[510 - s0 + jbase];   // bp[j'] = b2[510-s0+jbase+j']
    float cr0 = 0.f, cr1 = 0.f;
    float wprev = bp[0];
    #pragma unroll 8
    for (int j = 0; j < 128; j++) {
        float wnew = bp[j + 1];
        float aj = ap[j];
        cr0 = fmaf(aj, wnew, cr0);
        cr1 = fmaf(aj, wprev, cr1);
        wprev = wnew;
    }
    part0[t] = cr0; part1[t] = cr1;
    __syncthreads();
    if (t < 128) {
        float c0 = part0[t] + part0[t+128] + part0[t+256] + part0[t+384];
        float c1 = part1[t] + part1[t+128] + part1[t+256] + part1[t+384];
        int ss0 = sh*256 + 2*t;
        float var0 = bc[2] + 2.f * c0 * (1.f/NA);
        float var1 = bc[2] + 2.f * c1 * (1.f/NA);
        float scale = dg[c];
        *(float2*)&g_w1[c*NA + ss0] = make_float2(scale * rsqrtf(var0 + BNEPS),
                                                  scale * rsqrtf(var1 + BNEPS));
    }
}

// ---------------- fused MI (z=0) + DIS (z=1), transposed smem, float2 loads ----------------
__global__ void k_midis(const float* __restrict__ dbt,
                        const float* __restrict__ dW2,
                        const float* __restrict__ db2) {
    __shared__ float sh[8704];
    const int tid = threadIdx.x;            // 256
    const int j0 = blockIdx.x * 32, s0 = blockIdx.y * 32;
    const int tx = tid & 15, ty = tid >> 4;
    const int jj0 = 2*tx, ss0 = 2*ty;
    const int base = (j0 - s0 - 32) & (NA-1);
    const int r_lo = jj0 - ss0 + 30;        // even
    float v00, v01, v10, v11;
    if (blockIdx.z == 0) {
        // transposed: sMU_T/sNI_T/sCC_T [l][34], sL_T [l][66]
        float* sMU = sh;            // 32*34 = 1088
        float* sNI = sh + 1088;     // 1088
        float* sCC = sh + 2176;     // 1088
        float* sL  = sh + 3264;     // 32*66 = 2112
        float acc00 = 0.f, acc01 = 0.f, acc10 = 0.f, acc11 = 0.f;
        for (int l0 = 0; l0 < LAT; l0 += 32) {
            #pragma unroll
            for (int i = 0; i < 4; i++) {
                int idx = tid + i*256;
                int rr = idx >> 5, cc = idx & 31;
                int g = (j0 + rr)*LAT + l0 + cc;
                sMU[cc*34 + rr] = g_mu[g]; sNI[cc*34 + rr] = g_ni2v[g]; sCC[cc*34 + rr] = g_cc[g];
            }
            #pragma unroll
            for (int i = 0; i < 8; i++) {
                int idx = tid + i*256;
                int rr = idx >> 5, cc = idx & 31;
                sL[cc*66 + rr] = g_lat[((base + rr) & (NA-1))*LAT + l0 + cc];
            }
            __syncthreads();
            #pragma unroll
            for (int l = 0; l < 32; l++) {
                float2 mu  = *(const float2*)&sMU[l*34 + jj0];
                float2 nn  = *(const float2*)&sNI[l*34 + jj0];
                float2 cc2 = *(const float2*)&sCC[l*34 + jj0];
                float2 Llo = *(const float2*)&sL[l*66 + r_lo];      // rows r_lo, r_lo+1
                float2 Lhi = *(const float2*)&sL[l*66 + r_lo + 2];  // rows r_lo+2, r_lo+3
                float d;
                d = Llo.y - mu.x; acc00 += fmaxf(fmaf(d*d, nn.x, cc2.x), -13.9f);  // (ss0,   jj0)
                d = Lhi.x - mu.y; acc01 += fmaxf(fmaf(d*d, nn.y, cc2.y), -13.9f);  // (ss0,   jj0+1)
                d = Llo.x - mu.x; acc10 += fmaxf(fmaf(d*d, nn.x, cc2.x), -13.9f);  // (ss0+1, jj0)
                d = Llo.y - mu.y; acc11 += fmaxf(fmaf(d*d, nn.y, cc2.y), -13.9f);  // (ss0+1, jj0+1)
            }
            __syncthreads();
        }
        const float inv = 1.f / LAT;
        v00 = acc00 * inv; v01 = acc01 * inv; v10 = acc10 * inv; v11 = acc11 * inv;
        g_mi[(s0+ss0  )*NA + j0+jj0  ] = v00;
        g_mi[(s0+ss0  )*NA + j0+jj0+1] = v01;
        g_mi[(s0+ss0+1)*NA + j0+jj0  ] = v10;
        g_mi[(s0+ss0+1)*NA + j0+jj0+1] = v11;
    } else {
        // transposed: sa_T/sw_T [c][34], sb_T [c][66]; sources are [c][s] so rr sits in lanes
        float* sa   = sh;                 // 64*34 = 2176
        float* sw   = sh + 2176;          // 2176
        float* sb   = sh + 4352;          // 64*66 = 4224
        float* sdbt = sh + 8576;          // 64
        float* sdw2 = sh + 8640;          // 64
        if (tid < NH) { sdbt[tid] = dbt[tid]; sdw2[tid] = dW2[tid]; }
        #pragma unroll
        for (int i = 0; i < 8; i++) {
            int idx = tid + i*256;
            int rr = idx & 31, c = idx >> 5;    // c in 0..63, rr in lanes -> coalesced
            sa[c*34 + rr] = g_Ac[c*NA + j0 + rr];
            sw[c*34 + rr] = g_w1[c*NA + s0 + rr];
        }
        #pragma unroll
        for (int i = 0; i < 16; i++) {
            int idx = tid + i*256;
            int rr = idx & 63, c = idx >> 6;    // c in 0..63
            sb[c*66 + rr] = g_Bc[c*NA + ((base + rr) & (NA-1))];
        }
        __syncthreads();
        float acc00 = 0.f, acc01 = 0.f, acc10 = 0.f, acc11 = 0.f;
        #pragma unroll 8
        for (int c = 0; c < NH; c++) {
            float2 av = *(const float2*)&sa[c*34 + jj0];
            float2 wv = *(const float2*)&sw[c*34 + ss0];
            float bt = sdbt[c], w2 = sdw2[c];
            float2 Blo = *(const float2*)&sb[c*66 + r_lo];
            float2 Bhi = *(const float2*)&sb[c*66 + r_lo + 2];
            float u;
            u = fmaf(av.x + Blo.y, wv.x, bt); u = (u > 0.f) ? u : 0.01f*u; acc00 = fmaf(u, w2, acc00);
            u = fmaf(av.y + Bhi.x, wv.x, bt); u = (u > 0.f) ? u : 0.01f*u; acc01 = fmaf(u, w2, acc01);
            u = fmaf(av.x + Blo.x, wv.y, bt); u = (u > 0.f) ? u : 0.01f*u; acc10 = fmaf(u, w2, acc10);
            u = fmaf(av.y + Blo.y, wv.y, bt); u = (u > 0.f) ? u : 0.01f*u; acc11 = fmaf(u, w2, acc11);
        }
        float b2v = db2[0];
        v00 = fabsf(acc00 + b2v); v01 = fabsf(acc01 + b2v);
        v10 = fabsf(acc10 + b2v); v11 = fabsf(acc11 + b2v);
        g_dis[(s0+ss0  )*NA + j0+jj0  ] = v00;
        g_dis[(s0+ss0  )*NA + j0+jj0+1] = v01;
        g_dis[(s0+ss0+1)*NA + j0+jj0  ] = v10;
        g_dis[(s0+ss0+1)*NA + j0+jj0+1] = v11;
    }
    // ---- block min/max -> global atomic keys ----
    float mn = fminf(fminf(v00, v01), fminf(v10, v11));
    float mx = fmaxf(fmaxf(v00, v01), fmaxf(v10, v11));
    #pragma unroll
    for (int o = 16; o; o >>= 1) {
        mn = fminf(mn, __shfl_xor_sync(0xFFFFFFFFu, mn, o));
        mx = fmaxf(mx, __shfl_xor_sync(0xFFFFFFFFu, mx, o));
    }
    __shared__ float wmn[8], wmx[8];
    if ((tid & 31) == 0) { wmn[tid>>5] = mn; wmx[tid>>5] = mx; }
    __syncthreads();
    if (tid == 0) {
        float a = wmn[0], b = wmx[0];
        #pragma unroll
        for (int k = 1; k < 8; k++) { a = fminf(a, wmn[k]); b = fmaxf(b, wmx[k]); }
        atomicMin(&g_keymin[blockIdx.z], fkey(a));
        atomicMax(&g_keymax[blockIdx.z], fkey(b));
    }
}

// ---------------- normalized sums + last-block final assembly ----------------
__global__ void k_sums(float* __restrict__ out) {
    int tid = threadIdx.x;
    int base = blockIdx.x * 1024;
    float mi_min = funkey(g_keymin[0]);
    float mi_inv = 1.f / (funkey(g_keymax[0]) - mi_min + 1e-12f);
    float ds_min = funkey(g_keymin[1]);
    float ds_inv = 1.f / (funkey(g_keymax[1]) - ds_min + 1e-12f);
    double s1 = 0.0, s2 = 0.0;
    #pragma unroll
    for (int i = 0; i < 4; i++) {
        int idx = base + tid + i*256;
        float mi_n = (g_mi[idx] - mi_min) * mi_inv;
        float ds_n = (g_dis[idx] - ds_min) * ds_inv;
        s1 += (double)ds_n;
        s2 += (double)fminf(mi_n + ds_n, 1.0f);
    }
    __shared__ double d1[256], d2[256];
    d1[tid] = s1; d2[tid] = s2;
    __syncthreads();
    for (int o = 128; o; o >>= 1) {
        if (tid < o) { d1[tid] += d1[tid+o]; d2[tid] += d2[tid+o]; }
        __syncthreads();
    }
    if (tid == 0) {
        atomicAdd(&g_sum_disn, d1[0]);
        atomicAdd(&g_sum_min, d2[0]);
        __threadfence();
        unsigned old = atomicAdd(&g_done, 1u);
        if (old == 255u) {   // last of 256 blocks
            __threadfence();
            double sum_disn = atomicAdd(&g_sum_disn, 0.0);
            double sum_min  = atomicAdd(&g_sum_min, 0.0);
            double ent = atomicAdd(&g_ent, 0.0) / (double)NA;
            double kl  = atomicAdd(&g_kl, 0.0)  / (double)NA;
            double loss0 = fmin(ent*1e-4 + kl*1e-4, 2000.0);
            double ce = log1p(exp(loss0));
            double dis_norm = sum_disn / (double)NA;
            double dis_loss = -sum_min / (double)NA;
            double cdis = (dis_norm + dis_loss) / (double)NA;
            out[0] = (float)(ce + cdis);
            out[1] = (float)cdis;
            out[2] = (float)ce;
        }
    }
}

// ---------------- launcher ----------------
extern "C" void kernel_launch(void* const* d_in, const int* in_sizes, int n_in,
                              void* d_out, int out_size) {
    const float* obs  = (const float*)d_in[0];
    const float* hid  = (const float*)d_in[1];
    const float* eps  = (const float*)d_in[2];
    const float* eW1  = (const float*)d_in[3];
    const float* eb1  = (const float*)d_in[4];
    const float* eg   = (const float*)d_in[5];
    const float* ebt  = (const float*)d_in[6];
    const float* eW2  = (const float*)d_in[7];
    const float* eb2  = (const float*)d_in[8];
    const float* iW1  = (const float*)d_in[9];
    const float* ib1  = (const float*)d_in[10];
    const float* ig   = (const float*)d_in[11];
    const float* ibt  = (const float*)d_in[12];
    const float* iW2  = (const float*)d_in[13];
    const float* ib2  = (const float*)d_in[14];
    const float* dW1  = (const float*)d_in[15];
    const float* db1  = (const float*)d_in[16]; (void)db1; // cancels in BN
    const float* dg   = (const float*)d_in[17];
    const float* dbt  = (const float*)d_in[18];
    const float* dW2  = (const float*)d_in[19];
    const float* db2  = (const float*)d_in[20];
    float* out = (float*)d_out;

    k_lin<<<2*NA, 128>>>(obs, hid, eW1, eb1, iW1, ib1);
    k_bn<<<2, 1024>>>(eg, ebt, ig, ibt);
    k_lat<<<256, 256>>>(eW2, eb2, iW2, ib2, eps, dW1);
    k_col<<<dim3(64, 2), 512>>>(dg);
    k_midis<<<dim3(16, 16, 2), 256>>>(dbt, dW2, db2);
    k_sums<<<256, 256>>>(out);
}

// round 15
// speedup vs baseline: 3.3384x; 1.1410x over previous
#include <cuda_runtime.h>
#include <math.h>

#define NA   512
#define OBSD 128
#define INP  656
#define HID  64
#define LAT  256
#define NH   64
#define LOG2PI 1.8378770664093453f
#define BNEPS 1e-5f

typedef unsigned long long ull;

// ---------------- scratch (device globals; no allocation allowed) ----------------
// g_A/g_B/g_Ac/g_Bc/g_w1 are TRANSPOSED: [c][s] i.e. index c*NA + s
__device__ __align__(16) float g_pre_e[NA*NH];
__device__ __align__(16) float g_pre_i[NA*NH];
__device__ float g_scale[2][NH], g_shift[2][NH];
__device__ __align__(16) float g_mu[NA*LAT];
__device__ __align__(16) float g_ni2v[NA*LAT], g_cc[NA*LAT], g_lat[NA*LAT];
__device__ __align__(16) float g_A[NH*NA], g_B[NH*NA];
__device__ __align__(16) float g_Ac[NH*NA], g_Bc[NH*NA];
__device__ __align__(16) float g_w1[NH*NA];
__device__ float g_csA[NH], g_csB[NH], g_csS[NH];   // column stats (atomic)
__device__ __align__(16) float g_mi[NA*NA], g_dis[NA*NA];
__device__ double g_ent, g_kl, g_sum_disn, g_sum_min;
__device__ unsigned g_keymin[2], g_keymax[2];
__device__ unsigned g_done;

// ordered-uint encoding for float atomic min/max
__device__ __forceinline__ unsigned fkey(float f) {
    unsigned u = __float_as_uint(f);
    return (u & 0x80000000u) ? ~u : (u | 0x80000000u);
}
__device__ __forceinline__ float funkey(unsigned k) {
    unsigned u = (k & 0x80000000u) ? (k & 0x7fffffffu) : ~k;
    return __uint_as_float(u);
}

// ---- packed f32x2 helpers (sm_103a; only add/mul/fma exist packed) ----
__device__ __forceinline__ ull p2_add(ull a, ull b) {
    ull r; asm("add.rn.f32x2 %0,%1,%2;" : "=l"(r) : "l"(a), "l"(b)); return r;
}
__device__ __forceinline__ ull p2_mul(ull a, ull b) {
    ull r; asm("mul.rn.f32x2 %0,%1,%2;" : "=l"(r) : "l"(a), "l"(b)); return r;
}
__device__ __forceinline__ ull p2_fma(ull a, ull b, ull c) {
    ull r; asm("fma.rn.f32x2 %0,%1,%2,%3;" : "=l"(r) : "l"(a), "l"(b), "l"(c)); return r;
}
__device__ __forceinline__ ull p2_pack(float lo, float hi) {
    ull r; asm("mov.b64 %0,{%1,%2};" : "=l"(r) : "f"(lo), "f"(hi)); return r;
}
__device__ __forceinline__ float p2_lo(ull a) { return __uint_as_float((unsigned)a); }
__device__ __forceinline__ float p2_hi(ull a) { return __uint_as_float((unsigned)(a >> 32)); }
__device__ __forceinline__ ull lds_b64(const float* p) {
    return __double_as_longlong(*(const double*)p);
}

// ---------------- fused linear1 (encoder + inference), 1 row/block, 8-way split ----------------
__global__ void k_lin(const float* __restrict__ obs, const float* __restrict__ hid,
                      const float* __restrict__ eW1, const float* __restrict__ eb1,
                      const float* __restrict__ iW1, const float* __restrict__ ib1) {
    int b = blockIdx.x, t = threadIdx.x;   // 1024 blocks, 128 threads
    if (b == 0) {
        if (t == 0) {
            g_ent = 0.0; g_kl = 0.0; g_sum_disn = 0.0; g_sum_min = 0.0;
            g_keymin[0] = 0xFFFFFFFFu; g_keymin[1] = 0xFFFFFFFFu;
            g_keymax[0] = 0u; g_keymax[1] = 0u;
            g_done = 0u;
        }
        if (t < NH) { g_csA[t] = 0.f; g_csB[t] = 0.f; g_csS[t] = 0.f; }
    }
    __shared__ float s[HID + INP];
    __shared__ float part[8][NH];
    int g = t & 15, hh = t >> 4;   // 16 col-groups x 8 l-slices
    int c0 = g * 4;
    float4 acc = make_float4(0.f, 0.f, 0.f, 0.f);
    if (b < NA) {
        int i = b;
        if (t < 32) ((float4*)s)[t] = *(const float4*)(obs + i*INP + (INP-OBSD) + 4*t);
        __syncthreads();
        int l0 = hh * 16;
        #pragma unroll 16
        for (int l = l0; l < l0 + 16; l++) {
            float4 w = *(const float4*)&eW1[l*NH + c0];
            float x = s[l];
            acc.x = fmaf(x, w.x, acc.x); acc.y = fmaf(x, w.y, acc.y);
            acc.z = fmaf(x, w.z, acc.z); acc.w = fmaf(x, w.w, acc.w);
        }
        part[hh][c0+0] = acc.x; part[hh][c0+1] = acc.y;
        part[hh][c0+2] = acc.z; part[hh][c0+3] = acc.w;
        __syncthreads();
        if (t < NH) {
            float r = eb1[t];
            #pragma unroll
            for (int k = 0; k < 8; k++) r += part[k][t];
            g_pre_e[i*NH + t] = r;
        }
    } else {
        int i = b - NA;
        if (t < 16) ((float4*)s)[t] = ((const float4*)(hid + i*HID))[t];
        {
            const float4* o4 = (const float4*)(obs + i*INP);
            float4* s4 = (float4*)(s + HID);
            for (int l = t; l < INP/4; l += 128) s4[l] = o4[l];
        }
        __syncthreads();
        int l0 = hh * 90;
        #pragma unroll 10
        for (int l = l0; l < l0 + 90; l++) {
            float4 w = *(const float4*)&iW1[l*NH + c0];
            float x = s[l];
            acc.x = fmaf(x, w.x, acc.x); acc.y = fmaf(x, w.y, acc.y);
            acc.z = fmaf(x, w.z, acc.z); acc.w = fmaf(x, w.w, acc.w);
        }
        part[hh][c0+0] = acc.x; part[hh][c0+1] = acc.y;
        part[hh][c0+2] = acc.z; part[hh][c0+3] = acc.w;
        __syncthreads();
        if (t < NH) {
            float r = ib1[t];
            #pragma unroll
            for (int k = 0; k < 8; k++) r += part[k][t];
            g_pre_i[i*NH + t] = r;
        }
    }
}

// ---------------- fused BN stats (both tensors), single pass, coalesced ----------------
__global__ void k_bn(const float* __restrict__ eg, const float* __restrict__ ebt,
                     const float* __restrict__ ig, const float* __restrict__ ibt) {
    int which = blockIdx.x;    // 2 blocks, 1024 threads
    const float* pre = which ? g_pre_i : g_pre_e;
    const float* gm  = which ? ig  : eg;
    const float* bt  = which ? ibt : ebt;
    int t = threadIdx.x;
    int c = t & 63, rg = t >> 6;   // 16 row groups
    float s = 0.f, s2 = 0.f;
    for (int r = rg; r < NA; r += 16) {
        float x = pre[r*NH + c];
        s += x; s2 = fmaf(x, x, s2);
    }
    __shared__ float sh1[16][NH], sh2[16][NH];
    sh1[rg][c] = s; sh2[rg][c] = s2;
    __syncthreads();
    if (t < NH) {
        float a = 0.f, b = 0.f;
        #pragma unroll
        for (int k = 0; k < 16; k++) { a += sh1[k][t]; b += sh2[k][t]; }
        float mean = a * (1.f/NA);
        float var = b * (1.f/NA) - mean*mean;
        float sc = gm[t] * rsqrtf(var + BNEPS);
        g_scale[which][t] = sc;
        g_shift[which][t] = bt[t] - mean*sc;
    }
}

// ---------------- fused: enc linear2 + inf linear2 + latent head + entropy + KL + A/B GEMV + col stats ----------------
__global__ void k_lat(const float* __restrict__ eW2, const float* __restrict__ eb2,
                      const float* __restrict__ iW2, const float* __restrict__ ib2,
                      const float* __restrict__ eps, const float* __restrict__ dW1) {
    int i0 = blockIdx.x * 2, t = threadIdx.x;   // 256 blocks, 256 threads
    __shared__ float he[2][NH], hif[2][NH];
    __shared__ float sMuE[2][LAT], sMuI[2][LAT];
    __shared__ float sLat[2][LAT];
    __shared__ float red1[256], red2[256];
    __shared__ float pa[4][2][NH], pb[4][2][NH];
    {
        int g = (t >> 6) & 1, c = t & 63;
        if (t < 128) {
            float x = fmaf(g_pre_e[(i0+g)*NH + c], g_scale[0][c], g_shift[0][c]);
            he[g][c] = (x > 0.f) ? x : 0.01f*x;
        } else {
            float x = fmaf(g_pre_i[(i0+g)*NH + c], g_scale[1][c], g_shift[1][c]);
            hif[g][c] = (x > 0.f) ? x : 0.01f*x;
        }
    }
    __syncthreads();
    const int c0 = 2*t;
    float be0 = eb2[c0], be1 = eb2[c0+1];
    float bi0 = ib2[c0], bi1 = ib2[c0+1];
    float e00 = be0, e01 = be1, e10 = be0, e11 = be1;
    float i00 = bi0, i01 = bi1, i10 = bi0, i11 = bi1;
    #pragma unroll 8
    for (int l = 0; l < NH; l++) {
        float2 we = *(const float2*)&eW2[l*(2*LAT) + c0];
        float2 wi = *(const float2*)&iW2[l*(2*LAT) + c0];
        float h0 = he[0][l], h1 = he[1][l];
        float q0 = hif[0][l], q1 = hif[1][l];
        e00 = fmaf(h0, we.x, e00); e01 = fmaf(h0, we.y, e01);
        e10 = fmaf(h1, we.x, e10); e11 = fmaf(h1, we.y, e11);
        i00 = fmaf(q0, wi.x, i00); i01 = fmaf(q0, wi.y, i01);
        i10 = fmaf(q1, wi.x, i10); i11 = fmaf(q1, wi.y, i11);
    }
    if (t < 128) {
        sMuE[0][c0] = e00; sMuE[0][c0+1] = e01;
        sMuE[1][c0] = e10; sMuE[1][c0+1] = e11;
        sMuI[0][c0] = i00; sMuI[0][c0+1] = i01;
        sMuI[1][c0] = i10; sMuI[1][c0+1] = i11;
        *(float2*)&g_mu[i0*LAT + c0]     = make_float2(e00, e01);
        *(float2*)&g_mu[(i0+1)*LAT + c0] = make_float2(e10, e11);
    }
    __syncthreads();
    float ent = 0.f, kl = 0.f;
    if (t >= 128) {
        const int li = c0 - LAT;
        float eA0[2] = {e00, e10}, eA1[2] = {e01, e11};
        float iA0[2] = {i00, i10}, iA1[2] = {i01, i11};
        #pragma unroll
        for (int g = 0; g < 2; g++) {
            int gi = (i0+g)*LAT + li;
            float v0 = fmaxf(expf(eA0[g]), 0.002f);
            float v1 = fmaxf(expf(eA1[g]), 0.002f);
            float ls0 = 0.5f*logf(v0), ls1 = 0.5f*logf(v1);
            float mu0 = sMuE[g][li], mu1 = sMuE[g][li+1];
            *(float2*)&g_ni2v[gi] = make_float2(-0.5f/v0, -0.5f/v1);
            *(float2*)&g_cc[gi]   = make_float2(13.9f - ls0 - 0.5f*LOG2PI,
                                                13.9f - ls1 - 0.5f*LOG2PI);
            float2 e2 = *(const float2*)&eps[gi];
            float l0v = fmaf(sqrtf(v0), e2.x, mu0);
            float l1v = fmaf(sqrtf(v1), e2.y, mu1);
            *(float2*)&g_lat[gi] = make_float2(l0v, l1v);
            sLat[g][li] = l0v; sLat[g][li+1] = l1v;
            ent += 1.f + LOG2PI + ls0 + ls1;
            float vq0 = fmaxf(expf(iA0[g]), 0.002f);
            float vq1 = fmaxf(expf(iA1[g]), 0.002f);
            float lsq0 = 0.5f*logf(vq0), lsq1 = 0.5f*logf(vq1);
            float d0 = mu0 - sMuI[g][li];
            float d1 = mu1 - sMuI[g][li+1];
            kl += (lsq0 - ls0 + (v0 + d0*d0) / (2.f*vq0) - 0.5f)
                + (lsq1 - ls1 + (v1 + d1*d1) / (2.f*vq1) - 0.5f);
        }
    }
    red1[t] = ent; red2[t] = kl;
    __syncthreads();
    for (int o = 128; o; o >>= 1) {
        if (t < o) { red1[t] += red1[t+o]; red2[t] += red2[t+o]; }
        __syncthreads();
    }
    if (t == 0) { atomicAdd(&g_ent, (double)red1[0]); atomicAdd(&g_kl, (double)red2[0]); }
    __syncthreads();   // sLat fully written before GEMV reads it
    // ---- A/B GEMV on the latent already in smem ----
    const int c = t & 63, q = t >> 6;
    float a0 = 0.f, b0 = 0.f, a1 = 0.f, b1 = 0.f;
    const int l0 = q * 64;
    #pragma unroll 8
    for (int l = l0; l < l0 + 64; l++) {
        float wa = dW1[l*NH + c];
        float wb = dW1[(l + LAT)*NH + c];
        float L0 = sLat[0][l], L1 = sLat[1][l];
        a0 = fmaf(L0, wa, a0); b0 = fmaf(L0, wb, b0);
        a1 = fmaf(L1, wa, a1); b1 = fmaf(L1, wb, b1);
    }
    pa[q][0][c] = a0; pa[q][1][c] = a1;
    pb[q][0][c] = b0; pb[q][1][c] = b1;
    __syncthreads();
    if (t < 128) {
        int g = t >> 6, c2 = t & 63;
        float av = pa[0][g][c2] + pa[1][g][c2] + pa[2][g][c2] + pa[3][g][c2];
        float bv = pb[0][g][c2] + pb[1][g][c2] + pb[2][g][c2] + pb[3][g][c2];
        g_A[c2*NA + i0+g] = av;
        g_B[c2*NA + i0+g] = bv;
        atomicAdd(&g_csA[c2], av);
        atomicAdd(&g_csB[c2], bv);
        atomicAdd(&g_csS[c2], av*av + bv*bv);
    }
}

// ---------------- fused: center (to g_Ac/g_Bc) + circ-corr -> w1 (stats precomputed) ----------------
// grid (64 columns, 2 s-halves), 512 threads
__global__ void k_col(const float* __restrict__ dg) {
    int c = blockIdx.x, sh = blockIdx.y;
    int t = threadIdx.x;
    __shared__ float a[NA], b2[2*NA];
    __shared__ float part0[512], part1[512];
    float mA = g_csA[c] * (1.f/NA);
    float mB = g_csB[c] * (1.f/NA);
    float s2 = g_csS[c] * (1.f/NA) - mA*mA - mB*mB;
    float av = g_A[c*NA + t] - mA, bv = g_B[c*NA + t] - mB;
    a[t] = av; b2[t] = bv; b2[t + NA] = bv;
    if (sh == 0) { g_Ac[c*NA + t] = av; g_Bc[c*NA + t] = bv; }
    __syncthreads();
    // cr(s) = sum_j a[j]*b2[511-s+j]; 2 s per thread with sliding carry
    const int sq = t & 127, jh = t >> 7;
    const int s0 = sh*256 + 2*sq;
    const int jbase = jh * 128;
    const float* ap = &a[jbase];
    const float* bp = &b2[510 - s0 + jbase];
    float cr0 = 0.f, cr1 = 0.f;
    float wprev = bp[0];
    #pragma unroll 8
    for (int j = 0; j < 128; j++) {
        float wnew = bp[j + 1];
        float aj = ap[j];
        cr0 = fmaf(aj, wnew, cr0);
        cr1 = fmaf(aj, wprev, cr1);
        wprev = wnew;
    }
    part0[t] = cr0; part1[t] = cr1;
    __syncthreads();
    if (t < 128) {
        float c0 = part0[t] + part0[t+128] + part0[t+256] + part0[t+384];
        float c1 = part1[t] + part1[t+128] + part1[t+256] + part1[t+384];
        int ss0 = sh*256 + 2*t;
        float var0 = s2 + 2.f * c0 * (1.f/NA);
        float var1 = s2 + 2.f * c1 * (1.f/NA);
        float scale = dg[c];
        *(float2*)&g_w1[c*NA + ss0] = make_float2(scale * rsqrtf(var0 + BNEPS),
                                                  scale * rsqrtf(var1 + BNEPS));
    }
}

// ---------------- fused MI (z=0) + DIS (z=1): 32j x 64s tiles, 2jx4s per thread ----------------
// grid dim3(16, 8, 2), 256 threads
__global__ void k_midis(const float* __restrict__ dbt,
                        const float* __restrict__ dW2,
                        const float* __restrict__ db2) {
    __shared__ float sh[6528];
    const int tid = threadIdx.x;            // 256
    const int j0 = blockIdx.x * 32, s0 = blockIdx.y * 64;
    const int tx = tid & 15, ty = tid >> 4;
    const int jj0 = 2*tx, ss0 = 4*ty;
    const int base = (j0 - s0 - 64) & (NA-1);
    const int w0 = jj0 - ss0 + 60;          // even, in [0,90]; window rows w0..w0+5
    float vmn, vmx;
    if (blockIdx.z == 0) {
        // ---- MI: packed f32x2 over the j-pair, scalar max ----
        float* sNM = sh;            // [32 l][34]  (-mu)
        float* sNI = sh + 1088;     // [32 l][34]
        float* sCC = sh + 2176;     // [32 l][34]
        float* sL  = sh + 3264;     // [32 l][98]  (96 rows + pad)
        float accL[4] = {0.f,0.f,0.f,0.f}, accH[4] = {0.f,0.f,0.f,0.f};
        for (int l0 = 0; l0 < LAT; l0 += 32) {
            #pragma unroll
            for (int i = 0; i < 4; i++) {
                int idx = tid + i*256;
                int jj = idx >> 5, lc = idx & 31;
                int g = (j0 + jj)*LAT + l0 + lc;
                sNM[lc*34 + jj] = -g_mu[g];
                sNI[lc*34 + jj] = g_ni2v[g];
                sCC[lc*34 + jj] = g_cc[g];
            }
            #pragma unroll
            for (int i = 0; i < 12; i++) {
                int idx = tid + i*256;
                int rr = idx >> 5, lc = idx & 31;
                sL[lc*98 + rr] = g_lat[((base + rr) & (NA-1))*LAT + l0 + lc];
            }
            __syncthreads();
            #pragma unroll
            for (int l = 0; l < 32; l++) {
                ull nm2 = lds_b64(&sNM[l*34 + jj0]);
                ull ni2 = lds_b64(&sNI[l*34 + jj0]);
                ull cc2 = lds_b64(&sCC[l*34 + jj0]);
                float2 L01 = *(const float2*)&sL[l*98 + w0];
                float2 L23 = *(const float2*)&sL[l*98 + w0 + 2];
                float2 L45 = *(const float2*)&sL[l*98 + w0 + 4];
                // pairs {Lw[3-a], Lw[4-a]}:
                ull P[4];
                P[0] = p2_pack(L23.y, L45.x);   // a=0: (3,4)
                P[1] = p2_pack(L23.x, L23.y);   // a=1: (2,3)
                P[2] = p2_pack(L01.y, L23.x);   // a=2: (1,2)
                P[3] = p2_pack(L01.x, L01.y);   // a=3: (0,1)
                #pragma unroll
                for (int a = 0; a < 4; a++) {
                    ull d = p2_add(P[a], nm2);
                    ull q = p2_mul(d, d);
                    ull r = p2_fma(q, ni2, cc2);
                    accL[a] += fmaxf(p2_lo(r), -13.9f);
                    accH[a] += fmaxf(p2_hi(r), -13.9f);
                }
            }
            __syncthreads();
        }
        const float inv = 1.f / LAT;
        float o[4][2];
        #pragma unroll
        for (int a = 0; a < 4; a++) {
            o[a][0] = accL[a]*inv; o[a][1] = accH[a]*inv;
            *(float2*)&g_mi[(s0+ss0+a)*NA + j0+jj0] = make_float2(o[a][0], o[a][1]);
        }
        vmn = o[0][0]; vmx = o[0][0];
        #pragma unroll
        for (int a = 0; a < 4; a++) {
            vmn = fminf(vmn, fminf(o[a][0], o[a][1]));
            vmx = fmaxf(vmx, fmaxf(o[a][0], o[a][1]));
        }
    } else {
        // ---- DIS: scalar, c-chunked (2 chunks of 32) ----
        float* sa   = sh;            // [32 c][34]
        float* sw   = sh + 1088;     // [32 c][68]
        float* sb   = sh + 3264;     // [32 c][98]
        float* sdbt = sh + 6400;     // 64
        float* sdw2 = sh + 6464;     // 64
        if (tid < NH) { sdbt[tid] = dbt[tid]; sdw2[tid] = dW2[tid]; }
        float acc[4][2] = {{0.f,0.f},{0.f,0.f},{0.f,0.f},{0.f,0.f}};
        for (int cb = 0; cb < NH; cb += 32) {
            #pragma unroll
            for (int i = 0; i < 4; i++) {
                int idx = tid + i*256;
                int cc = idx >> 5, jj = idx & 31;
                sa[cc*34 + jj] = g_Ac[(cb+cc)*NA + j0 + jj];
            }
            #pragma unroll
            for (int i = 0; i < 8; i++) {
                int idx = tid + i*256;
                int cc = idx >> 6, ss = idx & 63;
                sw[cc*68 + ss] = g_w1[(cb+cc)*NA + s0 + ss];
            }
            #pragma unroll
            for (int i = 0; i < 16; i++) {
                int idx = tid + i*256;
                int cc = idx >> 7, rr = idx & 127;
                if (rr < 96)
                    sb[cc*98 + rr] = g_Bc[(cb+cc)*NA + ((base + rr) & (NA-1))];
            }
            __syncthreads();
            #pragma unroll 4
            for (int cc = 0; cc < 32; cc++) {
                float2 a2 = *(const float2*)&sa[cc*34 + jj0];
                float4 w4 = *(const float4*)&sw[cc*68 + ss0];
                float2 B01 = *(const float2*)&sb[cc*98 + w0];
                float2 B23 = *(const float2*)&sb[cc*98 + w0 + 2];
                float2 B45 = *(const float2*)&sb[cc*98 + w0 + 4];
                float Bw[5] = {B01.x, B01.y, B23.x, B23.y, B45.x};
                float bt = sdbt[cb+cc], w2 = sdw2[cb+cc];
                float wa[4] = {w4.x, w4.y, w4.z, w4.w};
                float aj[2] = {a2.x, a2.y};
                #pragma unroll
                for (int a = 0; a < 4; a++) {
                    #pragma unroll
                    for (int bb = 0; bb < 2; bb++) {
                        float u = fmaf(aj[bb] + Bw[3 + bb - a], wa[a], bt);
                        u = fmaxf(u, 0.01f*u);   // leaky relu
                        acc[a][bb] = fmaf(u, w2, acc[a][bb]);
                    }
                }
            }
            __syncthreads();
        }
        float b2v = db2[0];
        float o[4][2];
        #pragma unroll
        for (int a = 0; a < 4; a++) {
            o[a][0] = fabsf(acc[a][0] + b2v);
            o[a][1] = fabsf(acc[a][1] + b2v);
            *(float2*)&g_dis[(s0+ss0+a)*NA + j0+jj0] = make_float2(o[a][0], o[a][1]);
        }
        vmn = o[0][0]; vmx = o[0][0];
        #pragma unroll
        for (int a = 0; a < 4; a++) {
            vmn = fminf(vmn, fminf(o[a][0], o[a][1]));
            vmx = fmaxf(vmx, fmaxf(o[a][0], o[a][1]));
        }
    }
    // ---- block min/max -> global atomic keys ----
    #pragma unroll
    for (int o2 = 16; o2; o2 >>= 1) {
        vmn = fminf(vmn, __shfl_xor_sync(0xFFFFFFFFu, vmn, o2));
        vmx = fmaxf(vmx, __shfl_xor_sync(0xFFFFFFFFu, vmx, o2));
    }
    __shared__ float wmn[8], wmx[8];
    if ((tid & 31) == 0) { wmn[tid>>5] = vmn; wmx[tid>>5] = vmx; }
    __syncthreads();
    if (tid == 0) {
        float a = wmn[0], b = wmx[0];
        #pragma unroll
        for (int k = 1; k < 8; k++) { a = fminf(a, wmn[k]); b = fmaxf(b, wmx[k]); }
        atomicMin(&g_keymin[blockIdx.z], fkey(a));
        atomicMax(&g_keymax[blockIdx.z], fkey(b));
    }
}

// ---------------- normalized sums + last-block final assembly ----------------
__global__ void k_sums(float* __restrict__ out) {
    int tid = threadIdx.x;
    int base = blockIdx.x * 1024;
    float mi_min = funkey(g_keymin[0]);
    float mi_inv = 1.f / (funkey(g_keymax[0]) - mi_min + 1e-12f);
    float ds_min = funkey(g_keymin[1]);
    float ds_inv = 1.f / (funkey(g_keymax[1]) - ds_min + 1e-12f);
    double s1 = 0.0, s2 = 0.0;
    #pragma unroll
    for (int i = 0; i < 4; i++) {
        int idx = base + tid + i*256;
        float mi_n = (g_mi[idx] - mi_min) * mi_inv;
        float ds_n = (g_dis[idx] - ds_min) * ds_inv;
        s1 += (double)ds_n;
        s2 += (double)fminf(mi_n + ds_n, 1.0f);
    }
    __shared__ double d1[256], d2[256];
    d1[tid] = s1; d2[tid] = s2;
    __syncthreads();
    for (int o = 128; o; o >>= 1) {
        if (tid < o) { d1[tid] += d1[tid+o]; d2[tid] += d2[tid+o]; }
        __syncthreads();
    }
    if (tid == 0) {
        atomicAdd(&g_sum_disn, d1[0]);
        atomicAdd(&g_sum_min, d2[0]);
        __threadfence();
        unsigned old = atomicAdd(&g_done, 1u);
        if (old == 255u) {
            __threadfence();
            double sum_disn = atomicAdd(&g_sum_disn, 0.0);
            double sum_min  = atomicAdd(&g_sum_min, 0.0);
            double ent = atomicAdd(&g_ent, 0.0) / (double)NA;
            double kl  = atomicAdd(&g_kl, 0.0)  / (double)NA;
            double loss0 = fmin(ent*1e-4 + kl*1e-4, 2000.0);
            double ce = log1p(exp(loss0));
            double dis_norm = sum_disn / (double)NA;
            double dis_loss = -sum_min / (double)NA;
            double cdis = (dis_norm + dis_loss) / (double)NA;
            out[0] = (float)(ce + cdis);
            out[1] = (float)cdis;
            out[2] = (float)ce;
        }
    }
}

// ---------------- launcher ----------------
extern "C" void kernel_launch(void* const* d_in, const int* in_sizes, int n_in,
                              void* d_out, int out_size) {
    const float* obs  = (const float*)d_in[0];
    const float* hid  = (const float*)d_in[1];
    const float* eps  = (const float*)d_in[2];
    const float* eW1  = (const float*)d_in[3];
    const float* eb1  = (const float*)d_in[4];
    const float* eg   = (const float*)d_in[5];
    const float* ebt  = (const float*)d_in[6];
    const float* eW2  = (const float*)d_in[7];
    const float* eb2  = (const float*)d_in[8];
    const float* iW1  = (const float*)d_in[9];
    const float* ib1  = (const float*)d_in[10];
    const float* ig   = (const float*)d_in[11];
    const float* ibt  = (const float*)d_in[12];
    const float* iW2  = (const float*)d_in[13];
    const float* ib2  = (const float*)d_in[14];
    const float* dW1  = (const float*)d_in[15];
    const float* db1  = (const float*)d_in[16]; (void)db1; // cancels in BN
    const float* dg   = (const float*)d_in[17];
    const float* dbt  = (const float*)d_in[18];
    const float* dW2  = (const float*)d_in[19];
    const float* db2  = (const float*)d_in[20];
    float* out = (float*)d_out;

    k_lin<<<2*NA, 128>>>(obs, hid, eW1, eb1, iW1, ib1);
    k_bn<<<2, 1024>>>(eg, ebt, ig, ibt);
    k_lat<<<256, 256>>>(eW2, eb2, iW2, ib2, eps, dW1);
    k_col<<<dim3(64, 2), 512>>>(dg);
    k_midis<<<dim3(16, 8, 2), 256>>>(dbt, dW2, db2);
    k_sums<<<256, 256>>>(out);
}

// round 16
// speedup vs baseline: 3.6671x; 1.0985x over previous
#include <cuda_runtime.h>
#include <math.h>

#define NA   512
#define OBSD 128
#define INP  656
#define HID  64
#define LAT  256
#define NH   64
#define LOG2PI 1.8378770664093453f
#define BNEPS 1e-5f

typedef unsigned long long ull;

// ---------------- scratch (device globals; no allocation allowed) ----------------
// g_A/g_B/g_Ac/g_Bc/g_w1 are TRANSPOSED: [c][s] i.e. index c*NA + s
__device__ __align__(16) float g_pre_e[NA*NH];
__device__ __align__(16) float g_pre_i[NA*NH];
__device__ float g_scale[2][NH], g_shift[2][NH];
__device__ __align__(16) float g_mu[NA*LAT];
__device__ __align__(16) float g_ni2v[NA*LAT], g_cc[NA*LAT], g_lat[NA*LAT];
__device__ __align__(16) float g_A[NH*NA], g_B[NH*NA];
__device__ __align__(16) float g_Ac[NH*NA], g_Bc[NH*NA];
__device__ __align__(16) float g_w1[NH*NA];
__device__ float g_csA[NH], g_csB[NH], g_csS[NH];   // column stats (atomic)
__device__ __align__(16) float g_mi[NA*NA], g_dis[NA*NA];
__device__ double g_ent, g_kl, g_sum_disn, g_sum_min;
__device__ unsigned g_keymin[2], g_keymax[2];
__device__ unsigned g_done;

// ordered-uint encoding for float atomic min/max
__device__ __forceinline__ unsigned fkey(float f) {
    unsigned u = __float_as_uint(f);
    return (u & 0x80000000u) ? ~u : (u | 0x80000000u);
}
__device__ __forceinline__ float funkey(unsigned k) {
    unsigned u = (k & 0x80000000u) ? (k & 0x7fffffffu) : ~k;
    return __uint_as_float(u);
}

// ---- packed f32x2 helpers (sm_103a; only add/mul/fma exist packed) ----
__device__ __forceinline__ ull p2_add(ull a, ull b) {
    ull r; asm("add.rn.f32x2 %0,%1,%2;" : "=l"(r) : "l"(a), "l"(b)); return r;
}
__device__ __forceinline__ ull p2_mul(ull a, ull b) {
    ull r; asm("mul.rn.f32x2 %0,%1,%2;" : "=l"(r) : "l"(a), "l"(b)); return r;
}
__device__ __forceinline__ ull p2_fma(ull a, ull b, ull c) {
    ull r; asm("fma.rn.f32x2 %0,%1,%2,%3;" : "=l"(r) : "l"(a), "l"(b), "l"(c)); return r;
}
__device__ __forceinline__ ull p2_pack(float lo, float hi) {
    ull r; asm("mov.b64 %0,{%1,%2};" : "=l"(r) : "f"(lo), "f"(hi)); return r;
}
__device__ __forceinline__ float p2_lo(ull a) { return __uint_as_float((unsigned)a); }
__device__ __forceinline__ float p2_hi(ull a) { return __uint_as_float((unsigned)(a >> 32)); }
__device__ __forceinline__ ull lds_b64(const float* p) {
    return __double_as_longlong(*(const double*)p);
}

// ---------------- fused linear1 (encoder + inference), 1 row/block, 8-way split ----------------
__global__ void k_lin(const float* __restrict__ obs, const float* __restrict__ hid,
                      const float* __restrict__ eW1, const float* __restrict__ eb1,
                      const float* __restrict__ iW1, const float* __restrict__ ib1) {
    int b = blockIdx.x, t = threadIdx.x;   // 1024 blocks, 128 threads
    if (b == 0) {
        if (t == 0) {
            g_ent = 0.0; g_kl = 0.0; g_sum_disn = 0.0; g_sum_min = 0.0;
            g_keymin[0] = 0xFFFFFFFFu; g_keymin[1] = 0xFFFFFFFFu;
            g_keymax[0] = 0u; g_keymax[1] = 0u;
            g_done = 0u;
        }
        if (t < NH) { g_csA[t] = 0.f; g_csB[t] = 0.f; g_csS[t] = 0.f; }
    }
    __shared__ float s[HID + INP];
    __shared__ float part[8][NH];
    int g = t & 15, hh = t >> 4;   // 16 col-groups x 8 l-slices
    int c0 = g * 4;
    float4 acc = make_float4(0.f, 0.f, 0.f, 0.f);
    if (b < NA) {
        int i = b;
        if (t < 32) ((float4*)s)[t] = *(const float4*)(obs + i*INP + (INP-OBSD) + 4*t);
        __syncthreads();
        int l0 = hh * 16;
        #pragma unroll 16
        for (int l = l0; l < l0 + 16; l++) {
            float4 w = *(const float4*)&eW1[l*NH + c0];
            float x = s[l];
            acc.x = fmaf(x, w.x, acc.x); acc.y = fmaf(x, w.y, acc.y);
            acc.z = fmaf(x, w.z, acc.z); acc.w = fmaf(x, w.w, acc.w);
        }
        part[hh][c0+0] = acc.x; part[hh][c0+1] = acc.y;
        part[hh][c0+2] = acc.z; part[hh][c0+3] = acc.w;
        __syncthreads();
        if (t < NH) {
            float r = eb1[t];
            #pragma unroll
            for (int k = 0; k < 8; k++) r += part[k][t];
            g_pre_e[i*NH + t] = r;
        }
    } else {
        int i = b - NA;
        if (t < 16) ((float4*)s)[t] = ((const float4*)(hid + i*HID))[t];
        {
            const float4* o4 = (const float4*)(obs + i*INP);
            float4* s4 = (float4*)(s + HID);
            for (int l = t; l < INP/4; l += 128) s4[l] = o4[l];
        }
        __syncthreads();
        int l0 = hh * 90;
        #pragma unroll 10
        for (int l = l0; l < l0 + 90; l++) {
            float4 w = *(const float4*)&iW1[l*NH + c0];
            float x = s[l];
            acc.x = fmaf(x, w.x, acc.x); acc.y = fmaf(x, w.y, acc.y);
            acc.z = fmaf(x, w.z, acc.z); acc.w = fmaf(x, w.w, acc.w);
        }
        part[hh][c0+0] = acc.x; part[hh][c0+1] = acc.y;
        part[hh][c0+2] = acc.z; part[hh][c0+3] = acc.w;
        __syncthreads();
        if (t < NH) {
            float r = ib1[t];
            #pragma unroll
            for (int k = 0; k < 8; k++) r += part[k][t];
            g_pre_i[i*NH + t] = r;
        }
    }
}

// ---------------- fused BN stats (both tensors), single pass, coalesced ----------------
__global__ void k_bn(const float* __restrict__ eg, const float* __restrict__ ebt,
                     const float* __restrict__ ig, const float* __restrict__ ibt) {
    int which = blockIdx.x;    // 2 blocks, 1024 threads
    const float* pre = which ? g_pre_i : g_pre_e;
    const float* gm  = which ? ig  : eg;
    const float* bt  = which ? ibt : ebt;
    int t = threadIdx.x;
    int c = t & 63, rg = t >> 6;   // 16 row groups
    float s = 0.f, s2 = 0.f;
    for (int r = rg; r < NA; r += 16) {
        float x = pre[r*NH + c];
        s += x; s2 = fmaf(x, x, s2);
    }
    __shared__ float sh1[16][NH], sh2[16][NH];
    sh1[rg][c] = s; sh2[rg][c] = s2;
    __syncthreads();
    if (t < NH) {
        float a = 0.f, b = 0.f;
        #pragma unroll
        for (int k = 0; k < 16; k++) { a += sh1[k][t]; b += sh2[k][t]; }
        float mean = a * (1.f/NA);
        float var = b * (1.f/NA) - mean*mean;
        float sc = gm[t] * rsqrtf(var + BNEPS);
        g_scale[which][t] = sc;
        g_shift[which][t] = bt[t] - mean*sc;
    }
}

// ---------------- fused: enc linear2 + inf linear2 + latent head + entropy + KL + A/B GEMV + col stats ----------------
// 256 blocks x 256 threads, 2 rows/block. Thread roles:
//   t in [0,64):    encoder, cols 4t..4t+3        (mu region)
//   t in [64,128):  encoder, cols 4t..4t+3        (logvar region)
//   t in [128,192): inference, cols 4(t-128)..+3  (mu region)
//   t in [192,256): inference, cols 4(t-128)..+3  (logvar region)
__global__ void k_lat(const float* __restrict__ eW2, const float* __restrict__ eb2,
                      const float* __restrict__ iW2, const float* __restrict__ ib2,
                      const float* __restrict__ eps, const float* __restrict__ dW1) {
    int i0 = blockIdx.x * 2, t = threadIdx.x;
    __shared__ float he[2][NH], hif[2][NH];
    __shared__ float sMuE[2][LAT], sMuI[2][LAT];
    __shared__ float sVarE[2][LAT], sLsE[2][LAT];
    __shared__ float sLat[2][LAT];
    __shared__ float red1[256], red2[256];
    __shared__ float pa[4][2][NH], pb[4][2][NH];
    {
        int g = (t >> 6) & 1, c = t & 63;
        if (t < 128) {
            float x = fmaf(g_pre_e[(i0+g)*NH + c], g_scale[0][c], g_shift[0][c]);
            he[g][c] = (x > 0.f) ? x : 0.01f*x;
        } else {
            float x = fmaf(g_pre_i[(i0+g)*NH + c], g_scale[1][c], g_shift[1][c]);
            hif[g][c] = (x > 0.f) ? x : 0.01f*x;
        }
    }
    __syncthreads();
    const bool isE = (t < 128);
    const int c0 = isE ? 4*t : 4*(t-128);           // column base within 2*LAT
    const float* __restrict__ W = isE ? eW2 : iW2;
    const float* __restrict__ Bv = isE ? eb2 : ib2;
    float4 bq = *(const float4*)&Bv[c0];
    float4 a0 = bq, a1 = bq;                         // rows g=0,1
    {
        const float (*h)[NH] = isE ? he : hif;
        #pragma unroll 8
        for (int l = 0; l < NH; l++) {
            float4 w = *(const float4*)&W[l*(2*LAT) + c0];
            float h0 = h[0][l], h1 = h[1][l];
            a0.x = fmaf(h0, w.x, a0.x); a0.y = fmaf(h0, w.y, a0.y);
            a0.z = fmaf(h0, w.z, a0.z); a0.w = fmaf(h0, w.w, a0.w);
            a1.x = fmaf(h1, w.x, a1.x); a1.y = fmaf(h1, w.y, a1.y);
            a1.z = fmaf(h1, w.z, a1.z); a1.w = fmaf(h1, w.w, a1.w);
        }
    }
    // phase 2: stash mu
    if (t < 64) {
        *(float4*)&sMuE[0][c0] = a0;
        *(float4*)&sMuE[1][c0] = a1;
        *(float4*)&g_mu[i0*LAT + c0]     = a0;
        *(float4*)&g_mu[(i0+1)*LAT + c0] = a1;
    } else if (t >= 128 && t < 192) {
        *(float4*)&sMuI[0][c0] = a0;
        *(float4*)&sMuI[1][c0] = a1;
    }
    float ent = 0.f, kl = 0.f;
    // encoder logvar threads: head stats (no mu needed yet)
    if (isE && t >= 64) {
        const int li = c0 - LAT;   // [0,252]
        float lv[2][4] = {{a0.x,a0.y,a0.z,a0.w},{a1.x,a1.y,a1.z,a1.w}};
        #pragma unroll
        for (int g = 0; g < 2; g++) {
            float4 vv, ls, ni, cc;
            float* vvp = (float*)&vv; float* lsp = (float*)&ls;
            float* nip = (float*)&ni; float* ccp = (float*)&cc;
            #pragma unroll
            for (int k = 0; k < 4; k++) {
                float v = fmaxf(expf(lv[g][k]), 0.002f);
                float l = 0.5f*logf(v);
                vvp[k] = v; lsp[k] = l;
                nip[k] = -0.5f/v;
                ccp[k] = 13.9f - l - 0.5f*LOG2PI;
                ent += 0.5f + 0.5f*LOG2PI + l;
            }
            int gi = (i0+g)*LAT + li;
            *(float4*)&g_ni2v[gi] = ni;
            *(float4*)&g_cc[gi]   = cc;
            *(float4*)&sVarE[g][li] = vv;
            *(float4*)&sLsE[g][li]  = ls;
        }
    }
    __syncthreads();
    // phase 3: latent (needs mu) + KL (needs var/ls/muE/muI)
    if (isE && t >= 64) {
        const int li = c0 - LAT;
        #pragma unroll
        for (int g = 0; g < 2; g++) {
            int gi = (i0+g)*LAT + li;
            float4 mu = *(const float4*)&sMuE[g][li];
            float4 vv = *(const float4*)&sVarE[g][li];
            float4 e4 = *(const float4*)&eps[gi];
            float4 lt;
            lt.x = fmaf(sqrtf(vv.x), e4.x, mu.x);
            lt.y = fmaf(sqrtf(vv.y), e4.y, mu.y);
            lt.z = fmaf(sqrtf(vv.z), e4.z, mu.z);
            lt.w = fmaf(sqrtf(vv.w), e4.w, mu.w);
            *(float4*)&g_lat[gi] = lt;
            *(float4*)&sLat[g][li] = lt;
        }
    } else if (!isE && t >= 192) {
        const int li = c0 - LAT;
        float lv[2][4] = {{a0.x,a0.y,a0.z,a0.w},{a1.x,a1.y,a1.z,a1.w}};
        #pragma unroll
        for (int g = 0; g < 2; g++) {
            float4 mu  = *(const float4*)&sMuE[g][li];
            float4 muq = *(const float4*)&sMuI[g][li];
            float4 vv  = *(const float4*)&sVarE[g][li];
            float4 ls  = *(const float4*)&sLsE[g][li];
            const float* mup = (const float*)&mu; const float* muqp = (const float*)&muq;
            const float* vvp = (const float*)&vv; const float* lsp = (const float*)&ls;
            #pragma unroll
            for (int k = 0; k < 4; k++) {
                float vq = fmaxf(expf(lv[g][k]), 0.002f);
                float lsq = 0.5f*logf(vq);
                float d = mup[k] - muqp[k];
                kl += lsq - lsp[k] + (vvp[k] + d*d) / (2.f*vq) - 0.5f;
            }
        }
    }
    red1[t] = ent; red2[t] = kl;
    __syncthreads();
    for (int o = 128; o; o >>= 1) {
        if (t < o) { red1[t] += red1[t+o]; red2[t] += red2[t+o]; }
        __syncthreads();
    }
    if (t == 0) { atomicAdd(&g_ent, (double)red1[0]); atomicAdd(&g_kl, (double)red2[0]); }
    __syncthreads();
    // ---- A/B GEMV on the latent already in smem ----
    const int c = t & 63, q = t >> 6;
    float b0 = 0.f, b1 = 0.f, aa0 = 0.f, aa1 = 0.f;
    const int l0 = q * 64;
    #pragma unroll 8
    for (int l = l0; l < l0 + 64; l++) {
        float wa = dW1[l*NH + c];
        float wb = dW1[(l + LAT)*NH + c];
        float L0 = sLat[0][l], L1 = sLat[1][l];
        aa0 = fmaf(L0, wa, aa0); b0 = fmaf(L0, wb, b0);
        aa1 = fmaf(L1, wa, aa1); b1 = fmaf(L1, wb, b1);
    }
    pa[q][0][c] = aa0; pa[q][1][c] = aa1;
    pb[q][0][c] = b0; pb[q][1][c] = b1;
    __syncthreads();
    if (t < 128) {
        int g = t >> 6, c2 = t & 63;
        float av = pa[0][g][c2] + pa[1][g][c2] + pa[2][g][c2] + pa[3][g][c2];
        float bv = pb[0][g][c2] + pb[1][g][c2] + pb[2][g][c2] + pb[3][g][c2];
        g_A[c2*NA + i0+g] = av;
        g_B[c2*NA + i0+g] = bv;
        atomicAdd(&g_csA[c2], av);
        atomicAdd(&g_csB[c2], bv);
        atomicAdd(&g_csS[c2], av*av + bv*bv);
    }
}

// ---------------- fused: center (to g_Ac/g_Bc) + circ-corr -> w1 (stats precomputed) ----------------
// grid (64 columns, 2 s-halves), 512 threads; float2 conflict-free correlation loop
__global__ void k_col(const float* __restrict__ dg) {
    int c = blockIdx.x, sh = blockIdx.y;
    int t = threadIdx.x;
    __shared__ float a[NA], b2[2*NA];
    __shared__ float part0[512], part1[512];
    float mA = g_csA[c] * (1.f/NA);
    float mB = g_csB[c] * (1.f/NA);
    float s2 = g_csS[c] * (1.f/NA) - mA*mA - mB*mB;
    float av = g_A[c*NA + t] - mA, bv = g_B[c*NA + t] - mB;
    a[t] = av; b2[t] = bv; b2[t + NA] = bv;
    if (sh == 0) { g_Ac[c*NA + t] = av; g_Bc[c*NA + t] = bv; }
    __syncthreads();
    // cr0(s0):   sum_j a[j]*b2[511-s0+j]
    // cr1(s0+1): sum_j a[j]*b2[510-s0+j]
    // base e = 510-s0+jbase is even -> float2 aligned, lane-consecutive 8B -> conflict-free
    const int sq = t & 127, jh = t >> 7;
    const int s0 = sh*256 + 2*sq;
    const int jbase = jh * 128;
    const float2* ap2 = (const float2*)&a[jbase];
    const float2* bp2 = (const float2*)&b2[510 - s0 + jbase];
    float cr0 = 0.f, cr1 = 0.f;
    float2 cur = bp2[0];
    #pragma unroll 8
    for (int k = 0; k < 64; k++) {
        float2 nxt = bp2[k + 1];
        float2 a2 = ap2[k];
        cr1 = fmaf(a2.x, cur.x, cr1);
        cr0 = fmaf(a2.x, cur.y, cr0);
        cr1 = fmaf(a2.y, cur.y, cr1);
        cr0 = fmaf(a2.y, nxt.x, cr0);
        cur = nxt;
    }
    part0[t] = cr0; part1[t] = cr1;
    __syncthreads();
    if (t < 128) {
        float c0 = part0[t] + part0[t+128] + part0[t+256] + part0[t+384];
        float c1 = part1[t] + part1[t+128] + part1[t+256] + part1[t+384];
        int ss0 = sh*256 + 2*t;
        float var0 = s2 + 2.f * c0 * (1.f/NA);
        float var1 = s2 + 2.f * c1 * (1.f/NA);
        float scale = dg[c];
        *(float2*)&g_w1[c*NA + ss0] = make_float2(scale * rsqrtf(var0 + BNEPS),
                                                  scale * rsqrtf(var1 + BNEPS));
    }
}

// ---------------- fused MI (z=0) + DIS (z=1): 32j x 64s tiles, 2jx4s per thread ----------------
// grid dim3(16, 8, 2), 256 threads
__global__ void k_midis(const float* __restrict__ dbt,
                        const float* __restrict__ dW2,
                        const float* __restrict__ db2) {
    __shared__ float sh[6528];
    const int tid = threadIdx.x;            // 256
    const int j0 = blockIdx.x * 32, s0 = blockIdx.y * 64;
    const int tx = tid & 15, ty = tid >> 4;
    const int jj0 = 2*tx, ss0 = 4*ty;
    const int base = (j0 - s0 - 64) & (NA-1);
    const int w0 = jj0 - ss0 + 60;          // even, in [0,90]; window rows w0..w0+5
    float vmn, vmx;
    if (blockIdx.z == 0) {
        // ---- MI: packed f32x2 over the j-pair, scalar max ----
        float* sNM = sh;            // [32 l][34]  (-mu)
        float* sNI = sh + 1088;     // [32 l][34]
        float* sCC = sh + 2176;     // [32 l][34]
        float* sL  = sh + 3264;     // [32 l][98]  (96 rows + pad)
        float accL[4] = {0.f,0.f,0.f,0.f}, accH[4] = {0.f,0.f,0.f,0.f};
        for (int l0 = 0; l0 < LAT; l0 += 32) {
            #pragma unroll
            for (int i = 0; i < 4; i++) {
                int idx = tid + i*256;
                int jj = idx >> 5, lc = idx & 31;
                int g = (j0 + jj)*LAT + l0 + lc;
                sNM[lc*34 + jj] = -g_mu[g];
                sNI[lc*34 + jj] = g_ni2v[g];
                sCC[lc*34 + jj] = g_cc[g];
            }
            #pragma unroll
            for (int i = 0; i < 12; i++) {
                int idx = tid + i*256;
                int rr = idx >> 5, lc = idx & 31;
                sL[lc*98 + rr] = g_lat[((base + rr) & (NA-1))*LAT + l0 + lc];
            }
            __syncthreads();
            #pragma unroll
            for (int l = 0; l < 32; l++) {
                ull nm2 = lds_b64(&sNM[l*34 + jj0]);
                ull ni2 = lds_b64(&sNI[l*34 + jj0]);
                ull cc2 = lds_b64(&sCC[l*34 + jj0]);
                float2 L01 = *(const float2*)&sL[l*98 + w0];
                float2 L23 = *(const float2*)&sL[l*98 + w0 + 2];
                float2 L45 = *(const float2*)&sL[l*98 + w0 + 4];
                ull P[4];
                P[0] = p2_pack(L23.y, L45.x);   // a=0: (3,4)
                P[1] = p2_pack(L23.x, L23.y);   // a=1: (2,3)
                P[2] = p2_pack(L01.y, L23.x);   // a=2: (1,2)
                P[3] = p2_pack(L01.x, L01.y);   // a=3: (0,1)
                #pragma unroll
                for (int a = 0; a < 4; a++) {
                    ull d = p2_add(P[a], nm2);
                    ull q = p2_mul(d, d);
                    ull r = p2_fma(q, ni2, cc2);
                    accL[a] += fmaxf(p2_lo(r), -13.9f);
                    accH[a] += fmaxf(p2_hi(r), -13.9f);
                }
            }
            __syncthreads();
        }
        const float inv = 1.f / LAT;
        float o[4][2];
        #pragma unroll
        for (int a = 0; a < 4; a++) {
            o[a][0] = accL[a]*inv; o[a][1] = accH[a]*inv;
            *(float2*)&g_mi[(s0+ss0+a)*NA + j0+jj0] = make_float2(o[a][0], o[a][1]);
        }
        vmn = o[0][0]; vmx = o[0][0];
        #pragma unroll
        for (int a = 0; a < 4; a++) {
            vmn = fminf(vmn, fminf(o[a][0], o[a][1]));
            vmx = fmaxf(vmx, fmaxf(o[a][0], o[a][1]));
        }
    } else {
        // ---- DIS: scalar, c-chunked (2 chunks of 32) ----
        float* sa   = sh;            // [32 c][34]
        float* sw   = sh + 1088;     // [32 c][68]
        float* sb   = sh + 3264;     // [32 c][98]
        float* sdbt = sh + 6400;     // 64
        float* sdw2 = sh + 6464;     // 64
        if (tid < NH) { sdbt[tid] = dbt[tid]; sdw2[tid] = dW2[tid]; }
        float acc[4][2] = {{0.f,0.f},{0.f,0.f},{0.f,0.f},{0.f,0.f}};
        for (int cb = 0; cb < NH; cb += 32) {
            #pragma unroll
            for (int i = 0; i < 4; i++) {
                int idx = tid + i*256;
                int cc = idx >> 5, jj = idx & 31;
                sa[cc*34 + jj] = g_Ac[(cb+cc)*NA + j0 + jj];
            }
            #pragma unroll
            for (int i = 0; i < 8; i++) {
                int idx = tid + i*256;
                int cc = idx >> 6, ss = idx & 63;
                sw[cc*68 + ss] = g_w1[(cb+cc)*NA + s0 + ss];
            }
            #pragma unroll
            for (int i = 0; i < 16; i++) {
                int idx = tid + i*256;
                int cc = idx >> 7, rr = idx & 127;
                if (rr < 96)
                    sb[cc*98 + rr] = g_Bc[(cb+cc)*NA + ((base + rr) & (NA-1))];
            }
            __syncthreads();
            #pragma unroll 4
            for (int cc = 0; cc < 32; cc++) {
                float2 a2 = *(const float2*)&sa[cc*34 + jj0];
                float4 w4 = *(const float4*)&sw[cc*68 + ss0];
                float2 B01 = *(const float2*)&sb[cc*98 + w0];
                float2 B23 = *(const float2*)&sb[cc*98 + w0 + 2];
                float2 B45 = *(const float2*)&sb[cc*98 + w0 + 4];
                float Bw[5] = {B01.x, B01.y, B23.x, B23.y, B45.x};
                float bt = sdbt[cb+cc], w2 = sdw2[cb+cc];
                float wa[4] = {w4.x, w4.y, w4.z, w4.w};
                float aj[2] = {a2.x, a2.y};
                #pragma unroll
                for (int a = 0; a < 4; a++) {
                    #pragma unroll
                    for (int bb = 0; bb < 2; bb++) {
                        float u = fmaf(aj[bb] + Bw[3 + bb - a], wa[a], bt);
                        u = fmaxf(u, 0.01f*u);   // leaky relu
                        acc[a][bb] = fmaf(u, w2, acc[a][bb]);
                    }
                }
            }
            __syncthreads();
        }
        float b2v = db2[0];
        float o[4][2];
        #pragma unroll
        for (int a = 0; a < 4; a++) {
            o[a][0] = fabsf(acc[a][0] + b2v);
            o[a][1] = fabsf(acc[a][1] + b2v);
            *(float2*)&g_dis[(s0+ss0+a)*NA + j0+jj0] = make_float2(o[a][0], o[a][1]);
        }
        vmn = o[0][0]; vmx = o[0][0];
        #pragma unroll
        for (int a = 0; a < 4; a++) {
            vmn = fminf(vmn, fminf(o[a][0], o[a][1]));
            vmx = fmaxf(vmx, fmaxf(o[a][0], o[a][1]));
        }
    }
    // ---- block min/max -> global atomic keys ----
    #pragma unroll
    for (int o2 = 16; o2; o2 >>= 1) {
        vmn = fminf(vmn, __shfl_xor_sync(0xFFFFFFFFu, vmn, o2));
        vmx = fmaxf(vmx, __shfl_xor_sync(0xFFFFFFFFu, vmx, o2));
    }
    __shared__ float wmn[8], wmx[8];
    if ((tid & 31) == 0) { wmn[tid>>5] = vmn; wmx[tid>>5] = vmx; }
    __syncthreads();
    if (tid == 0) {
        float a = wmn[0], b = wmx[0];
        #pragma unroll
        for (int k = 1; k < 8; k++) { a = fminf(a, wmn[k]); b = fmaxf(b, wmx[k]); }
        atomicMin(&g_keymin[blockIdx.z], fkey(a));
        atomicMax(&g_keymax[blockIdx.z], fkey(b));
    }
}

// ---------------- normalized sums (float4) + last-block final assembly ----------------
__global__ void k_sums(float* __restrict__ out) {
    int tid = threadIdx.x;                      // 128 blocks x 256 threads
    float mi_min = funkey(g_keymin[0]);
    float mi_inv = 1.f / (funkey(g_keymax[0]) - mi_min + 1e-12f);
    float ds_min = funkey(g_keymin[1]);
    float ds_inv = 1.f / (funkey(g_keymax[1]) - ds_min + 1e-12f);
    const float4* mi4 = (const float4*)g_mi;
    const float4* ds4 = (const float4*)g_dis;
    double s1 = 0.0, s2 = 0.0;
    #pragma unroll
    for (int i = 0; i < 2; i++) {
        int f = blockIdx.x*512 + tid + i*256;
        float4 m = mi4[f], d = ds4[f];
        float mn0 = (m.x - mi_min)*mi_inv, dn0 = (d.x - ds_min)*ds_inv;
        float mn1 = (m.y - mi_min)*mi_inv, dn1 = (d.y - ds_min)*ds_inv;
        float mn2 = (m.z - mi_min)*mi_inv, dn2 = (d.z - ds_min)*ds_inv;
        float mn3 = (m.w - mi_min)*mi_inv, dn3 = (d.w - ds_min)*ds_inv;
        s1 += (double)dn0 + (double)dn1 + (double)dn2 + (double)dn3;
        s2 += (double)fminf(mn0 + dn0, 1.0f) + (double)fminf(mn1 + dn1, 1.0f)
            + (double)fminf(mn2 + dn2, 1.0f) + (double)fminf(mn3 + dn3, 1.0f);
    }
    __shared__ double d1[256], d2[256];
    d1[tid] = s1; d2[tid] = s2;
    __syncthreads();
    for (int o = 128; o; o >>= 1) {
        if (tid < o) { d1[tid] += d1[tid+o]; d2[tid] += d2[tid+o]; }
        __syncthreads();
    }
    if (tid == 0) {
        atomicAdd(&g_sum_disn, d1[0]);
        atomicAdd(&g_sum_min, d2[0]);
        __threadfence();
        unsigned old = atomicAdd(&g_done, 1u);
        if (old == 127u) {   // last of 128 blocks
            __threadfence();
            double sum_disn = atomicAdd(&g_sum_disn, 0.0);
            double sum_min  = atomicAdd(&g_sum_min, 0.0);
            double ent = atomicAdd(&g_ent, 0.0) / (double)NA;
            double kl  = atomicAdd(&g_kl, 0.0)  / (double)NA;
            double loss0 = fmin(ent*1e-4 + kl*1e-4, 2000.0);
            double ce = log1p(exp(loss0));
            double dis_norm = sum_disn / (double)NA;
            double dis_loss = -sum_min / (double)NA;
            double cdis = (dis_norm + dis_loss) / (double)NA;
            out[0] = (float)(ce + cdis);
            out[1] = (float)cdis;
            out[2] = (float)ce;
        }
    }
}

// ---------------- launcher ----------------
extern "C" void kernel_launch(void* const* d_in, const int* in_sizes, int n_in,
                              void* d_out, int out_size) {
    const float* obs  = (const float*)d_in[0];
    const float* hid  = (const float*)d_in[1];
    const float* eps  = (const float*)d_in[2];
    const float* eW1  = (const float*)d_in[3];
    const float* eb1  = (const float*)d_in[4];
    const float* eg   = (const float*)d_in[5];
    const float* ebt  = (const float*)d_in[6];
    const float* eW2  = (const float*)d_in[7];
    const float* eb2  = (const float*)d_in[8];
    const float* iW1  = (const float*)d_in[9];
    const float* ib1  = (const float*)d_in[10];
    const float* ig   = (const float*)d_in[11];
    const float* ibt  = (const float*)d_in[12];
    const float* iW2  = (const float*)d_in[13];
    const float* ib2  = (const float*)d_in[14];
    const float* dW1  = (const float*)d_in[15];
    const float* db1  = (const float*)d_in[16]; (void)db1; // cancels in BN
    const float* dg   = (const float*)d_in[17];
    const float* dbt  = (const float*)d_in[18];
    const float* dW2  = (const float*)d_in[19];
    const float* db2  = (const float*)d_in[20];
    float* out = (float*)d_out;

    k_lin<<<2*NA, 128>>>(obs, hid, eW1, eb1, iW1, ib1);
    k_bn<<<2, 1024>>>(eg, ebt, ig, ibt);
    k_lat<<<256, 256>>>(eW2, eb2, iW2, ib2, eps, dW1);
    k_col<<<dim3(64, 2), 512>>>(dg);
    k_midis<<<dim3(16, 8, 2), 256>>>(dbt, dW2, db2);
    k_sums<<<128, 256>>>(out);
}